// round 7
// baseline (speedup 1.0000x reference)
#include <cuda_runtime.h>
#include <cuda_bf16.h>
#include <cstdint>

#define B   8
#define L   4096
#define D   1024
#define DQK 1024
#define M   (B * L)           // 32768 tokens
#define BLD ((size_t)M * D)   // 33554432
#define NTOT 3072

// ---------------- scratch (device globals; no allocation allowed) ----------
__device__ float g_q[(size_t)M * DQK];     // 128 MiB
__device__ float g_k[(size_t)M * DQK];     // 128 MiB
__device__ float g_res[(size_t)M * D];     // 128 MiB
__device__ float g_scan[(size_t)M * D];    // 128 MiB
__device__ float g_probs[M];
__device__ int   g_flag[M];
__device__ int   g_chunkid[M];
__device__ int   g_blidx[M];
__device__ int   g_nch[B];
__device__ float g_auxb[B];

// bf16 2-way splits of A (tokens) and B (combined weights, TRANSPOSED: [n][k])
__device__ __nv_bfloat16 g_Ahi [(size_t)M * 1024];
__device__ __nv_bfloat16 g_Amid[(size_t)M * 1024];
__device__ __nv_bfloat16 g_Bhi [(size_t)NTOT * 1024];
__device__ __nv_bfloat16 g_Bmid[(size_t)NTOT * 1024];

// ======================= helpers ===========================================
__device__ __forceinline__ uint32_t smem_u32(const void* p) {
    uint32_t a;
    asm("{ .reg .u64 t; cvta.to.shared.u64 t, %1; cvt.u32.u64 %0, t; }"
        : "=r"(a) : "l"(p));
    return a;
}
__device__ __forceinline__ void cp_async16(uint32_t saddr, const void* gaddr) {
    asm volatile("cp.async.cg.shared.global [%0], [%1], 16;"
                 :: "r"(saddr), "l"(gaddr));
}
__device__ __forceinline__ void cp_commit() {
    asm volatile("cp.async.commit_group;");
}
template<int N> __device__ __forceinline__ void cp_waitg() {
    asm volatile("cp.async.wait_group %0;" :: "n"(N));
}
__device__ __forceinline__ void ldsm_x4(uint32_t addr, uint32_t& r0, uint32_t& r1,
                                        uint32_t& r2, uint32_t& r3) {
    asm volatile("ldmatrix.sync.aligned.m8n8.x4.shared.b16 {%0,%1,%2,%3}, [%4];"
                 : "=r"(r0), "=r"(r1), "=r"(r2), "=r"(r3) : "r"(addr));
}
__device__ __forceinline__ void mma_bf16(float* c,
                                         const uint32_t* a,
                                         uint32_t b0, uint32_t b1) {
    asm volatile(
        "mma.sync.aligned.m16n8k16.row.col.f32.bf16.bf16.f32 "
        "{%0,%1,%2,%3}, {%4,%5,%6,%7}, {%8,%9}, {%0,%1,%2,%3};"
        : "+f"(c[0]), "+f"(c[1]), "+f"(c[2]), "+f"(c[3])
        : "r"(a[0]), "r"(a[1]), "r"(a[2]), "r"(a[3]), "r"(b0), "r"(b1));
}

// ---------------- Prep 1: split tokens -> bf16 hi/mid -----------------------
__global__ __launch_bounds__(256) void split_a_kernel(const float* __restrict__ A)
{
    size_t i4 = (size_t)blockIdx.x * 256 + threadIdx.x;   // float4 index
    float4 v = ((const float4*)A)[i4];
    float x[4] = {v.x, v.y, v.z, v.w};
    unsigned short h[4], mm[4];
#pragma unroll
    for (int j = 0; j < 4; j++) {
        __nv_bfloat16 bh = __float2bfloat16_rn(x[j]);
        float r1 = x[j] - __bfloat162float(bh);
        __nv_bfloat16 bm = __float2bfloat16_rn(r1);
        h[j]  = __bfloat16_as_ushort(bh);
        mm[j] = __bfloat16_as_ushort(bm);
    }
    ((uint2*)g_Ahi)[i4]  = make_uint2((unsigned)h[0]  | ((unsigned)h[1]  << 16),
                                      (unsigned)h[2]  | ((unsigned)h[3]  << 16));
    ((uint2*)g_Amid)[i4] = make_uint2((unsigned)mm[0] | ((unsigned)mm[1] << 16),
                                      (unsigned)mm[2] | ((unsigned)mm[3] << 16));
}

// ---------------- Prep 2: split + transpose weights -> [n][k] bf16 ----------
__global__ __launch_bounds__(256) void split_b_kernel(
    const float* __restrict__ Wqk, const float* __restrict__ Wres)
{
    int id = blockIdx.x * 256 + threadIdx.x;   // 0..393215
    int n  = id % NTOT;
    int kg = id / NTOT;                         // 0..127
    int k0 = kg * 8;
    unsigned short h[8], mm[8];
#pragma unroll
    for (int j = 0; j < 8; j++) {
        int k = k0 + j;
        float x = (n < 2048) ? Wqk[(size_t)k * 2048 + n]
                             : Wres[(size_t)k * 1024 + (n - 2048)];
        __nv_bfloat16 bh = __float2bfloat16_rn(x);
        float r1 = x - __bfloat162float(bh);
        __nv_bfloat16 bm = __float2bfloat16_rn(r1);
        h[j]  = __bfloat16_as_ushort(bh);
        mm[j] = __bfloat16_as_ushort(bm);
    }
    size_t off = (size_t)n * 1024 + k0;  // bf16 elements
#define PACK4(a) make_uint4((unsigned)a[0] | ((unsigned)a[1] << 16), \
                            (unsigned)a[2] | ((unsigned)a[3] << 16), \
                            (unsigned)a[4] | ((unsigned)a[5] << 16), \
                            (unsigned)a[6] | ((unsigned)a[7] << 16))
    *(uint4*)((char*)g_Bhi  + off * 2) = PACK4(h);
    *(uint4*)((char*)g_Bmid + off * 2) = PACK4(mm);
#undef PACK4
}

// ---------------- Kernel 1: mma.sync split-bf16 GEMM (3 products) -----------
// C[M, 3072] = tokens @ [W_qk | W_res], products hi*hi + hi*mid + mid*hi.
// CTA tile 128x128, warps 4(m) x 2(n), warp tile 32x64, K-chunks of 64.
// 3-stage cp.async pipeline. Inner loop kept small (no ks unroll) and with
// minimal live fragments (per-ng B staging) to avoid spills / I$ overflow.
#define TILE_B      16384           // one 128x64 bf16 tile (128B rows)
#define STAGE_BYTES (4 * TILE_B)    // 64 KB
#define GEMM_SMEM   (3 * STAGE_BYTES)

__device__ __forceinline__ void fill_stage4(
    uint32_t st32, const char* const* gsrc, int chunk, int tid)
{
#pragma unroll
    for (int t = 0; t < 4; t++) {
#pragma unroll
        for (int it = 0; it < 4; it++) {
            int w = tid + it * 256;                    // 0..1023
            int row = w >> 3;
            int colB = (w & 7) * 16;
            const char* g = gsrc[t] + (size_t)row * 2048 + chunk * 128 + colB;
            uint32_t dst = st32 + t * TILE_B + row * 128
                         + (colB ^ ((row & 7) << 4));
            cp_async16(dst, g);
        }
    }
}

__global__ void __launch_bounds__(256, 1) gemm_kernel()
{
    extern __shared__ char smem[];
    uint32_t sb = smem_u32(smem);
    const int tid = threadIdx.x;
    const int lane = tid & 31;
    const int wid = tid >> 5;
    const int warp_m = wid & 3;          // m offset 32*warp_m
    const int warp_n = wid >> 2;         // n offset 64*warp_n
    const int m0 = blockIdx.y * 128;
    const int n0 = blockIdx.x * 128;

    const char* gsrc[4];
    gsrc[0] = (const char*)g_Ahi  + (size_t)m0 * 2048;
    gsrc[1] = (const char*)g_Amid + (size_t)m0 * 2048;
    gsrc[2] = (const char*)g_Bhi  + (size_t)n0 * 2048;
    gsrc[3] = (const char*)g_Bmid + (size_t)n0 * 2048;

    float acc[2][8][4];
#pragma unroll
    for (int i = 0; i < 2; i++)
#pragma unroll
        for (int j = 0; j < 8; j++)
#pragma unroll
            for (int q = 0; q < 4; q++) acc[i][j][q] = 0.f;

    // per-thread ldmatrix address invariants
    const int aRow  = warp_m * 32 + (lane & 15);       // +16*mi later
    const int aXor  = (aRow & 7) << 4;
    const int aColB = (lane >> 4) * 16;                // 0/16
    const int bRow  = warp_n * 64 + (lane & 7) + ((lane >> 4) & 1) * 8; // +16*ng
    const int bXor  = (bRow & 7) << 4;
    const int bColB = ((lane >> 3) & 1) * 16;          // 0/16

    fill_stage4(sb, gsrc, 0, tid);
    cp_commit();
    fill_stage4(sb + STAGE_BYTES, gsrc, 1, tid);
    cp_commit();

#pragma unroll 1
    for (int c = 0; c < 16; c++) {
        uint32_t stage = sb + (c % 3) * STAGE_BYTES;
        if (c < 14) {
            fill_stage4(sb + ((c + 2) % 3) * STAGE_BYTES, gsrc, c + 2, tid);
            cp_commit();
            cp_waitg<2>();
        } else if (c == 14) {
            cp_waitg<1>();
        } else {
            cp_waitg<0>();
        }
        __syncthreads();

        uint32_t aHi = stage, aMid = stage + TILE_B;
        uint32_t bHi = stage + 2 * TILE_B, bMid = stage + 3 * TILE_B;
#pragma unroll 1
        for (int ks = 0; ks < 4; ks++) {
            uint32_t ah[2][4], am[2][4];
#pragma unroll
            for (int mi = 0; mi < 2; mi++) {
                uint32_t roff = (aRow + mi * 16) * 128 + ((ks * 32 + aColB) ^ aXor);
                ldsm_x4(aHi  + roff, ah[mi][0], ah[mi][1], ah[mi][2], ah[mi][3]);
                ldsm_x4(aMid + roff, am[mi][0], am[mi][1], am[mi][2], am[mi][3]);
            }
#pragma unroll
            for (int ng = 0; ng < 4; ng++) {
                uint32_t roff = (bRow + ng * 16) * 128 + ((ks * 32 + bColB) ^ bXor);
                uint32_t b0, b1, b2, b3;
                // hi-B: serves hi*hi and mid*hi
                ldsm_x4(bHi + roff, b0, b1, b2, b3);
                mma_bf16(acc[0][ng*2],   ah[0], b0, b1);
                mma_bf16(acc[0][ng*2+1], ah[0], b2, b3);
                mma_bf16(acc[1][ng*2],   ah[1], b0, b1);
                mma_bf16(acc[1][ng*2+1], ah[1], b2, b3);
                mma_bf16(acc[0][ng*2],   am[0], b0, b1);
                mma_bf16(acc[0][ng*2+1], am[0], b2, b3);
                mma_bf16(acc[1][ng*2],   am[1], b0, b1);
                mma_bf16(acc[1][ng*2+1], am[1], b2, b3);
                // mid-B: serves hi*mid
                ldsm_x4(bMid + roff, b0, b1, b2, b3);
                mma_bf16(acc[0][ng*2],   ah[0], b0, b1);
                mma_bf16(acc[0][ng*2+1], ah[0], b2, b3);
                mma_bf16(acc[1][ng*2],   ah[1], b0, b1);
                mma_bf16(acc[1][ng*2+1], ah[1], b2, b3);
            }
        }
        __syncthreads();
    }

    float* cbase; int coloff;
    if (n0 < 1024)      { cbase = g_q;   coloff = n0; }
    else if (n0 < 2048) { cbase = g_k;   coloff = n0 - 1024; }
    else                { cbase = g_res; coloff = n0 - 2048; }

#pragma unroll
    for (int mi = 0; mi < 2; mi++) {
        int r0 = m0 + warp_m * 32 + mi * 16 + (lane >> 2);
#pragma unroll
        for (int ni = 0; ni < 8; ni++) {
            int col = coloff + warp_n * 64 + ni * 8 + (lane & 3) * 2;
            *(float2*)&cbase[(size_t)r0 * 1024 + col] =
                make_float2(acc[mi][ni][0], acc[mi][ni][1]);
            *(float2*)&cbase[(size_t)(r0 + 8) * 1024 + col] =
                make_float2(acc[mi][ni][2], acc[mi][ni][3]);
        }
    }
}

// ---------------- Kernel 2: per-token cosine -> probs + near-zero flag ------
__global__ __launch_bounds__(128) void probs_kernel(const float* __restrict__ start_key)
{
    int token = blockIdx.x;
    int l = token & (L - 1);
    const float4* qv = (const float4*)(g_q + (size_t)token * DQK);
    const float4* kv = (l == 0) ? (const float4*)start_key
                                : (const float4*)(g_k + (size_t)(token - 1) * DQK);
    float dot = 0.f, qq = 0.f, kk = 0.f;
    for (int i = threadIdx.x; i < DQK / 4; i += 128) {
        float4 a = qv[i], c = kv[i];
        dot += a.x * c.x + a.y * c.y + a.z * c.z + a.w * c.w;
        qq  += a.x * a.x + a.y * a.y + a.z * a.z + a.w * a.w;
        kk  += c.x * c.x + c.y * c.y + c.z * c.z + c.w * c.w;
    }
#pragma unroll
    for (int o = 16; o; o >>= 1) {
        dot += __shfl_down_sync(0xffffffffu, dot, o);
        qq  += __shfl_down_sync(0xffffffffu, qq,  o);
        kk  += __shfl_down_sync(0xffffffffu, kk,  o);
    }
    __shared__ float sd[4], sq[4], sk[4];
    int w = threadIdx.x >> 5;
    if ((threadIdx.x & 31) == 0) { sd[w] = dot; sq[w] = qq; sk[w] = kk; }
    __syncthreads();
    if (threadIdx.x == 0) {
        dot = sd[0] + sd[1] + sd[2] + sd[3];
        qq  = sq[0] + sq[1] + sq[2] + sq[3];
        kk  = sk[0] + sk[1] + sk[2] + sk[3];
        float denom = fmaxf(sqrtf(qq) * sqrtf(kk), 1e-8f);
        float cosv = dot / denom;
        g_probs[token] = (1.0f - cosv) * 0.5f;
        g_flag[token] = (fabsf(cosv) < 2.5e-4f) ? 1 : 0;
    }
}

// ---------------- Kernel 2b: exact fp32 fixup for near-threshold tokens -----
__global__ __launch_bounds__(256) void fixup_kernel(
    const float* __restrict__ tokens, const float* __restrict__ Wqk,
    const float* __restrict__ start_key)
{
    int token = blockIdx.x;
    if (!g_flag[token]) return;
    int l = token & (L - 1);
    int tid = threadIdx.x;

    __shared__ float cur[1024], prev[1024];
    __shared__ float qv[1024], kv[1024];
    __shared__ float red[3][8];

    for (int i = tid; i < 1024; i += 256) {
        cur[i]  = tokens[(size_t)token * D + i];
        prev[i] = (l > 0) ? tokens[(size_t)(token - 1) * D + i] : 0.f;
    }
    __syncthreads();

#pragma unroll
    for (int j = 0; j < 4; j++) {
        int e = tid + j * 256;                 // q column
        float accq = 0.f;
        for (int d = 0; d < 1024; d++)
            accq = fmaf(cur[d], Wqk[(size_t)d * 2048 + e], accq);
        qv[e] = accq;
        if (l > 0) {
            float acck = 0.f;
            for (int d = 0; d < 1024; d++)
                acck = fmaf(prev[d], Wqk[(size_t)d * 2048 + 1024 + e], acck);
            kv[e] = acck;
        } else {
            kv[e] = start_key[e];
        }
    }
    __syncthreads();

    float dot = 0.f, qq = 0.f, kk = 0.f;
    for (int i = tid; i < 1024; i += 256) {
        float a = qv[i], c = kv[i];
        dot = fmaf(a, c, dot); qq = fmaf(a, a, qq); kk = fmaf(c, c, kk);
    }
#pragma unroll
    for (int o = 16; o; o >>= 1) {
        dot += __shfl_down_sync(0xffffffffu, dot, o);
        qq  += __shfl_down_sync(0xffffffffu, qq,  o);
        kk  += __shfl_down_sync(0xffffffffu, kk,  o);
    }
    int w = tid >> 5;
    if ((tid & 31) == 0) { red[0][w] = dot; red[1][w] = qq; red[2][w] = kk; }
    __syncthreads();
    if (tid == 0) {
        dot = 0.f; qq = 0.f; kk = 0.f;
#pragma unroll
        for (int i = 0; i < 8; i++) { dot += red[0][i]; qq += red[1][i]; kk += red[2][i]; }
        float denom = fmaxf(sqrtf(qq) * sqrtf(kk), 1e-8f);
        g_probs[token] = (1.0f - dot / denom) * 0.5f;
    }
}

// ---------------- Kernel 3: per-batch boundary scan + aux -------------------
__global__ __launch_bounds__(1024) void boundary_kernel()
{
    int b = blockIdx.x;
    int tid = threadIdx.x;
    __shared__ int   s[1024];
    __shared__ float sf[1024];

    int l0 = tid * 4;
    float p[4]; int bd[4]; int cnt = 0; float psum = 0.f;
#pragma unroll
    for (int i = 0; i < 4; i++) {
        int l = l0 + i;
        p[i] = g_probs[b * L + l];
        bd[i] = (l == 0) || (p[i] > 0.5f);
        cnt += bd[i];
        psum += p[i];
    }
    s[tid] = cnt;
    sf[tid] = psum;
    __syncthreads();
    for (int off = 1; off < 1024; off <<= 1) {
        int v = (tid >= off) ? s[tid - off] : 0;
        __syncthreads();
        if (tid >= off) s[tid] += v;
        __syncthreads();
    }
    int incl = s[tid];
    int base = incl - cnt;
    int total = s[1023];
    int run = base;
#pragma unroll
    for (int i = 0; i < 4; i++) {
        int l = l0 + i;
        if (bd[i]) { g_blidx[b * L + run] = l; run++; }
        g_chunkid[b * L + l] = run - 1;
    }
    __syncthreads();
    for (int off = 512; off > 0; off >>= 1) {
        if (tid < off) sf[tid] += sf[tid + off];
        __syncthreads();
    }
    if (tid == 0) {
        float F = (float)total / (float)L;
        float G = sf[0] / (float)L;
        g_auxb[b] = 1.2f * (5.0f * F * G + (1.0f - F) * (1.0f - G));
        g_nch[b] = total;
    }
}

// ---------------- Kernel 4a: zero padded chunk slots of downsampled ---------
__global__ __launch_bounds__(256) void zero_down_kernel(float* __restrict__ out)
{
    int row = blockIdx.x;          // b*L + j
    int b = row >> 12;
    int j = row & (L - 1);
    if (j < g_nch[b]) return;
    float4* o = (float4*)(out + (size_t)row * D);
    o[threadIdx.x] = make_float4(0.f, 0.f, 0.f, 0.f);
}

// ---------------- Kernel 4b: windowed-parallel chunk EMA scan ---------------
__global__ __launch_bounds__(128) void chunk_scan_kernel(
    const float* __restrict__ tokens, float* __restrict__ out)
{
    int b = blockIdx.z;
    int nch = g_nch[b];
    int j0 = blockIdx.y * 128;
    if (j0 >= nch) return;
    int d = blockIdx.x * 128 + threadIdx.x;
    int jstart = (j0 >= 64) ? (j0 - 64) : 0;
    int jend = min(j0 + 128, nch);
    int cnt = jend - jstart;

    __shared__ int   sl[192];
    __shared__ float sp[192];
    for (int i = threadIdx.x; i < cnt; i += 128) {
        int l = g_blidx[b * L + jstart + i];
        sl[i] = l;
        sp[i] = g_probs[b * L + l];
    }
    __syncthreads();

    float h = 0.f;
    int i = 0;
    int warm = j0 - jstart;
    for (; i < warm; i++) {
        float p = sp[i];
        float t = tokens[((size_t)b * L + sl[i]) * D + d];
        h = fmaf(1.f - p, h, p * t);
    }
    for (; i < cnt; i++) {
        int j = jstart + i;
        float p = sp[i];
        float t = tokens[((size_t)b * L + sl[i]) * D + d];
        float x = p * t;
        out[((size_t)b * L + j) * D + d] = x;          // downsampled
        h = fmaf(1.f - p, h, x);
        g_scan[((size_t)b * L + j) * D + d] = h;
    }
}

// ---------------- Kernel 5: ups = gather(scan) + res + b_res ----------------
__global__ __launch_bounds__(256) void ups_kernel(
    float* __restrict__ out, const float* __restrict__ b_res)
{
    int row = blockIdx.x;          // b*L + l
    int b = row >> 12;
    int cid = g_chunkid[row];
    const float4* sc = (const float4*)(g_scan + (size_t)(b * L + cid) * D);
    const float4* rs = (const float4*)(g_res + (size_t)row * D);
    const float4* br = (const float4*)b_res;
    float4* o = (float4*)(out + BLD + (size_t)row * D);
    int t = threadIdx.x;
    float4 a = sc[t], c = rs[t], e = br[t];
    o[t] = make_float4(a.x + c.x + e.x, a.y + c.y + e.y,
                       a.z + c.z + e.z, a.w + c.w + e.w);
}

// ---------------- Kernel 6: finalize aux scalar -----------------------------
__global__ void aux_final_kernel(float* __restrict__ out)
{
    float s = 0.f;
    for (int i = 0; i < B; i++) s += g_auxb[i];
    out[2 * BLD] = (s / (float)B) * 0.03f;
}

// ---------------- launch ----------------------------------------------------
extern "C" void kernel_launch(void* const* d_in, const int* in_sizes, int n_in,
                              void* d_out, int out_size)
{
    const float* tokens = (const float*)d_in[0];
    const float* Wqk    = (const float*)d_in[1];
    const float* skey   = (const float*)d_in[2];
    const float* Wres   = (const float*)d_in[3];
    const float* bres   = (const float*)d_in[4];
    float* out = (float*)d_out;

    cudaFuncSetAttribute(gemm_kernel,
                         cudaFuncAttributeMaxDynamicSharedMemorySize, GEMM_SMEM);

    split_a_kernel<<<32768, 256>>>(tokens);                  // 33.5M/4/256
    split_b_kernel<<<1536, 256>>>(Wqk, Wres);                // 3072*128/256
    gemm_kernel<<<dim3(24, 256), 256, GEMM_SMEM>>>();
    probs_kernel<<<M, 128>>>(skey);
    fixup_kernel<<<M, 256>>>(tokens, Wqk, skey);
    boundary_kernel<<<B, 1024>>>();
    zero_down_kernel<<<M, 256>>>(out);
    chunk_scan_kernel<<<dim3(D / 128, L / 128, B), 128>>>(tokens, out);
    ups_kernel<<<M, 256>>>(out, bres);
    aux_final_kernel<<<1, 1>>>(out);
}

// round 9
// speedup vs baseline: 1.0295x; 1.0295x over previous
#include <cuda_runtime.h>
#include <cuda_bf16.h>
#include <cstdint>

#define B   8
#define L   4096
#define D   1024
#define DQK 1024
#define M   (B * L)           // 32768 tokens
#define BLD ((size_t)M * D)   // 33554432
#define NTOT 3072
#define TILE_B 16384          // one 128x64 bf16 tile (128B rows, swizzled)

// ---------------- scratch (device globals; no allocation allowed) ----------
__device__ float g_q[(size_t)M * DQK];     // 128 MiB
__device__ float g_k[(size_t)M * DQK];     // 128 MiB
__device__ float g_res[(size_t)M * D];     // 128 MiB
__device__ float g_scan[(size_t)M * D];    // 128 MiB
__device__ float g_probs[M];
__device__ int   g_flag[M];
__device__ int   g_chunkid[M];
__device__ int   g_blidx[M];
__device__ int   g_nch[B];
__device__ float g_auxb[B];

// PRE-SWIZZLED tiled layouts: [block][chunk 0..15][16KB tile]
// tile byte (row, colB) -> row*128 + (colB ^ ((row&7)<<4))
__device__ __nv_bfloat16 g_Ahi [(size_t)M * 1024];     // [m_block][chunk][tile]
__device__ __nv_bfloat16 g_Amid[(size_t)M * 1024];
__device__ __nv_bfloat16 g_Bhi [(size_t)NTOT * 1024];  // [n_block][chunk][tile]
__device__ __nv_bfloat16 g_Bmid[(size_t)NTOT * 1024];

// ======================= helpers ===========================================
__device__ __forceinline__ uint32_t smem_u32(const void* p) {
    uint32_t a;
    asm("{ .reg .u64 t; cvta.to.shared.u64 t, %1; cvt.u32.u64 %0, t; }"
        : "=r"(a) : "l"(p));
    return a;
}
__device__ __forceinline__ void mbar_init(uint32_t a, uint32_t cnt) {
    asm volatile("mbarrier.init.shared.b64 [%0], %1;" :: "r"(a), "r"(cnt) : "memory");
}
__device__ __forceinline__ void mbar_expect_tx(uint32_t a, uint32_t bytes) {
    asm volatile("mbarrier.arrive.expect_tx.shared.b64 _, [%0], %1;"
                 :: "r"(a), "r"(bytes) : "memory");
}
__device__ __forceinline__ void mbar_wait(uint32_t a, uint32_t parity) {
    uint32_t done;
    asm volatile(
        "{\n\t.reg .pred p;\n\t"
        "mbarrier.try_wait.parity.acquire.cta.shared::cta.b64 p, [%1], %2;\n\t"
        "selp.b32 %0, 1, 0, p;\n\t}"
        : "=r"(done) : "r"(a), "r"(parity) : "memory");
    if (!done) {
        asm volatile(
            "{\n\t.reg .pred P1;\n\t"
            "WL_%=:\n\t"
            "mbarrier.try_wait.parity.acquire.cta.shared::cta.b64 P1, [%0], %1, 0x989680;\n\t"
            "@P1 bra.uni WD_%=;\n\t"
            "bra.uni WL_%=;\n\t"
            "WD_%=:\n\t}"
            :: "r"(a), "r"(parity) : "memory");
    }
}
__device__ __forceinline__ void bulk_cp(uint32_t dst, const void* src,
                                        uint32_t bytes, uint32_t mbar) {
    asm volatile(
        "cp.async.bulk.shared::cta.global.mbarrier::complete_tx::bytes "
        "[%0], [%1], %2, [%3];"
        :: "r"(dst), "l"(src), "r"(bytes), "r"(mbar) : "memory");
}
__device__ __forceinline__ void ldsm_x4(uint32_t addr, uint32_t& r0, uint32_t& r1,
                                        uint32_t& r2, uint32_t& r3) {
    asm volatile("ldmatrix.sync.aligned.m8n8.x4.shared.b16 {%0,%1,%2,%3}, [%4];"
                 : "=r"(r0), "=r"(r1), "=r"(r2), "=r"(r3) : "r"(addr));
}
__device__ __forceinline__ void mma_bf16(float* c,
                                         const uint32_t* a,
                                         uint32_t b0, uint32_t b1) {
    asm volatile(
        "mma.sync.aligned.m16n8k16.row.col.f32.bf16.bf16.f32 "
        "{%0,%1,%2,%3}, {%4,%5,%6,%7}, {%8,%9}, {%0,%1,%2,%3};"
        : "+f"(c[0]), "+f"(c[1]), "+f"(c[2]), "+f"(c[3])
        : "r"(a[0]), "r"(a[1]), "r"(a[2]), "r"(a[3]), "r"(b0), "r"(b1));
}

// tile address for element (row 0..127 within block, kg = k/8 within row)
__device__ __forceinline__ size_t tile_addr(int block, int row, int kg) {
    int chunk = kg >> 3;                 // k chunk of 64
    int colB  = (kg & 7) * 16;           // 16B group within 128B row
    int sw    = colB ^ ((row & 7) << 4);
    return ((size_t)block * 16 + chunk) * TILE_B + row * 128 + sw;
}

// ---------------- Prep 1: split tokens -> swizzled-tiled bf16 hi/mid --------
__global__ __launch_bounds__(256) void split_a_kernel(const float* __restrict__ A)
{
    int idx = blockIdx.x * 256 + threadIdx.x;      // 0 .. M*128-1
    int m  = idx >> 7;
    int kg = idx & 127;
    const float4* src = (const float4*)(A + (size_t)m * 1024 + kg * 8);
    float4 v0 = src[0], v1 = src[1];
    float x[8] = {v0.x, v0.y, v0.z, v0.w, v1.x, v1.y, v1.z, v1.w};
    unsigned short h[8], mm[8];
#pragma unroll
    for (int j = 0; j < 8; j++) {
        __nv_bfloat16 bh = __float2bfloat16_rn(x[j]);
        float r1 = x[j] - __bfloat162float(bh);
        __nv_bfloat16 bm = __float2bfloat16_rn(r1);
        h[j]  = __bfloat16_as_ushort(bh);
        mm[j] = __bfloat16_as_ushort(bm);
    }
    size_t a = tile_addr(m >> 7, m & 127, kg);
#define PACK4(arr) make_uint4((unsigned)arr[0] | ((unsigned)arr[1] << 16), \
                              (unsigned)arr[2] | ((unsigned)arr[3] << 16), \
                              (unsigned)arr[4] | ((unsigned)arr[5] << 16), \
                              (unsigned)arr[6] | ((unsigned)arr[7] << 16))
    *(uint4*)((char*)g_Ahi  + a) = PACK4(h);
    *(uint4*)((char*)g_Amid + a) = PACK4(mm);
}

// ---------------- Prep 2: split + transpose weights -> swizzled tiles -------
__global__ __launch_bounds__(256) void split_b_kernel(
    const float* __restrict__ Wqk, const float* __restrict__ Wres)
{
    int id = blockIdx.x * 256 + threadIdx.x;   // 0..393215
    int n  = id % NTOT;                         // coalesced reads over n
    int kg = id / NTOT;                         // 0..127
    unsigned short h[8], mm[8];
#pragma unroll
    for (int j = 0; j < 8; j++) {
        int k = kg * 8 + j;
        float x = (n < 2048) ? Wqk[(size_t)k * 2048 + n]
                             : Wres[(size_t)k * 1024 + (n - 2048)];
        __nv_bfloat16 bh = __float2bfloat16_rn(x);
        float r1 = x - __bfloat162float(bh);
        __nv_bfloat16 bm = __float2bfloat16_rn(r1);
        h[j]  = __bfloat16_as_ushort(bh);
        mm[j] = __bfloat16_as_ushort(bm);
    }
    size_t a = tile_addr(n >> 7, n & 127, kg);
    *(uint4*)((char*)g_Bhi  + a) = PACK4(h);
    *(uint4*)((char*)g_Bmid + a) = PACK4(mm);
#undef PACK4
}

// ---------------- Kernel 1: mma.sync split-bf16 GEMM (3 products) -----------
// Fills via cp.async.bulk (4 x 16KB per stage, single-thread issue, mbarrier
// completion) from the pre-swizzled tiled globals. 3-stage pipeline.
#define STAGE_BYTES (4 * TILE_B)    // 64 KB
#define GEMM_SMEM   (128 + 3 * STAGE_BYTES)

__global__ void __launch_bounds__(256, 1) gemm_kernel()
{
    extern __shared__ char smem[];
    uint32_t sb = smem_u32(smem);
    const int tid = threadIdx.x;
    const int lane = tid & 31;
    const int wid = tid >> 5;
    const int warp_m = wid & 3;          // m offset 32*warp_m
    const int warp_n = wid >> 2;         // n offset 64*warp_n
    const int m0 = blockIdx.y * 128;
    const int n0 = blockIdx.x * 128;

    const char* gsrc[4];
    gsrc[0] = (const char*)g_Ahi  + (size_t)(m0 >> 7) * 16 * TILE_B;
    gsrc[1] = (const char*)g_Amid + (size_t)(m0 >> 7) * 16 * TILE_B;
    gsrc[2] = (const char*)g_Bhi  + (size_t)(n0 >> 7) * 16 * TILE_B;
    gsrc[3] = (const char*)g_Bmid + (size_t)(n0 >> 7) * 16 * TILE_B;

    // mbarriers at sb+0/8/16, stages at sb+128
    if (tid == 0) {
        mbar_init(sb + 0, 1);
        mbar_init(sb + 8, 1);
        mbar_init(sb + 16, 1);
    }
    __syncthreads();

    float acc[2][8][4];
#pragma unroll
    for (int i = 0; i < 2; i++)
#pragma unroll
        for (int j = 0; j < 8; j++)
#pragma unroll
            for (int q = 0; q < 4; q++) acc[i][j][q] = 0.f;

    const int aRow  = warp_m * 32 + (lane & 15);
    const int aXor  = (aRow & 7) << 4;
    const int aColB = (lane >> 4) * 16;
    const int bRow  = warp_n * 64 + (lane & 7) + ((lane >> 4) & 1) * 8;
    const int bXor  = (bRow & 7) << 4;
    const int bColB = ((lane >> 3) & 1) * 16;

    // prologue: issue chunks 0 and 1
    if (tid == 0) {
#pragma unroll
        for (int c = 0; c < 2; c++) {
            uint32_t mb = sb + c * 8;
            uint32_t st = sb + 128 + c * STAGE_BYTES;
            mbar_expect_tx(mb, STAGE_BYTES);
#pragma unroll
            for (int t = 0; t < 4; t++)
                bulk_cp(st + t * TILE_B, gsrc[t] + (size_t)c * TILE_B, TILE_B, mb);
        }
    }

#pragma unroll 1
    for (int c = 0; c < 16; c++) {
        int s = c % 3;
        uint32_t stage = sb + 128 + s * STAGE_BYTES;
        if (c < 14 && tid == 0) {
            int s2 = (c + 2) % 3;
            uint32_t mb = sb + s2 * 8;
            uint32_t st = sb + 128 + s2 * STAGE_BYTES;
            mbar_expect_tx(mb, STAGE_BYTES);
#pragma unroll
            for (int t = 0; t < 4; t++)
                bulk_cp(st + t * TILE_B, gsrc[t] + (size_t)(c + 2) * TILE_B, TILE_B, mb);
        }
        mbar_wait(sb + s * 8, (c / 3) & 1);
        __syncthreads();

        uint32_t aHi = stage, aMid = stage + TILE_B;
        uint32_t bHi = stage + 2 * TILE_B, bMid = stage + 3 * TILE_B;
#pragma unroll 1
        for (int ks = 0; ks < 4; ks++) {
            uint32_t ah[2][4], am[2][4];
#pragma unroll
            for (int mi = 0; mi < 2; mi++) {
                uint32_t roff = (aRow + mi * 16) * 128 + ((ks * 32 + aColB) ^ aXor);
                ldsm_x4(aHi  + roff, ah[mi][0], ah[mi][1], ah[mi][2], ah[mi][3]);
                ldsm_x4(aMid + roff, am[mi][0], am[mi][1], am[mi][2], am[mi][3]);
            }
#pragma unroll
            for (int ng = 0; ng < 4; ng++) {
                uint32_t roff = (bRow + ng * 16) * 128 + ((ks * 32 + bColB) ^ bXor);
                uint32_t b0, b1, b2, b3;
                ldsm_x4(bHi + roff, b0, b1, b2, b3);
                mma_bf16(acc[0][ng*2],   ah[0], b0, b1);
                mma_bf16(acc[0][ng*2+1], ah[0], b2, b3);
                mma_bf16(acc[1][ng*2],   ah[1], b0, b1);
                mma_bf16(acc[1][ng*2+1], ah[1], b2, b3);
                mma_bf16(acc[0][ng*2],   am[0], b0, b1);
                mma_bf16(acc[0][ng*2+1], am[0], b2, b3);
                mma_bf16(acc[1][ng*2],   am[1], b0, b1);
                mma_bf16(acc[1][ng*2+1], am[1], b2, b3);
                ldsm_x4(bMid + roff, b0, b1, b2, b3);
                mma_bf16(acc[0][ng*2],   ah[0], b0, b1);
                mma_bf16(acc[0][ng*2+1], ah[0], b2, b3);
                mma_bf16(acc[1][ng*2],   ah[1], b0, b1);
                mma_bf16(acc[1][ng*2+1], ah[1], b2, b3);
            }
        }
        __syncthreads();
    }

    float* cbase; int coloff;
    if (n0 < 1024)      { cbase = g_q;   coloff = n0; }
    else if (n0 < 2048) { cbase = g_k;   coloff = n0 - 1024; }
    else                { cbase = g_res; coloff = n0 - 2048; }

#pragma unroll
    for (int mi = 0; mi < 2; mi++) {
        int r0 = m0 + warp_m * 32 + mi * 16 + (lane >> 2);
#pragma unroll
        for (int ni = 0; ni < 8; ni++) {
            int col = coloff + warp_n * 64 + ni * 8 + (lane & 3) * 2;
            *(float2*)&cbase[(size_t)r0 * 1024 + col] =
                make_float2(acc[mi][ni][0], acc[mi][ni][1]);
            *(float2*)&cbase[(size_t)(r0 + 8) * 1024 + col] =
                make_float2(acc[mi][ni][2], acc[mi][ni][3]);
        }
    }
}

// ---------------- Kernel 2: per-token cosine -> probs + near-zero flag ------
__global__ __launch_bounds__(128) void probs_kernel(const float* __restrict__ start_key)
{
    int token = blockIdx.x;
    int l = token & (L - 1);
    const float4* qv = (const float4*)(g_q + (size_t)token * DQK);
    const float4* kv = (l == 0) ? (const float4*)start_key
                                : (const float4*)(g_k + (size_t)(token - 1) * DQK);
    float dot = 0.f, qq = 0.f, kk = 0.f;
    for (int i = threadIdx.x; i < DQK / 4; i += 128) {
        float4 a = qv[i], c = kv[i];
        dot += a.x * c.x + a.y * c.y + a.z * c.z + a.w * c.w;
        qq  += a.x * a.x + a.y * a.y + a.z * a.z + a.w * a.w;
        kk  += c.x * c.x + c.y * c.y + c.z * c.z + c.w * c.w;
    }
#pragma unroll
    for (int o = 16; o; o >>= 1) {
        dot += __shfl_down_sync(0xffffffffu, dot, o);
        qq  += __shfl_down_sync(0xffffffffu, qq,  o);
        kk  += __shfl_down_sync(0xffffffffu, kk,  o);
    }
    __shared__ float sd[4], sq[4], sk[4];
    int w = threadIdx.x >> 5;
    if ((threadIdx.x & 31) == 0) { sd[w] = dot; sq[w] = qq; sk[w] = kk; }
    __syncthreads();
    if (threadIdx.x == 0) {
        dot = sd[0] + sd[1] + sd[2] + sd[3];
        qq  = sq[0] + sq[1] + sq[2] + sq[3];
        kk  = sk[0] + sk[1] + sk[2] + sk[3];
        float denom = fmaxf(sqrtf(qq) * sqrtf(kk), 1e-8f);
        float cosv = dot / denom;
        g_probs[token] = (1.0f - cosv) * 0.5f;
        g_flag[token] = (fabsf(cosv) < 2.5e-4f) ? 1 : 0;
    }
}

// ---------------- Kernel 2b: exact fp32 fixup for near-threshold tokens -----
__global__ __launch_bounds__(256) void fixup_kernel(
    const float* __restrict__ tokens, const float* __restrict__ Wqk,
    const float* __restrict__ start_key)
{
    int token = blockIdx.x;
    if (!g_flag[token]) return;
    int l = token & (L - 1);
    int tid = threadIdx.x;

    __shared__ float cur[1024], prev[1024];
    __shared__ float qv[1024], kv[1024];
    __shared__ float red[3][8];

    for (int i = tid; i < 1024; i += 256) {
        cur[i]  = tokens[(size_t)token * D + i];
        prev[i] = (l > 0) ? tokens[(size_t)(token - 1) * D + i] : 0.f;
    }
    __syncthreads();

#pragma unroll
    for (int j = 0; j < 4; j++) {
        int e = tid + j * 256;
        float accq = 0.f;
        for (int d = 0; d < 1024; d++)
            accq = fmaf(cur[d], Wqk[(size_t)d * 2048 + e], accq);
        qv[e] = accq;
        if (l > 0) {
            float acck = 0.f;
            for (int d = 0; d < 1024; d++)
                acck = fmaf(prev[d], Wqk[(size_t)d * 2048 + 1024 + e], acck);
            kv[e] = acck;
        } else {
            kv[e] = start_key[e];
        }
    }
    __syncthreads();

    float dot = 0.f, qq = 0.f, kk = 0.f;
    for (int i = tid; i < 1024; i += 256) {
        float a = qv[i], c = kv[i];
        dot = fmaf(a, c, dot); qq = fmaf(a, a, qq); kk = fmaf(c, c, kk);
    }
#pragma unroll
    for (int o = 16; o; o >>= 1) {
        dot += __shfl_down_sync(0xffffffffu, dot, o);
        qq  += __shfl_down_sync(0xffffffffu, qq,  o);
        kk  += __shfl_down_sync(0xffffffffu, kk,  o);
    }
    int w = tid >> 5;
    if ((tid & 31) == 0) { red[0][w] = dot; red[1][w] = qq; red[2][w] = kk; }
    __syncthreads();
    if (tid == 0) {
        dot = 0.f; qq = 0.f; kk = 0.f;
#pragma unroll
        for (int i = 0; i < 8; i++) { dot += red[0][i]; qq += red[1][i]; kk += red[2][i]; }
        float denom = fmaxf(sqrtf(qq) * sqrtf(kk), 1e-8f);
        g_probs[token] = (1.0f - dot / denom) * 0.5f;
    }
}

// ---------------- Kernel 3: per-batch boundary scan + aux -------------------
__global__ __launch_bounds__(1024) void boundary_kernel()
{
    int b = blockIdx.x;
    int tid = threadIdx.x;
    __shared__ int   s[1024];
    __shared__ float sf[1024];

    int l0 = tid * 4;
    float p[4]; int bd[4]; int cnt = 0; float psum = 0.f;
#pragma unroll
    for (int i = 0; i < 4; i++) {
        int l = l0 + i;
        p[i] = g_probs[b * L + l];
        bd[i] = (l == 0) || (p[i] > 0.5f);
        cnt += bd[i];
        psum += p[i];
    }
    s[tid] = cnt;
    sf[tid] = psum;
    __syncthreads();
    for (int off = 1; off < 1024; off <<= 1) {
        int v = (tid >= off) ? s[tid - off] : 0;
        __syncthreads();
        if (tid >= off) s[tid] += v;
        __syncthreads();
    }
    int incl = s[tid];
    int base = incl - cnt;
    int total = s[1023];
    int run = base;
#pragma unroll
    for (int i = 0; i < 4; i++) {
        int l = l0 + i;
        if (bd[i]) { g_blidx[b * L + run] = l; run++; }
        g_chunkid[b * L + l] = run - 1;
    }
    __syncthreads();
    for (int off = 512; off > 0; off >>= 1) {
        if (tid < off) sf[tid] += sf[tid + off];
        __syncthreads();
    }
    if (tid == 0) {
        float F = (float)total / (float)L;
        float G = sf[0] / (float)L;
        g_auxb[b] = 1.2f * (5.0f * F * G + (1.0f - F) * (1.0f - G));
        g_nch[b] = total;
    }
}

// ---------------- Kernel 4a: zero padded chunk slots of downsampled ---------
__global__ __launch_bounds__(256) void zero_down_kernel(float* __restrict__ out)
{
    int row = blockIdx.x;          // b*L + j
    int b = row >> 12;
    int j = row & (L - 1);
    if (j < g_nch[b]) return;
    float4* o = (float4*)(out + (size_t)row * D);
    o[threadIdx.x] = make_float4(0.f, 0.f, 0.f, 0.f);
}

// ---------------- Kernel 4b: windowed-parallel chunk EMA scan ---------------
__global__ __launch_bounds__(128) void chunk_scan_kernel(
    const float* __restrict__ tokens, float* __restrict__ out)
{
    int b = blockIdx.z;
    int nch = g_nch[b];
    int j0 = blockIdx.y * 128;
    if (j0 >= nch) return;
    int d = blockIdx.x * 128 + threadIdx.x;
    int jstart = (j0 >= 64) ? (j0 - 64) : 0;
    int jend = min(j0 + 128, nch);
    int cnt = jend - jstart;

    __shared__ int   sl[192];
    __shared__ float sp[192];
    for (int i = threadIdx.x; i < cnt; i += 128) {
        int l = g_blidx[b * L + jstart + i];
        sl[i] = l;
        sp[i] = g_probs[b * L + l];
    }
    __syncthreads();

    float h = 0.f;
    int i = 0;
    int warm = j0 - jstart;
    for (; i < warm; i++) {
        float p = sp[i];
        float t = tokens[((size_t)b * L + sl[i]) * D + d];
        h = fmaf(1.f - p, h, p * t);
    }
    for (; i < cnt; i++) {
        int j = jstart + i;
        float p = sp[i];
        float t = tokens[((size_t)b * L + sl[i]) * D + d];
        float x = p * t;
        out[((size_t)b * L + j) * D + d] = x;          // downsampled
        h = fmaf(1.f - p, h, x);
        g_scan[((size_t)b * L + j) * D + d] = h;
    }
}

// ---------------- Kernel 5: ups = gather(scan) + res + b_res ----------------
__global__ __launch_bounds__(256) void ups_kernel(
    float* __restrict__ out, const float* __restrict__ b_res)
{
    int row = blockIdx.x;          // b*L + l
    int b = row >> 12;
    int cid = g_chunkid[row];
    const float4* sc = (const float4*)(g_scan + (size_t)(b * L + cid) * D);
    const float4* rs = (const float4*)(g_res + (size_t)row * D);
    const float4* br = (const float4*)b_res;
    float4* o = (float4*)(out + BLD + (size_t)row * D);
    int t = threadIdx.x;
    float4 a = sc[t], c = rs[t], e = br[t];
    o[t] = make_float4(a.x + c.x + e.x, a.y + c.y + e.y,
                       a.z + c.z + e.z, a.w + c.w + e.w);
}

// ---------------- Kernel 6: finalize aux scalar -----------------------------
__global__ void aux_final_kernel(float* __restrict__ out)
{
    float s = 0.f;
    for (int i = 0; i < B; i++) s += g_auxb[i];
    out[2 * BLD] = (s / (float)B) * 0.03f;
}

// ---------------- launch ----------------------------------------------------
extern "C" void kernel_launch(void* const* d_in, const int* in_sizes, int n_in,
                              void* d_out, int out_size)
{
    const float* tokens = (const float*)d_in[0];
    const float* Wqk    = (const float*)d_in[1];
    const float* skey   = (const float*)d_in[2];
    const float* Wres   = (const float*)d_in[3];
    const float* bres   = (const float*)d_in[4];
    float* out = (float*)d_out;

    cudaFuncSetAttribute(gemm_kernel,
                         cudaFuncAttributeMaxDynamicSharedMemorySize, GEMM_SMEM);

    split_a_kernel<<<M * 128 / 256, 256>>>(tokens);
    split_b_kernel<<<NTOT * 128 / 256, 256>>>(Wqk, Wres);
    gemm_kernel<<<dim3(24, 256), 256, GEMM_SMEM>>>();
    probs_kernel<<<M, 128>>>(skey);
    fixup_kernel<<<M, 256>>>(tokens, Wqk, skey);
    boundary_kernel<<<B, 1024>>>();
    zero_down_kernel<<<M, 256>>>(out);
    chunk_scan_kernel<<<dim3(D / 128, L / 128, B), 128>>>(tokens, out);
    ups_kernel<<<M, 256>>>(out, bres);
    aux_final_kernel<<<1, 1>>>(out);
}

// round 10
// speedup vs baseline: 1.0900x; 1.0588x over previous
#include <cuda_runtime.h>
#include <cuda_bf16.h>
#include <cstdint>

#define B   8
#define L   4096
#define D   1024
#define DQK 1024
#define M   (B * L)           // 32768 tokens
#define BLD ((size_t)M * D)   // 33554432
#define NTOT 3072
#define TILE_B 16384          // one 128x64 bf16 tile (128B rows, swizzled)

// ---------------- scratch (device globals; no allocation allowed) ----------
__device__ float g_q[(size_t)M * DQK];     // 128 MiB
__device__ float g_k[(size_t)M * DQK];     // 128 MiB
__device__ float g_res[(size_t)M * D];     // 128 MiB
__device__ float g_scan[(size_t)M * D];    // 128 MiB
__device__ float g_probs[M];
__device__ int   g_flag[M];
__device__ int   g_chunkid[M];
__device__ int   g_blidx[M];
__device__ int   g_nch[B];
__device__ float g_auxb[B];

// PRE-SWIZZLED tiled layouts: [block][chunk 0..15][16KB tile]
__device__ __nv_bfloat16 g_Ahi [(size_t)M * 1024];
__device__ __nv_bfloat16 g_Amid[(size_t)M * 1024];
__device__ __nv_bfloat16 g_Bhi [(size_t)NTOT * 1024];
__device__ __nv_bfloat16 g_Bmid[(size_t)NTOT * 1024];

// ======================= helpers ===========================================
__device__ __forceinline__ uint32_t smem_u32(const void* p) {
    uint32_t a;
    asm("{ .reg .u64 t; cvta.to.shared.u64 t, %1; cvt.u32.u64 %0, t; }"
        : "=r"(a) : "l"(p));
    return a;
}
__device__ __forceinline__ void mbar_init(uint32_t a, uint32_t cnt) {
    asm volatile("mbarrier.init.shared.b64 [%0], %1;" :: "r"(a), "r"(cnt) : "memory");
}
__device__ __forceinline__ void mbar_expect_tx(uint32_t a, uint32_t bytes) {
    asm volatile("mbarrier.arrive.expect_tx.shared.b64 _, [%0], %1;"
                 :: "r"(a), "r"(bytes) : "memory");
}
__device__ __forceinline__ void mbar_wait(uint32_t a, uint32_t parity) {
    uint32_t done;
    asm volatile(
        "{\n\t.reg .pred p;\n\t"
        "mbarrier.try_wait.parity.acquire.cta.shared::cta.b64 p, [%1], %2;\n\t"
        "selp.b32 %0, 1, 0, p;\n\t}"
        : "=r"(done) : "r"(a), "r"(parity) : "memory");
    if (!done) {
        asm volatile(
            "{\n\t.reg .pred P1;\n\t"
            "WL_%=:\n\t"
            "mbarrier.try_wait.parity.acquire.cta.shared::cta.b64 P1, [%0], %1, 0x989680;\n\t"
            "@P1 bra.uni WD_%=;\n\t"
            "bra.uni WL_%=;\n\t"
            "WD_%=:\n\t}"
            :: "r"(a), "r"(parity) : "memory");
    }
}
__device__ __forceinline__ void bulk_cp(uint32_t dst, const void* src,
                                        uint32_t bytes, uint32_t mbar) {
    asm volatile(
        "cp.async.bulk.shared::cta.global.mbarrier::complete_tx::bytes "
        "[%0], [%1], %2, [%3];"
        :: "r"(dst), "l"(src), "r"(bytes), "r"(mbar) : "memory");
}
__device__ __forceinline__ void ldsm_x4(uint32_t addr, uint32_t& r0, uint32_t& r1,
                                        uint32_t& r2, uint32_t& r3) {
    asm volatile("ldmatrix.sync.aligned.m8n8.x4.shared.b16 {%0,%1,%2,%3}, [%4];"
                 : "=r"(r0), "=r"(r1), "=r"(r2), "=r"(r3) : "r"(addr));
}
__device__ __forceinline__ void mma_bf16(float* c,
                                         const uint32_t* a,
                                         uint32_t b0, uint32_t b1) {
    asm volatile(
        "mma.sync.aligned.m16n8k16.row.col.f32.bf16.bf16.f32 "
        "{%0,%1,%2,%3}, {%4,%5,%6,%7}, {%8,%9}, {%0,%1,%2,%3};"
        : "+f"(c[0]), "+f"(c[1]), "+f"(c[2]), "+f"(c[3])
        : "r"(a[0]), "r"(a[1]), "r"(a[2]), "r"(a[3]), "r"(b0), "r"(b1));
}

__device__ __forceinline__ size_t tile_addr(int block, int row, int kg) {
    int chunk = kg >> 3;
    int colB  = (kg & 7) * 16;
    int sw    = colB ^ ((row & 7) << 4);
    return ((size_t)block * 16 + chunk) * TILE_B + row * 128 + sw;
}

// ---------------- Prep 1: split tokens -> swizzled-tiled bf16 hi/mid --------
__global__ __launch_bounds__(256) void split_a_kernel(const float* __restrict__ A)
{
    int idx = blockIdx.x * 256 + threadIdx.x;      // 0 .. M*128-1
    int m  = idx >> 7;
    int kg = idx & 127;
    const float4* src = (const float4*)(A + (size_t)m * 1024 + kg * 8);
    float4 v0 = src[0], v1 = src[1];
    float x[8] = {v0.x, v0.y, v0.z, v0.w, v1.x, v1.y, v1.z, v1.w};
    unsigned short h[8], mm[8];
#pragma unroll
    for (int j = 0; j < 8; j++) {
        __nv_bfloat16 bh = __float2bfloat16_rn(x[j]);
        float r1 = x[j] - __bfloat162float(bh);
        __nv_bfloat16 bm = __float2bfloat16_rn(r1);
        h[j]  = __bfloat16_as_ushort(bh);
        mm[j] = __bfloat16_as_ushort(bm);
    }
    size_t a = tile_addr(m >> 7, m & 127, kg);
#define PACK4(arr) make_uint4((unsigned)arr[0] | ((unsigned)arr[1] << 16), \
                              (unsigned)arr[2] | ((unsigned)arr[3] << 16), \
                              (unsigned)arr[4] | ((unsigned)arr[5] << 16), \
                              (unsigned)arr[6] | ((unsigned)arr[7] << 16))
    *(uint4*)((char*)g_Ahi  + a) = PACK4(h);
    *(uint4*)((char*)g_Amid + a) = PACK4(mm);
}

// ---------------- Prep 2: split + transpose weights -> swizzled tiles -------
__global__ __launch_bounds__(256) void split_b_kernel(
    const float* __restrict__ Wqk, const float* __restrict__ Wres)
{
    int id = blockIdx.x * 256 + threadIdx.x;   // 0..393215
    int n  = id % NTOT;
    int kg = id / NTOT;
    unsigned short h[8], mm[8];
#pragma unroll
    for (int j = 0; j < 8; j++) {
        int k = kg * 8 + j;
        float x = (n < 2048) ? Wqk[(size_t)k * 2048 + n]
                             : Wres[(size_t)k * 1024 + (n - 2048)];
        __nv_bfloat16 bh = __float2bfloat16_rn(x);
        float r1 = x - __bfloat162float(bh);
        __nv_bfloat16 bm = __float2bfloat16_rn(r1);
        h[j]  = __bfloat16_as_ushort(bh);
        mm[j] = __bfloat16_as_ushort(bm);
    }
    size_t a = tile_addr(n >> 7, n & 127, kg);
    *(uint4*)((char*)g_Bhi  + a) = PACK4(h);
    *(uint4*)((char*)g_Bmid + a) = PACK4(mm);
#undef PACK4
}

// ---------------- Kernel 1: mma.sync split-bf16 GEMM ------------------------
// QK cols (n0<2048): SINGLE product hi*hi (cos err ~2e-4; sign-critical cases
// recomputed exactly by fixup_kernel, band 2e-3).
// Res cols: 3 products hi*hi + hi*mid + mid*hi (element err ~1.5e-5).
#define STAGE_BYTES (4 * TILE_B)    // 64 KB
#define GEMM_SMEM   (128 + 3 * STAGE_BYTES)

__global__ void __launch_bounds__(256, 1) gemm_kernel()
{
    extern __shared__ char smem[];
    uint32_t sb = smem_u32(smem);
    const int tid = threadIdx.x;
    const int lane = tid & 31;
    const int wid = tid >> 5;
    const int warp_m = wid & 3;
    const int warp_n = wid >> 2;
    const int m0 = blockIdx.y * 128;
    const int n0 = blockIdx.x * 128;
    const int isres = (n0 >= 2048);
    const uint32_t txbytes = isres ? (uint32_t)STAGE_BYTES : (uint32_t)(2 * TILE_B);

    const char* gsrc[4];
    gsrc[0] = (const char*)g_Ahi  + (size_t)(m0 >> 7) * 16 * TILE_B;
    gsrc[1] = (const char*)g_Amid + (size_t)(m0 >> 7) * 16 * TILE_B;
    gsrc[2] = (const char*)g_Bhi  + (size_t)(n0 >> 7) * 16 * TILE_B;
    gsrc[3] = (const char*)g_Bmid + (size_t)(n0 >> 7) * 16 * TILE_B;

    if (tid == 0) {
        mbar_init(sb + 0, 1);
        mbar_init(sb + 8, 1);
        mbar_init(sb + 16, 1);
    }
    __syncthreads();

    float acc[2][8][4];
#pragma unroll
    for (int i = 0; i < 2; i++)
#pragma unroll
        for (int j = 0; j < 8; j++)
#pragma unroll
            for (int q = 0; q < 4; q++) acc[i][j][q] = 0.f;

    const int aRow  = warp_m * 32 + (lane & 15);
    const int aXor  = (aRow & 7) << 4;
    const int aColB = (lane >> 4) * 16;
    const int bRow  = warp_n * 64 + (lane & 7) + ((lane >> 4) & 1) * 8;
    const int bXor  = (bRow & 7) << 4;
    const int bColB = ((lane >> 3) & 1) * 16;

    // prologue: issue chunks 0 and 1
    if (tid == 0) {
#pragma unroll
        for (int c = 0; c < 2; c++) {
            uint32_t mb = sb + c * 8;
            uint32_t st = sb + 128 + c * STAGE_BYTES;
            mbar_expect_tx(mb, txbytes);
            bulk_cp(st,              gsrc[0] + (size_t)c * TILE_B, TILE_B, mb);
            bulk_cp(st + 2 * TILE_B, gsrc[2] + (size_t)c * TILE_B, TILE_B, mb);
            if (isres) {
                bulk_cp(st + TILE_B,     gsrc[1] + (size_t)c * TILE_B, TILE_B, mb);
                bulk_cp(st + 3 * TILE_B, gsrc[3] + (size_t)c * TILE_B, TILE_B, mb);
            }
        }
    }

#pragma unroll 1
    for (int c = 0; c < 16; c++) {
        int s = c % 3;
        uint32_t stage = sb + 128 + s * STAGE_BYTES;
        if (c < 14 && tid == 0) {
            int s2 = (c + 2) % 3;
            uint32_t mb = sb + s2 * 8;
            uint32_t st = sb + 128 + s2 * STAGE_BYTES;
            mbar_expect_tx(mb, txbytes);
            bulk_cp(st,              gsrc[0] + (size_t)(c + 2) * TILE_B, TILE_B, mb);
            bulk_cp(st + 2 * TILE_B, gsrc[2] + (size_t)(c + 2) * TILE_B, TILE_B, mb);
            if (isres) {
                bulk_cp(st + TILE_B,     gsrc[1] + (size_t)(c + 2) * TILE_B, TILE_B, mb);
                bulk_cp(st + 3 * TILE_B, gsrc[3] + (size_t)(c + 2) * TILE_B, TILE_B, mb);
            }
        }
        mbar_wait(sb + s * 8, (c / 3) & 1);
        __syncthreads();

        uint32_t aHi = stage, aMid = stage + TILE_B;
        uint32_t bHi = stage + 2 * TILE_B, bMid = stage + 3 * TILE_B;
        if (!isres) {
            // single product: hi * hi
#pragma unroll 1
            for (int ks = 0; ks < 4; ks++) {
                uint32_t ah[2][4];
#pragma unroll
                for (int mi = 0; mi < 2; mi++) {
                    uint32_t roff = (aRow + mi * 16) * 128 + ((ks * 32 + aColB) ^ aXor);
                    ldsm_x4(aHi + roff, ah[mi][0], ah[mi][1], ah[mi][2], ah[mi][3]);
                }
#pragma unroll
                for (int ng = 0; ng < 4; ng++) {
                    uint32_t roff = (bRow + ng * 16) * 128 + ((ks * 32 + bColB) ^ bXor);
                    uint32_t b0, b1, b2, b3;
                    ldsm_x4(bHi + roff, b0, b1, b2, b3);
                    mma_bf16(acc[0][ng*2],   ah[0], b0, b1);
                    mma_bf16(acc[0][ng*2+1], ah[0], b2, b3);
                    mma_bf16(acc[1][ng*2],   ah[1], b0, b1);
                    mma_bf16(acc[1][ng*2+1], ah[1], b2, b3);
                }
            }
        } else {
#pragma unroll 1
            for (int ks = 0; ks < 4; ks++) {
                uint32_t ah[2][4], am[2][4];
#pragma unroll
                for (int mi = 0; mi < 2; mi++) {
                    uint32_t roff = (aRow + mi * 16) * 128 + ((ks * 32 + aColB) ^ aXor);
                    ldsm_x4(aHi  + roff, ah[mi][0], ah[mi][1], ah[mi][2], ah[mi][3]);
                    ldsm_x4(aMid + roff, am[mi][0], am[mi][1], am[mi][2], am[mi][3]);
                }
#pragma unroll
                for (int ng = 0; ng < 4; ng++) {
                    uint32_t roff = (bRow + ng * 16) * 128 + ((ks * 32 + bColB) ^ bXor);
                    uint32_t b0, b1, b2, b3;
                    ldsm_x4(bHi + roff, b0, b1, b2, b3);
                    mma_bf16(acc[0][ng*2],   ah[0], b0, b1);
                    mma_bf16(acc[0][ng*2+1], ah[0], b2, b3);
                    mma_bf16(acc[1][ng*2],   ah[1], b0, b1);
                    mma_bf16(acc[1][ng*2+1], ah[1], b2, b3);
                    mma_bf16(acc[0][ng*2],   am[0], b0, b1);
                    mma_bf16(acc[0][ng*2+1], am[0], b2, b3);
                    mma_bf16(acc[1][ng*2],   am[1], b0, b1);
                    mma_bf16(acc[1][ng*2+1], am[1], b2, b3);
                    ldsm_x4(bMid + roff, b0, b1, b2, b3);
                    mma_bf16(acc[0][ng*2],   ah[0], b0, b1);
                    mma_bf16(acc[0][ng*2+1], ah[0], b2, b3);
                    mma_bf16(acc[1][ng*2],   ah[1], b0, b1);
                    mma_bf16(acc[1][ng*2+1], ah[1], b2, b3);
                }
            }
        }
        __syncthreads();
    }

    float* cbase; int coloff;
    if (n0 < 1024)      { cbase = g_q;   coloff = n0; }
    else if (n0 < 2048) { cbase = g_k;   coloff = n0 - 1024; }
    else                { cbase = g_res; coloff = n0 - 2048; }

#pragma unroll
    for (int mi = 0; mi < 2; mi++) {
        int r0 = m0 + warp_m * 32 + mi * 16 + (lane >> 2);
#pragma unroll
        for (int ni = 0; ni < 8; ni++) {
            int col = coloff + warp_n * 64 + ni * 8 + (lane & 3) * 2;
            *(float2*)&cbase[(size_t)r0 * 1024 + col] =
                make_float2(acc[mi][ni][0], acc[mi][ni][1]);
            *(float2*)&cbase[(size_t)(r0 + 8) * 1024 + col] =
                make_float2(acc[mi][ni][2], acc[mi][ni][3]);
        }
    }
}

// ---------------- Kernel 2: per-token cosine -> probs + near-zero flag ------
__global__ __launch_bounds__(128) void probs_kernel(const float* __restrict__ start_key)
{
    int token = blockIdx.x;
    int l = token & (L - 1);
    const float4* qv = (const float4*)(g_q + (size_t)token * DQK);
    const float4* kv = (l == 0) ? (const float4*)start_key
                                : (const float4*)(g_k + (size_t)(token - 1) * DQK);
    float dot = 0.f, qq = 0.f, kk = 0.f;
    for (int i = threadIdx.x; i < DQK / 4; i += 128) {
        float4 a = qv[i], c = kv[i];
        dot += a.x * c.x + a.y * c.y + a.z * c.z + a.w * c.w;
        qq  += a.x * a.x + a.y * a.y + a.z * a.z + a.w * a.w;
        kk  += c.x * c.x + c.y * c.y + c.z * c.z + c.w * c.w;
    }
#pragma unroll
    for (int o = 16; o; o >>= 1) {
        dot += __shfl_down_sync(0xffffffffu, dot, o);
        qq  += __shfl_down_sync(0xffffffffu, qq,  o);
        kk  += __shfl_down_sync(0xffffffffu, kk,  o);
    }
    __shared__ float sd[4], sq[4], sk[4];
    int w = threadIdx.x >> 5;
    if ((threadIdx.x & 31) == 0) { sd[w] = dot; sq[w] = qq; sk[w] = kk; }
    __syncthreads();
    if (threadIdx.x == 0) {
        dot = sd[0] + sd[1] + sd[2] + sd[3];
        qq  = sq[0] + sq[1] + sq[2] + sq[3];
        kk  = sk[0] + sk[1] + sk[2] + sk[3];
        float denom = fmaxf(sqrtf(qq) * sqrtf(kk), 1e-8f);
        float cosv = dot / denom;
        g_probs[token] = (1.0f - cosv) * 0.5f;
        g_flag[token] = (fabsf(cosv) < 2e-3f) ? 1 : 0;
    }
}

// ---------------- Kernel 2b: exact fp32 fixup for near-threshold tokens -----
__global__ __launch_bounds__(256) void fixup_kernel(
    const float* __restrict__ tokens, const float* __restrict__ Wqk,
    const float* __restrict__ start_key)
{
    int token = blockIdx.x;
    if (!g_flag[token]) return;
    int l = token & (L - 1);
    int tid = threadIdx.x;

    __shared__ float cur[1024], prev[1024];
    __shared__ float qv[1024], kv[1024];
    __shared__ float red[3][8];

    for (int i = tid; i < 1024; i += 256) {
        cur[i]  = tokens[(size_t)token * D + i];
        prev[i] = (l > 0) ? tokens[(size_t)(token - 1) * D + i] : 0.f;
    }
    __syncthreads();

#pragma unroll
    for (int j = 0; j < 4; j++) {
        int e = tid + j * 256;
        float accq = 0.f;
        for (int d = 0; d < 1024; d++)
            accq = fmaf(cur[d], Wqk[(size_t)d * 2048 + e], accq);
        qv[e] = accq;
        if (l > 0) {
            float acck = 0.f;
            for (int d = 0; d < 1024; d++)
                acck = fmaf(prev[d], Wqk[(size_t)d * 2048 + 1024 + e], acck);
            kv[e] = acck;
        } else {
            kv[e] = start_key[e];
        }
    }
    __syncthreads();

    float dot = 0.f, qq = 0.f, kk = 0.f;
    for (int i = tid; i < 1024; i += 256) {
        float a = qv[i], c = kv[i];
        dot = fmaf(a, c, dot); qq = fmaf(a, a, qq); kk = fmaf(c, c, kk);
    }
#pragma unroll
    for (int o = 16; o; o >>= 1) {
        dot += __shfl_down_sync(0xffffffffu, dot, o);
        qq  += __shfl_down_sync(0xffffffffu, qq,  o);
        kk  += __shfl_down_sync(0xffffffffu, kk,  o);
    }
    int w = tid >> 5;
    if ((tid & 31) == 0) { red[0][w] = dot; red[1][w] = qq; red[2][w] = kk; }
    __syncthreads();
    if (tid == 0) {
        dot = 0.f; qq = 0.f; kk = 0.f;
#pragma unroll
        for (int i = 0; i < 8; i++) { dot += red[0][i]; qq += red[1][i]; kk += red[2][i]; }
        float denom = fmaxf(sqrtf(qq) * sqrtf(kk), 1e-8f);
        g_probs[token] = (1.0f - dot / denom) * 0.5f;
    }
}

// ---------------- Kernel 3: per-batch boundary scan + aux -------------------
__global__ __launch_bounds__(1024) void boundary_kernel()
{
    int b = blockIdx.x;
    int tid = threadIdx.x;
    __shared__ int   s[1024];
    __shared__ float sf[1024];

    int l0 = tid * 4;
    float p[4]; int bd[4]; int cnt = 0; float psum = 0.f;
#pragma unroll
    for (int i = 0; i < 4; i++) {
        int l = l0 + i;
        p[i] = g_probs[b * L + l];
        bd[i] = (l == 0) || (p[i] > 0.5f);
        cnt += bd[i];
        psum += p[i];
    }
    s[tid] = cnt;
    sf[tid] = psum;
    __syncthreads();
    for (int off = 1; off < 1024; off <<= 1) {
        int v = (tid >= off) ? s[tid - off] : 0;
        __syncthreads();
        if (tid >= off) s[tid] += v;
        __syncthreads();
    }
    int incl = s[tid];
    int base = incl - cnt;
    int total = s[1023];
    int run = base;
#pragma unroll
    for (int i = 0; i < 4; i++) {
        int l = l0 + i;
        if (bd[i]) { g_blidx[b * L + run] = l; run++; }
        g_chunkid[b * L + l] = run - 1;
    }
    __syncthreads();
    for (int off = 512; off > 0; off >>= 1) {
        if (tid < off) sf[tid] += sf[tid + off];
        __syncthreads();
    }
    if (tid == 0) {
        float F = (float)total / (float)L;
        float G = sf[0] / (float)L;
        g_auxb[b] = 1.2f * (5.0f * F * G + (1.0f - F) * (1.0f - G));
        g_nch[b] = total;
    }
}

// ---------------- Kernel 4a: zero padded chunk slots of downsampled ---------
__global__ __launch_bounds__(256) void zero_down_kernel(float* __restrict__ out)
{
    int row = blockIdx.x;          // b*L + j
    int b = row >> 12;
    int j = row & (L - 1);
    if (j < g_nch[b]) return;
    float4* o = (float4*)(out + (size_t)row * D);
    o[threadIdx.x] = make_float4(0.f, 0.f, 0.f, 0.f);
}

// ---------------- Kernel 4b: windowed-parallel chunk EMA scan ---------------
__global__ __launch_bounds__(128) void chunk_scan_kernel(
    const float* __restrict__ tokens, float* __restrict__ out)
{
    int b = blockIdx.z;
    int nch = g_nch[b];
    int j0 = blockIdx.y * 128;
    if (j0 >= nch) return;
    int d = blockIdx.x * 128 + threadIdx.x;
    int jstart = (j0 >= 64) ? (j0 - 64) : 0;
    int jend = min(j0 + 128, nch);
    int cnt = jend - jstart;

    __shared__ int   sl[192];
    __shared__ float sp[192];
    for (int i = threadIdx.x; i < cnt; i += 128) {
        int l = g_blidx[b * L + jstart + i];
        sl[i] = l;
        sp[i] = g_probs[b * L + l];
    }
    __syncthreads();

    float h = 0.f;
    int i = 0;
    int warm = j0 - jstart;
    for (; i < warm; i++) {
        float p = sp[i];
        float t = tokens[((size_t)b * L + sl[i]) * D + d];
        h = fmaf(1.f - p, h, p * t);
    }
    for (; i < cnt; i++) {
        int j = jstart + i;
        float p = sp[i];
        float t = tokens[((size_t)b * L + sl[i]) * D + d];
        float x = p * t;
        out[((size_t)b * L + j) * D + d] = x;          // downsampled
        h = fmaf(1.f - p, h, x);
        g_scan[((size_t)b * L + j) * D + d] = h;
    }
}

// ---------------- Kernel 5: ups = gather(scan) + res + b_res ----------------
__global__ __launch_bounds__(256) void ups_kernel(
    float* __restrict__ out, const float* __restrict__ b_res)
{
    int row = blockIdx.x;          // b*L + l
    int b = row >> 12;
    int cid = g_chunkid[row];
    const float4* sc = (const float4*)(g_scan + (size_t)(b * L + cid) * D);
    const float4* rs = (const float4*)(g_res + (size_t)row * D);
    const float4* br = (const float4*)b_res;
    float4* o = (float4*)(out + BLD + (size_t)row * D);
    int t = threadIdx.x;
    float4 a = sc[t], c = rs[t], e = br[t];
    o[t] = make_float4(a.x + c.x + e.x, a.y + c.y + e.y,
                       a.z + c.z + e.z, a.w + c.w + e.w);
}

// ---------------- Kernel 6: finalize aux scalar -----------------------------
__global__ void aux_final_kernel(float* __restrict__ out)
{
    float s = 0.f;
    for (int i = 0; i < B; i++) s += g_auxb[i];
    out[2 * BLD] = (s / (float)B) * 0.03f;
}

// ---------------- launch ----------------------------------------------------
extern "C" void kernel_launch(void* const* d_in, const int* in_sizes, int n_in,
                              void* d_out, int out_size)
{
    const float* tokens = (const float*)d_in[0];
    const float* Wqk    = (const float*)d_in[1];
    const float* skey   = (const float*)d_in[2];
    const float* Wres   = (const float*)d_in[3];
    const float* bres   = (const float*)d_in[4];
    float* out = (float*)d_out;

    cudaFuncSetAttribute(gemm_kernel,
                         cudaFuncAttributeMaxDynamicSharedMemorySize, GEMM_SMEM);

    split_a_kernel<<<M * 128 / 256, 256>>>(tokens);
    split_b_kernel<<<NTOT * 128 / 256, 256>>>(Wqk, Wres);
    gemm_kernel<<<dim3(24, 256), 256, GEMM_SMEM>>>();
    probs_kernel<<<M, 128>>>(skey);
    fixup_kernel<<<M, 256>>>(tokens, Wqk, skey);
    boundary_kernel<<<B, 1024>>>();
    zero_down_kernel<<<M, 256>>>(out);
    chunk_scan_kernel<<<dim3(D / 128, L / 128, B), 128>>>(tokens, out);
    ups_kernel<<<M, 256>>>(out, bres);
    aux_final_kernel<<<1, 1>>>(out);
}

// round 11
// speedup vs baseline: 1.6614x; 1.5241x over previous
#include <cuda_runtime.h>
#include <cuda_bf16.h>
#include <cstdint>

#define B   8
#define L   4096
#define D   1024
#define DQK 1024
#define M   (B * L)           // 32768 tokens
#define BLD ((size_t)M * D)   // 33554432
#define NTOT 3072
#define TILE_B 16384          // one 128x64 bf16 tile (128B rows, swizzled)

// ---------------- scratch (device globals; no allocation allowed) ----------
__device__ float g_q[(size_t)M * DQK];     // 128 MiB
__device__ float g_k[(size_t)M * DQK];     // 128 MiB
__device__ float g_res[(size_t)M * D];     // 128 MiB
__device__ float g_scan[(size_t)M * D];    // 128 MiB
__device__ float g_probs[M];
__device__ int   g_flag[M];
__device__ int   g_fixlist[M];
__device__ int   g_nfix;
__device__ int   g_nfixpad;
__device__ int   g_chunkid[M];
__device__ int   g_blidx[M];
__device__ int   g_nch[B];
__device__ float g_auxb[B];

// PRE-SWIZZLED tiled layouts: [block][chunk 0..15][16KB tile]
__device__ __nv_bfloat16 g_Ahi [(size_t)M * 1024];
__device__ __nv_bfloat16 g_Amid[(size_t)M * 1024];
__device__ __nv_bfloat16 g_Bhi [(size_t)NTOT * 1024];
__device__ __nv_bfloat16 g_Bmid[(size_t)NTOT * 1024];

// ======================= helpers ===========================================
__device__ __forceinline__ uint32_t smem_u32(const void* p) {
    uint32_t a;
    asm("{ .reg .u64 t; cvta.to.shared.u64 t, %1; cvt.u32.u64 %0, t; }"
        : "=r"(a) : "l"(p));
    return a;
}
__device__ __forceinline__ void mbar_init(uint32_t a, uint32_t cnt) {
    asm volatile("mbarrier.init.shared.b64 [%0], %1;" :: "r"(a), "r"(cnt) : "memory");
}
__device__ __forceinline__ void mbar_expect_tx(uint32_t a, uint32_t bytes) {
    asm volatile("mbarrier.arrive.expect_tx.shared.b64 _, [%0], %1;"
                 :: "r"(a), "r"(bytes) : "memory");
}
__device__ __forceinline__ void mbar_wait(uint32_t a, uint32_t parity) {
    uint32_t done;
    asm volatile(
        "{\n\t.reg .pred p;\n\t"
        "mbarrier.try_wait.parity.acquire.cta.shared::cta.b64 p, [%1], %2;\n\t"
        "selp.b32 %0, 1, 0, p;\n\t}"
        : "=r"(done) : "r"(a), "r"(parity) : "memory");
    if (!done) {
        asm volatile(
            "{\n\t.reg .pred P1;\n\t"
            "WL_%=:\n\t"
            "mbarrier.try_wait.parity.acquire.cta.shared::cta.b64 P1, [%0], %1, 0x989680;\n\t"
            "@P1 bra.uni WD_%=;\n\t"
            "bra.uni WL_%=;\n\t"
            "WD_%=:\n\t}"
            :: "r"(a), "r"(parity) : "memory");
    }
}
__device__ __forceinline__ void bulk_cp(uint32_t dst, const void* src,
                                        uint32_t bytes, uint32_t mbar) {
    asm volatile(
        "cp.async.bulk.shared::cta.global.mbarrier::complete_tx::bytes "
        "[%0], [%1], %2, [%3];"
        :: "r"(dst), "l"(src), "r"(bytes), "r"(mbar) : "memory");
}
__device__ __forceinline__ void ldsm_x4(uint32_t addr, uint32_t& r0, uint32_t& r1,
                                        uint32_t& r2, uint32_t& r3) {
    asm volatile("ldmatrix.sync.aligned.m8n8.x4.shared.b16 {%0,%1,%2,%3}, [%4];"
                 : "=r"(r0), "=r"(r1), "=r"(r2), "=r"(r3) : "r"(addr));
}
__device__ __forceinline__ void mma_bf16(float* c,
                                         const uint32_t* a,
                                         uint32_t b0, uint32_t b1) {
    asm volatile(
        "mma.sync.aligned.m16n8k16.row.col.f32.bf16.bf16.f32 "
        "{%0,%1,%2,%3}, {%4,%5,%6,%7}, {%8,%9}, {%0,%1,%2,%3};"
        : "+f"(c[0]), "+f"(c[1]), "+f"(c[2]), "+f"(c[3])
        : "r"(a[0]), "r"(a[1]), "r"(a[2]), "r"(a[3]), "r"(b0), "r"(b1));
}

__device__ __forceinline__ size_t tile_addr(int block, int row, int kg) {
    int chunk = kg >> 3;
    int colB  = (kg & 7) * 16;
    int sw    = colB ^ ((row & 7) << 4);
    return ((size_t)block * 16 + chunk) * TILE_B + row * 128 + sw;
}

// ---------------- Prep 1: split tokens -> swizzled-tiled bf16 hi/mid --------
__global__ __launch_bounds__(256) void split_a_kernel(const float* __restrict__ A)
{
    int idx = blockIdx.x * 256 + threadIdx.x;      // 0 .. M*128-1
    int m  = idx >> 7;
    int kg = idx & 127;
    const float4* src = (const float4*)(A + (size_t)m * 1024 + kg * 8);
    float4 v0 = src[0], v1 = src[1];
    float x[8] = {v0.x, v0.y, v0.z, v0.w, v1.x, v1.y, v1.z, v1.w};
    unsigned short h[8], mm[8];
#pragma unroll
    for (int j = 0; j < 8; j++) {
        __nv_bfloat16 bh = __float2bfloat16_rn(x[j]);
        float r1 = x[j] - __bfloat162float(bh);
        __nv_bfloat16 bm = __float2bfloat16_rn(r1);
        h[j]  = __bfloat16_as_ushort(bh);
        mm[j] = __bfloat16_as_ushort(bm);
    }
    size_t a = tile_addr(m >> 7, m & 127, kg);
#define PACK4(arr) make_uint4((unsigned)arr[0] | ((unsigned)arr[1] << 16), \
                              (unsigned)arr[2] | ((unsigned)arr[3] << 16), \
                              (unsigned)arr[4] | ((unsigned)arr[5] << 16), \
                              (unsigned)arr[6] | ((unsigned)arr[7] << 16))
    *(uint4*)((char*)g_Ahi  + a) = PACK4(h);
    *(uint4*)((char*)g_Amid + a) = PACK4(mm);
}

// ---------------- Prep 2: split + transpose weights -> swizzled tiles -------
__global__ __launch_bounds__(256) void split_b_kernel(
    const float* __restrict__ Wqk, const float* __restrict__ Wres)
{
    int id = blockIdx.x * 256 + threadIdx.x;   // 0..393215
    int n  = id % NTOT;
    int kg = id / NTOT;
    unsigned short h[8], mm[8];
#pragma unroll
    for (int j = 0; j < 8; j++) {
        int k = kg * 8 + j;
        float x = (n < 2048) ? Wqk[(size_t)k * 2048 + n]
                             : Wres[(size_t)k * 1024 + (n - 2048)];
        __nv_bfloat16 bh = __float2bfloat16_rn(x);
        float r1 = x - __bfloat162float(bh);
        __nv_bfloat16 bm = __float2bfloat16_rn(r1);
        h[j]  = __bfloat16_as_ushort(bh);
        mm[j] = __bfloat16_as_ushort(bm);
    }
    size_t a = tile_addr(n >> 7, n & 127, kg);
    *(uint4*)((char*)g_Bhi  + a) = PACK4(h);
    *(uint4*)((char*)g_Bmid + a) = PACK4(mm);
#undef PACK4
}

// ---------------- Kernel 1: mma.sync split-bf16 GEMM ------------------------
// QK cols (n0<2048): SINGLE product hi*hi (sign-critical cases re-done by the
// gathered fixup GEMM below). Res cols: 3 products.
#define STAGE_BYTES (4 * TILE_B)    // 64 KB
#define GEMM_SMEM   (128 + 3 * STAGE_BYTES)

__global__ void __launch_bounds__(256, 1) gemm_kernel()
{
    extern __shared__ char smem[];
    uint32_t sb = smem_u32(smem);
    const int tid = threadIdx.x;
    const int lane = tid & 31;
    const int wid = tid >> 5;
    const int warp_m = wid & 3;
    const int warp_n = wid >> 2;
    const int m0 = blockIdx.y * 128;
    const int n0 = blockIdx.x * 128;
    const int isres = (n0 >= 2048);
    const uint32_t txbytes = isres ? (uint32_t)STAGE_BYTES : (uint32_t)(2 * TILE_B);

    const char* gsrc[4];
    gsrc[0] = (const char*)g_Ahi  + (size_t)(m0 >> 7) * 16 * TILE_B;
    gsrc[1] = (const char*)g_Amid + (size_t)(m0 >> 7) * 16 * TILE_B;
    gsrc[2] = (const char*)g_Bhi  + (size_t)(n0 >> 7) * 16 * TILE_B;
    gsrc[3] = (const char*)g_Bmid + (size_t)(n0 >> 7) * 16 * TILE_B;

    if (tid == 0) {
        mbar_init(sb + 0, 1);
        mbar_init(sb + 8, 1);
        mbar_init(sb + 16, 1);
    }
    __syncthreads();

    float acc[2][8][4];
#pragma unroll
    for (int i = 0; i < 2; i++)
#pragma unroll
        for (int j = 0; j < 8; j++)
#pragma unroll
            for (int q = 0; q < 4; q++) acc[i][j][q] = 0.f;

    const int aRow  = warp_m * 32 + (lane & 15);
    const int aXor  = (aRow & 7) << 4;
    const int aColB = (lane >> 4) * 16;
    const int bRow  = warp_n * 64 + (lane & 7) + ((lane >> 4) & 1) * 8;
    const int bXor  = (bRow & 7) << 4;
    const int bColB = ((lane >> 3) & 1) * 16;

    if (tid == 0) {
#pragma unroll
        for (int c = 0; c < 2; c++) {
            uint32_t mb = sb + c * 8;
            uint32_t st = sb + 128 + c * STAGE_BYTES;
            mbar_expect_tx(mb, txbytes);
            bulk_cp(st,              gsrc[0] + (size_t)c * TILE_B, TILE_B, mb);
            bulk_cp(st + 2 * TILE_B, gsrc[2] + (size_t)c * TILE_B, TILE_B, mb);
            if (isres) {
                bulk_cp(st + TILE_B,     gsrc[1] + (size_t)c * TILE_B, TILE_B, mb);
                bulk_cp(st + 3 * TILE_B, gsrc[3] + (size_t)c * TILE_B, TILE_B, mb);
            }
        }
    }

#pragma unroll 1
    for (int c = 0; c < 16; c++) {
        int s = c % 3;
        uint32_t stage = sb + 128 + s * STAGE_BYTES;
        if (c < 14 && tid == 0) {
            int s2 = (c + 2) % 3;
            uint32_t mb = sb + s2 * 8;
            uint32_t st = sb + 128 + s2 * STAGE_BYTES;
            mbar_expect_tx(mb, txbytes);
            bulk_cp(st,              gsrc[0] + (size_t)(c + 2) * TILE_B, TILE_B, mb);
            bulk_cp(st + 2 * TILE_B, gsrc[2] + (size_t)(c + 2) * TILE_B, TILE_B, mb);
            if (isres) {
                bulk_cp(st + TILE_B,     gsrc[1] + (size_t)(c + 2) * TILE_B, TILE_B, mb);
                bulk_cp(st + 3 * TILE_B, gsrc[3] + (size_t)(c + 2) * TILE_B, TILE_B, mb);
            }
        }
        mbar_wait(sb + s * 8, (c / 3) & 1);
        __syncthreads();

        uint32_t aHi = stage, aMid = stage + TILE_B;
        uint32_t bHi = stage + 2 * TILE_B, bMid = stage + 3 * TILE_B;
        if (!isres) {
#pragma unroll 1
            for (int ks = 0; ks < 4; ks++) {
                uint32_t ah[2][4];
#pragma unroll
                for (int mi = 0; mi < 2; mi++) {
                    uint32_t roff = (aRow + mi * 16) * 128 + ((ks * 32 + aColB) ^ aXor);
                    ldsm_x4(aHi + roff, ah[mi][0], ah[mi][1], ah[mi][2], ah[mi][3]);
                }
#pragma unroll
                for (int ng = 0; ng < 4; ng++) {
                    uint32_t roff = (bRow + ng * 16) * 128 + ((ks * 32 + bColB) ^ bXor);
                    uint32_t b0, b1, b2, b3;
                    ldsm_x4(bHi + roff, b0, b1, b2, b3);
                    mma_bf16(acc[0][ng*2],   ah[0], b0, b1);
                    mma_bf16(acc[0][ng*2+1], ah[0], b2, b3);
                    mma_bf16(acc[1][ng*2],   ah[1], b0, b1);
                    mma_bf16(acc[1][ng*2+1], ah[1], b2, b3);
                }
            }
        } else {
#pragma unroll 1
            for (int ks = 0; ks < 4; ks++) {
                uint32_t ah[2][4], am[2][4];
#pragma unroll
                for (int mi = 0; mi < 2; mi++) {
                    uint32_t roff = (aRow + mi * 16) * 128 + ((ks * 32 + aColB) ^ aXor);
                    ldsm_x4(aHi  + roff, ah[mi][0], ah[mi][1], ah[mi][2], ah[mi][3]);
                    ldsm_x4(aMid + roff, am[mi][0], am[mi][1], am[mi][2], am[mi][3]);
                }
#pragma unroll
                for (int ng = 0; ng < 4; ng++) {
                    uint32_t roff = (bRow + ng * 16) * 128 + ((ks * 32 + bColB) ^ bXor);
                    uint32_t b0, b1, b2, b3;
                    ldsm_x4(bHi + roff, b0, b1, b2, b3);
                    mma_bf16(acc[0][ng*2],   ah[0], b0, b1);
                    mma_bf16(acc[0][ng*2+1], ah[0], b2, b3);
                    mma_bf16(acc[1][ng*2],   ah[1], b0, b1);
                    mma_bf16(acc[1][ng*2+1], ah[1], b2, b3);
                    mma_bf16(acc[0][ng*2],   am[0], b0, b1);
                    mma_bf16(acc[0][ng*2+1], am[0], b2, b3);
                    mma_bf16(acc[1][ng*2],   am[1], b0, b1);
                    mma_bf16(acc[1][ng*2+1], am[1], b2, b3);
                    ldsm_x4(bMid + roff, b0, b1, b2, b3);
                    mma_bf16(acc[0][ng*2],   ah[0], b0, b1);
                    mma_bf16(acc[0][ng*2+1], ah[0], b2, b3);
                    mma_bf16(acc[1][ng*2],   ah[1], b0, b1);
                    mma_bf16(acc[1][ng*2+1], ah[1], b2, b3);
                }
            }
        }
        __syncthreads();
    }

    float* cbase; int coloff;
    if (n0 < 1024)      { cbase = g_q;   coloff = n0; }
    else if (n0 < 2048) { cbase = g_k;   coloff = n0 - 1024; }
    else                { cbase = g_res; coloff = n0 - 2048; }

#pragma unroll
    for (int mi = 0; mi < 2; mi++) {
        int r0 = m0 + warp_m * 32 + mi * 16 + (lane >> 2);
#pragma unroll
        for (int ni = 0; ni < 8; ni++) {
            int col = coloff + warp_n * 64 + ni * 8 + (lane & 3) * 2;
            *(float2*)&cbase[(size_t)r0 * 1024 + col] =
                make_float2(acc[mi][ni][0], acc[mi][ni][1]);
            *(float2*)&cbase[(size_t)(r0 + 8) * 1024 + col] =
                make_float2(acc[mi][ni][2], acc[mi][ni][3]);
        }
    }
}

// ---------------- zero fix counter ------------------------------------------
__global__ void zero_nfix_kernel() { g_nfix = 0; }

// ---------------- Kernel 2: cosine -> probs + flag + compact list -----------
__global__ __launch_bounds__(128) void probs_kernel(const float* __restrict__ start_key)
{
    int token = blockIdx.x;
    int l = token & (L - 1);
    const float4* qv = (const float4*)(g_q + (size_t)token * DQK);
    const float4* kv = (l == 0) ? (const float4*)start_key
                                : (const float4*)(g_k + (size_t)(token - 1) * DQK);
    float dot = 0.f, qq = 0.f, kk = 0.f;
    for (int i = threadIdx.x; i < DQK / 4; i += 128) {
        float4 a = qv[i], c = kv[i];
        dot += a.x * c.x + a.y * c.y + a.z * c.z + a.w * c.w;
        qq  += a.x * a.x + a.y * a.y + a.z * a.z + a.w * a.w;
        kk  += c.x * c.x + c.y * c.y + c.z * c.z + c.w * c.w;
    }
#pragma unroll
    for (int o = 16; o; o >>= 1) {
        dot += __shfl_down_sync(0xffffffffu, dot, o);
        qq  += __shfl_down_sync(0xffffffffu, qq,  o);
        kk  += __shfl_down_sync(0xffffffffu, kk,  o);
    }
    __shared__ float sd[4], sq[4], sk[4];
    int w = threadIdx.x >> 5;
    if ((threadIdx.x & 31) == 0) { sd[w] = dot; sq[w] = qq; sk[w] = kk; }
    __syncthreads();
    if (threadIdx.x == 0) {
        dot = sd[0] + sd[1] + sd[2] + sd[3];
        qq  = sq[0] + sq[1] + sq[2] + sq[3];
        kk  = sk[0] + sk[1] + sk[2] + sk[3];
        float denom = fmaxf(sqrtf(qq) * sqrtf(kk), 1e-8f);
        float cosv = dot / denom;
        g_probs[token] = (1.0f - cosv) * 0.5f;
        int fl = (fabsf(cosv) < 2e-3f) ? 1 : 0;
        g_flag[token] = fl;
        if (fl) {
            int slot = atomicAdd(&g_nfix, 1);
            g_fixlist[slot] = token;
        }
    }
}

// ---------------- pad fix list to multiple of 128 ---------------------------
__global__ void pad_fix_kernel()
{
    int nf = g_nfix;
    int np = (nf + 127) & ~127;
    if (nf > 0)
        for (int i = nf; i < np; i++) g_fixlist[i] = g_fixlist[0];
    g_nfixpad = (nf > 0) ? np : 0;
}

// ---------------- Kernel 2b: gathered 3-product GEMM over flagged tokens ----
// y < 256:  q-path:  rows = fixlist tokens,  B cols 0..1023  -> g_q rows
// y >= 256: k-path:  rows = fixlist[t]-1,    B cols 1024..2047 -> g_k rows
#define FIX_SMEM (512 + 4 * TILE_B)

__global__ void __launch_bounds__(256, 1) fixup_gemm_kernel()
{
    int mb = blockIdx.y & 255;
    if (mb * 128 >= g_nfixpad) return;
    const int isq = (blockIdx.y < 256);
    const int nblock = (isq ? 0 : 8) + blockIdx.x;     // global n-block 0..15

    extern __shared__ char smem[];
    int* toks = (int*)smem;
    uint32_t sb = smem_u32(smem) + 512;                 // tiles base
    const int tid = threadIdx.x;
    const int lane = tid & 31;
    const int wid = tid >> 5;
    const int warp_m = wid & 3;
    const int warp_n = wid >> 2;

    if (tid < 128) {
        int t = g_fixlist[mb * 128 + tid];
        toks[tid] = isq ? t : max(t - 1, 0);
    }
    __syncthreads();

    float acc[2][8][4];
#pragma unroll
    for (int i = 0; i < 2; i++)
#pragma unroll
        for (int j = 0; j < 8; j++)
#pragma unroll
            for (int q = 0; q < 4; q++) acc[i][j][q] = 0.f;

    const int aRow  = warp_m * 32 + (lane & 15);
    const int aXor  = (aRow & 7) << 4;
    const int aColB = (lane >> 4) * 16;
    const int bRow  = warp_n * 64 + (lane & 7) + ((lane >> 4) & 1) * 8;
    const int bXor  = (bRow & 7) << 4;
    const int bColB = ((lane >> 3) & 1) * 16;

    const char* bhiSrc  = (const char*)g_Bhi  + (size_t)nblock * 16 * TILE_B;
    const char* bmidSrc = (const char*)g_Bmid + (size_t)nblock * 16 * TILE_B;

#pragma unroll 1
    for (int c = 0; c < 16; c++) {
        // fill: gathered A (hi, mid) + contiguous B (hi, mid)
#pragma unroll
        for (int it = 0; it < 4; it++) {
            int w = tid + it * 256;                     // 0..1023
            int r = w >> 3, kg7 = w & 7;
            int tok = toks[r];
            size_t srcOff = ((size_t)(tok >> 7) * 16 + c) * TILE_B
                          + (tok & 127) * 128 + ((kg7 * 16) ^ (((tok & 127) & 7) << 4));
            uint32_t dst = r * 128 + ((kg7 * 16) ^ ((r & 7) << 4));
            *(uint4*)(smem + 512 + dst)              = *(const uint4*)((const char*)g_Ahi  + srcOff);
            *(uint4*)(smem + 512 + TILE_B + dst)     = *(const uint4*)((const char*)g_Amid + srcOff);
            *(uint4*)(smem + 512 + 2 * TILE_B + w * 16) =
                *(const uint4*)(bhiSrc  + (size_t)c * TILE_B + w * 16);
            *(uint4*)(smem + 512 + 3 * TILE_B + w * 16) =
                *(const uint4*)(bmidSrc + (size_t)c * TILE_B + w * 16);
        }
        __syncthreads();

        uint32_t aHi = sb, aMid = sb + TILE_B;
        uint32_t bHi = sb + 2 * TILE_B, bMid = sb + 3 * TILE_B;
#pragma unroll 1
        for (int ks = 0; ks < 4; ks++) {
            uint32_t ah[2][4], am[2][4];
#pragma unroll
            for (int mi = 0; mi < 2; mi++) {
                uint32_t roff = (aRow + mi * 16) * 128 + ((ks * 32 + aColB) ^ aXor);
                ldsm_x4(aHi  + roff, ah[mi][0], ah[mi][1], ah[mi][2], ah[mi][3]);
                ldsm_x4(aMid + roff, am[mi][0], am[mi][1], am[mi][2], am[mi][3]);
            }
#pragma unroll
            for (int ng = 0; ng < 4; ng++) {
                uint32_t roff = (bRow + ng * 16) * 128 + ((ks * 32 + bColB) ^ bXor);
                uint32_t b0, b1, b2, b3;
                ldsm_x4(bHi + roff, b0, b1, b2, b3);
                mma_bf16(acc[0][ng*2],   ah[0], b0, b1);
                mma_bf16(acc[0][ng*2+1], ah[0], b2, b3);
                mma_bf16(acc[1][ng*2],   ah[1], b0, b1);
                mma_bf16(acc[1][ng*2+1], ah[1], b2, b3);
                mma_bf16(acc[0][ng*2],   am[0], b0, b1);
                mma_bf16(acc[0][ng*2+1], am[0], b2, b3);
                mma_bf16(acc[1][ng*2],   am[1], b0, b1);
                mma_bf16(acc[1][ng*2+1], am[1], b2, b3);
                ldsm_x4(bMid + roff, b0, b1, b2, b3);
                mma_bf16(acc[0][ng*2],   ah[0], b0, b1);
                mma_bf16(acc[0][ng*2+1], ah[0], b2, b3);
                mma_bf16(acc[1][ng*2],   ah[1], b0, b1);
                mma_bf16(acc[1][ng*2+1], ah[1], b2, b3);
            }
        }
        __syncthreads();
    }

    float* cbase = isq ? g_q : g_k;
    int coloff = (nblock & 7) * 128;
#pragma unroll
    for (int mi = 0; mi < 2; mi++) {
        int rloc = warp_m * 32 + mi * 16 + (lane >> 2);
        int row0 = toks[rloc];
        int row1 = toks[rloc + 8];
#pragma unroll
        for (int ni = 0; ni < 8; ni++) {
            int col = coloff + warp_n * 64 + ni * 8 + (lane & 3) * 2;
            *(float2*)&cbase[(size_t)row0 * 1024 + col] =
                make_float2(acc[mi][ni][0], acc[mi][ni][1]);
            *(float2*)&cbase[(size_t)row1 * 1024 + col] =
                make_float2(acc[mi][ni][2], acc[mi][ni][3]);
        }
    }
}

// ---------------- Kernel 2c: exact cosine for flagged tokens ----------------
__global__ __launch_bounds__(128) void fixup_cos_kernel(const float* __restrict__ start_key)
{
    int token = blockIdx.x;
    if (!g_flag[token]) return;
    int l = token & (L - 1);
    const float4* qv = (const float4*)(g_q + (size_t)token * DQK);
    const float4* kv = (l == 0) ? (const float4*)start_key
                                : (const float4*)(g_k + (size_t)(token - 1) * DQK);
    float dot = 0.f, qq = 0.f, kk = 0.f;
    for (int i = threadIdx.x; i < DQK / 4; i += 128) {
        float4 a = qv[i], c = kv[i];
        dot += a.x * c.x + a.y * c.y + a.z * c.z + a.w * c.w;
        qq  += a.x * a.x + a.y * a.y + a.z * a.z + a.w * a.w;
        kk  += c.x * c.x + c.y * c.y + c.z * c.z + c.w * c.w;
    }
#pragma unroll
    for (int o = 16; o; o >>= 1) {
        dot += __shfl_down_sync(0xffffffffu, dot, o);
        qq  += __shfl_down_sync(0xffffffffu, qq,  o);
        kk  += __shfl_down_sync(0xffffffffu, kk,  o);
    }
    __shared__ float sd[4], sq[4], sk[4];
    int w = threadIdx.x >> 5;
    if ((threadIdx.x & 31) == 0) { sd[w] = dot; sq[w] = qq; sk[w] = kk; }
    __syncthreads();
    if (threadIdx.x == 0) {
        dot = sd[0] + sd[1] + sd[2] + sd[3];
        qq  = sq[0] + sq[1] + sq[2] + sq[3];
        kk  = sk[0] + sk[1] + sk[2] + sk[3];
        float denom = fmaxf(sqrtf(qq) * sqrtf(kk), 1e-8f);
        g_probs[token] = (1.0f - dot / denom) * 0.5f;
    }
}

// ---------------- Kernel 3: per-batch boundary scan + aux -------------------
__global__ __launch_bounds__(1024) void boundary_kernel()
{
    int b = blockIdx.x;
    int tid = threadIdx.x;
    __shared__ int   s[1024];
    __shared__ float sf[1024];

    int l0 = tid * 4;
    float p[4]; int bd[4]; int cnt = 0; float psum = 0.f;
#pragma unroll
    for (int i = 0; i < 4; i++) {
        int l = l0 + i;
        p[i] = g_probs[b * L + l];
        bd[i] = (l == 0) || (p[i] > 0.5f);
        cnt += bd[i];
        psum += p[i];
    }
    s[tid] = cnt;
    sf[tid] = psum;
    __syncthreads();
    for (int off = 1; off < 1024; off <<= 1) {
        int v = (tid >= off) ? s[tid - off] : 0;
        __syncthreads();
        if (tid >= off) s[tid] += v;
        __syncthreads();
    }
    int incl = s[tid];
    int base = incl - cnt;
    int total = s[1023];
    int run = base;
#pragma unroll
    for (int i = 0; i < 4; i++) {
        int l = l0 + i;
        if (bd[i]) { g_blidx[b * L + run] = l; run++; }
        g_chunkid[b * L + l] = run - 1;
    }
    __syncthreads();
    for (int off = 512; off > 0; off >>= 1) {
        if (tid < off) sf[tid] += sf[tid + off];
        __syncthreads();
    }
    if (tid == 0) {
        float F = (float)total / (float)L;
        float G = sf[0] / (float)L;
        g_auxb[b] = 1.2f * (5.0f * F * G + (1.0f - F) * (1.0f - G));
        g_nch[b] = total;
    }
}

// ---------------- Kernel 4a: zero padded chunk slots of downsampled ---------
__global__ __launch_bounds__(256) void zero_down_kernel(float* __restrict__ out)
{
    int row = blockIdx.x;          // b*L + j
    int b = row >> 12;
    int j = row & (L - 1);
    if (j < g_nch[b]) return;
    float4* o = (float4*)(out + (size_t)row * D);
    o[threadIdx.x] = make_float4(0.f, 0.f, 0.f, 0.f);
}

// ---------------- Kernel 4b: windowed-parallel chunk EMA scan ---------------
__global__ __launch_bounds__(128) void chunk_scan_kernel(
    const float* __restrict__ tokens, float* __restrict__ out)
{
    int b = blockIdx.z;
    int nch = g_nch[b];
    int j0 = blockIdx.y * 128;
    if (j0 >= nch) return;
    int d = blockIdx.x * 128 + threadIdx.x;
    int jstart = (j0 >= 64) ? (j0 - 64) : 0;
    int jend = min(j0 + 128, nch);
    int cnt = jend - jstart;

    __shared__ int   sl[192];
    __shared__ float sp[192];
    for (int i = threadIdx.x; i < cnt; i += 128) {
        int l = g_blidx[b * L + jstart + i];
        sl[i] = l;
        sp[i] = g_probs[b * L + l];
    }
    __syncthreads();

    float h = 0.f;
    int i = 0;
    int warm = j0 - jstart;
    for (; i < warm; i++) {
        float p = sp[i];
        float t = tokens[((size_t)b * L + sl[i]) * D + d];
        h = fmaf(1.f - p, h, p * t);
    }
    for (; i < cnt; i++) {
        int j = jstart + i;
        float p = sp[i];
        float t = tokens[((size_t)b * L + sl[i]) * D + d];
        float x = p * t;
        out[((size_t)b * L + j) * D + d] = x;          // downsampled
        h = fmaf(1.f - p, h, x);
        g_scan[((size_t)b * L + j) * D + d] = h;
    }
}

// ---------------- Kernel 5: ups = gather(scan) + res + b_res ----------------
__global__ __launch_bounds__(256) void ups_kernel(
    float* __restrict__ out, const float* __restrict__ b_res)
{
    int row = blockIdx.x;          // b*L + l
    int b = row >> 12;
    int cid = g_chunkid[row];
    const float4* sc = (const float4*)(g_scan + (size_t)(b * L + cid) * D);
    const float4* rs = (const float4*)(g_res + (size_t)row * D);
    const float4* br = (const float4*)b_res;
    float4* o = (float4*)(out + BLD + (size_t)row * D);
    int t = threadIdx.x;
    float4 a = sc[t], c = rs[t], e = br[t];
    o[t] = make_float4(a.x + c.x + e.x, a.y + c.y + e.y,
                       a.z + c.z + e.z, a.w + c.w + e.w);
}

// ---------------- Kernel 6: finalize aux scalar -----------------------------
__global__ void aux_final_kernel(float* __restrict__ out)
{
    float s = 0.f;
    for (int i = 0; i < B; i++) s += g_auxb[i];
    out[2 * BLD] = (s / (float)B) * 0.03f;
}

// ---------------- launch ----------------------------------------------------
extern "C" void kernel_launch(void* const* d_in, const int* in_sizes, int n_in,
                              void* d_out, int out_size)
{
    const float* tokens = (const float*)d_in[0];
    const float* Wqk    = (const float*)d_in[1];
    const float* skey   = (const float*)d_in[2];
    const float* Wres   = (const float*)d_in[3];
    const float* bres   = (const float*)d_in[4];
    float* out = (float*)d_out;

    cudaFuncSetAttribute(gemm_kernel,
                         cudaFuncAttributeMaxDynamicSharedMemorySize, GEMM_SMEM);
    cudaFuncSetAttribute(fixup_gemm_kernel,
                         cudaFuncAttributeMaxDynamicSharedMemorySize, FIX_SMEM);

    split_a_kernel<<<M * 128 / 256, 256>>>(tokens);
    split_b_kernel<<<NTOT * 128 / 256, 256>>>(Wqk, Wres);
    zero_nfix_kernel<<<1, 1>>>();
    gemm_kernel<<<dim3(24, 256), 256, GEMM_SMEM>>>();
    probs_kernel<<<M, 128>>>(skey);
    pad_fix_kernel<<<1, 1>>>();
    fixup_gemm_kernel<<<dim3(8, 512), 256, FIX_SMEM>>>();
    fixup_cos_kernel<<<M, 128>>>(skey);
    boundary_kernel<<<B, 1024>>>();
    zero_down_kernel<<<M, 256>>>(out);
    chunk_scan_kernel<<<dim3(D / 128, L / 128, B), 128>>>(tokens, out);
    ups_kernel<<<M, 256>>>(out, bres);
    aux_final_kernel<<<1, 1>>>(out);
}

// round 13
// speedup vs baseline: 1.9190x; 1.1551x over previous
#include <cuda_runtime.h>
#include <cuda_bf16.h>
#include <cstdint>

#define B   8
#define L   4096
#define D   1024
#define DQK 1024
#define M   (B * L)           // 32768 tokens
#define BLD ((size_t)M * D)   // 33554432
#define NTOT 3072
#define TILE_B 16384          // one 128x64 bf16 tile (128B rows, swizzled)

// ---------------- scratch (device globals; no allocation allowed) ----------
__device__ float g_q[(size_t)M * DQK];     // 128 MiB
__device__ float g_k[(size_t)M * DQK];     // 128 MiB
__device__ float g_res[(size_t)M * D];     // 128 MiB
__device__ float g_scan[(size_t)M * D];    // 128 MiB
__device__ float g_probs[M];
__device__ int   g_flag[M];
__device__ int   g_fixlist[M];
__device__ int   g_nfix;
__device__ int   g_nfixpad;
__device__ int   g_chunkid[M];
__device__ int   g_blidx[M];
__device__ int   g_nch[B];
__device__ float g_auxb[B];

// PRE-SWIZZLED tiled layouts: [block][chunk 0..15][16KB tile]
__device__ __nv_bfloat16 g_Ahi [(size_t)M * 1024];
__device__ __nv_bfloat16 g_Amid[(size_t)M * 1024];
__device__ __nv_bfloat16 g_Bhi [(size_t)NTOT * 1024];
__device__ __nv_bfloat16 g_Bmid[(size_t)NTOT * 1024];

// ======================= helpers ===========================================
__device__ __forceinline__ uint32_t smem_u32(const void* p) {
    uint32_t a;
    asm("{ .reg .u64 t; cvta.to.shared.u64 t, %1; cvt.u32.u64 %0, t; }"
        : "=r"(a) : "l"(p));
    return a;
}
__device__ __forceinline__ void mbar_init(uint32_t a, uint32_t cnt) {
    asm volatile("mbarrier.init.shared.b64 [%0], %1;" :: "r"(a), "r"(cnt) : "memory");
}
__device__ __forceinline__ void mbar_expect_tx(uint32_t a, uint32_t bytes) {
    asm volatile("mbarrier.arrive.expect_tx.shared.b64 _, [%0], %1;"
                 :: "r"(a), "r"(bytes) : "memory");
}
__device__ __forceinline__ void mbar_wait(uint32_t a, uint32_t parity) {
    uint32_t done;
    asm volatile(
        "{\n\t.reg .pred p;\n\t"
        "mbarrier.try_wait.parity.acquire.cta.shared::cta.b64 p, [%1], %2;\n\t"
        "selp.b32 %0, 1, 0, p;\n\t}"
        : "=r"(done) : "r"(a), "r"(parity) : "memory");
    if (!done) {
        asm volatile(
            "{\n\t.reg .pred P1;\n\t"
            "WL_%=:\n\t"
            "mbarrier.try_wait.parity.acquire.cta.shared::cta.b64 P1, [%0], %1, 0x989680;\n\t"
            "@P1 bra.uni WD_%=;\n\t"
            "bra.uni WL_%=;\n\t"
            "WD_%=:\n\t}"
            :: "r"(a), "r"(parity) : "memory");
    }
}
__device__ __forceinline__ void bulk_cp(uint32_t dst, const void* src,
                                        uint32_t bytes, uint32_t mbar) {
    asm volatile(
        "cp.async.bulk.shared::cta.global.mbarrier::complete_tx::bytes "
        "[%0], [%1], %2, [%3];"
        :: "r"(dst), "l"(src), "r"(bytes), "r"(mbar) : "memory");
}
__device__ __forceinline__ void ldsm_x4(uint32_t addr, uint32_t& r0, uint32_t& r1,
                                        uint32_t& r2, uint32_t& r3) {
    asm volatile("ldmatrix.sync.aligned.m8n8.x4.shared.b16 {%0,%1,%2,%3}, [%4];"
                 : "=r"(r0), "=r"(r1), "=r"(r2), "=r"(r3) : "r"(addr));
}
__device__ __forceinline__ void mma_bf16(float* c,
                                         const uint32_t* a,
                                         uint32_t b0, uint32_t b1) {
    asm volatile(
        "mma.sync.aligned.m16n8k16.row.col.f32.bf16.bf16.f32 "
        "{%0,%1,%2,%3}, {%4,%5,%6,%7}, {%8,%9}, {%0,%1,%2,%3};"
        : "+f"(c[0]), "+f"(c[1]), "+f"(c[2]), "+f"(c[3])
        : "r"(a[0]), "r"(a[1]), "r"(a[2]), "r"(a[3]), "r"(b0), "r"(b1));
}

__device__ __forceinline__ size_t tile_addr(int block, int row, int kg) {
    int chunk = kg >> 3;
    int colB  = (kg & 7) * 16;
    int sw    = colB ^ ((row & 7) << 4);
    return ((size_t)block * 16 + chunk) * TILE_B + row * 128 + sw;
}

// ---------------- Prep 1: split tokens -> swizzled-tiled bf16 hi/mid --------
__global__ __launch_bounds__(256) void split_a_kernel(const float* __restrict__ A)
{
    int idx = blockIdx.x * 256 + threadIdx.x;      // 0 .. M*128-1
    int m  = idx >> 7;
    int kg = idx & 127;
    const float4* src = (const float4*)(A + (size_t)m * 1024 + kg * 8);
    float4 v0 = src[0], v1 = src[1];
    float x[8] = {v0.x, v0.y, v0.z, v0.w, v1.x, v1.y, v1.z, v1.w};
    unsigned short h[8], mm[8];
#pragma unroll
    for (int j = 0; j < 8; j++) {
        __nv_bfloat16 bh = __float2bfloat16_rn(x[j]);
        float r1 = x[j] - __bfloat162float(bh);
        __nv_bfloat16 bm = __float2bfloat16_rn(r1);
        h[j]  = __bfloat16_as_ushort(bh);
        mm[j] = __bfloat16_as_ushort(bm);
    }
    size_t a = tile_addr(m >> 7, m & 127, kg);
#define PACK4(arr) make_uint4((unsigned)arr[0] | ((unsigned)arr[1] << 16), \
                              (unsigned)arr[2] | ((unsigned)arr[3] << 16), \
                              (unsigned)arr[4] | ((unsigned)arr[5] << 16), \
                              (unsigned)arr[6] | ((unsigned)arr[7] << 16))
    *(uint4*)((char*)g_Ahi  + a) = PACK4(h);
    *(uint4*)((char*)g_Amid + a) = PACK4(mm);
}

// ---------------- Prep 2: split + transpose weights -> swizzled tiles -------
__global__ __launch_bounds__(256) void split_b_kernel(
    const float* __restrict__ Wqk, const float* __restrict__ Wres)
{
    int id = blockIdx.x * 256 + threadIdx.x;   // 0..393215
    int n  = id % NTOT;
    int kg = id / NTOT;
    unsigned short h[8], mm[8];
#pragma unroll
    for (int j = 0; j < 8; j++) {
        int k = kg * 8 + j;
        float x = (n < 2048) ? Wqk[(size_t)k * 2048 + n]
                             : Wres[(size_t)k * 1024 + (n - 2048)];
        __nv_bfloat16 bh = __float2bfloat16_rn(x);
        float r1 = x - __bfloat162float(bh);
        __nv_bfloat16 bm = __float2bfloat16_rn(r1);
        h[j]  = __bfloat16_as_ushort(bh);
        mm[j] = __bfloat16_as_ushort(bm);
    }
    size_t a = tile_addr(n >> 7, n & 127, kg);
    *(uint4*)((char*)g_Bhi  + a) = PACK4(h);
    *(uint4*)((char*)g_Bmid + a) = PACK4(mm);
#undef PACK4
}

// ---------------- Kernel 1a: QK GEMM (single product, occ 2) ----------------
// C[M, 2048] = tokens_hi @ Wqk_hi. Stage = {Ahi, Bhi} = 32 KB, 3 stages.
#define QK_STAGE (2 * TILE_B)               // 32 KB
#define QK_SMEM  (128 + 3 * QK_STAGE)       // ~96 KB -> 2 CTAs/SM

__global__ void __launch_bounds__(256, 2) qk_gemm_kernel()
{
    extern __shared__ char smem[];
    uint32_t sb = smem_u32(smem);
    const int tid = threadIdx.x;
    const int lane = tid & 31;
    const int wid = tid >> 5;
    const int warp_m = wid & 3;
    const int warp_n = wid >> 2;
    const int m0 = blockIdx.y * 128;
    const int n0 = blockIdx.x * 128;

    const char* asrc = (const char*)g_Ahi + (size_t)(m0 >> 7) * 16 * TILE_B;
    const char* bsrc = (const char*)g_Bhi + (size_t)(n0 >> 7) * 16 * TILE_B;

    if (tid == 0) {
        mbar_init(sb + 0, 1);
        mbar_init(sb + 8, 1);
        mbar_init(sb + 16, 1);
    }
    __syncthreads();

    float acc[2][8][4];
#pragma unroll
    for (int i = 0; i < 2; i++)
#pragma unroll
        for (int j = 0; j < 8; j++)
#pragma unroll
            for (int q = 0; q < 4; q++) acc[i][j][q] = 0.f;

    const int aRow  = warp_m * 32 + (lane & 15);
    const int aXor  = (aRow & 7) << 4;
    const int aColB = (lane >> 4) * 16;
    const int bRow  = warp_n * 64 + (lane & 7) + ((lane >> 4) & 1) * 8;
    const int bXor  = (bRow & 7) << 4;
    const int bColB = ((lane >> 3) & 1) * 16;

    if (tid == 0) {
#pragma unroll
        for (int c = 0; c < 2; c++) {
            uint32_t mb = sb + c * 8;
            uint32_t st = sb + 128 + c * QK_STAGE;
            mbar_expect_tx(mb, QK_STAGE);
            bulk_cp(st,          asrc + (size_t)c * TILE_B, TILE_B, mb);
            bulk_cp(st + TILE_B, bsrc + (size_t)c * TILE_B, TILE_B, mb);
        }
    }

#pragma unroll 1
    for (int c = 0; c < 16; c++) {
        int s = c % 3;
        uint32_t stage = sb + 128 + s * QK_STAGE;
        if (c < 14 && tid == 0) {
            int s2 = (c + 2) % 3;
            uint32_t mb = sb + s2 * 8;
            uint32_t st = sb + 128 + s2 * QK_STAGE;
            mbar_expect_tx(mb, QK_STAGE);
            bulk_cp(st,          asrc + (size_t)(c + 2) * TILE_B, TILE_B, mb);
            bulk_cp(st + TILE_B, bsrc + (size_t)(c + 2) * TILE_B, TILE_B, mb);
        }
        mbar_wait(sb + s * 8, (c / 3) & 1);
        __syncthreads();

        uint32_t aHi = stage, bHi = stage + TILE_B;
#pragma unroll 1
        for (int ks = 0; ks < 4; ks++) {
            uint32_t ah[2][4];
#pragma unroll
            for (int mi = 0; mi < 2; mi++) {
                uint32_t roff = (aRow + mi * 16) * 128 + ((ks * 32 + aColB) ^ aXor);
                ldsm_x4(aHi + roff, ah[mi][0], ah[mi][1], ah[mi][2], ah[mi][3]);
            }
#pragma unroll
            for (int ng = 0; ng < 4; ng++) {
                uint32_t roff = (bRow + ng * 16) * 128 + ((ks * 32 + bColB) ^ bXor);
                uint32_t b0, b1, b2, b3;
                ldsm_x4(bHi + roff, b0, b1, b2, b3);
                mma_bf16(acc[0][ng*2],   ah[0], b0, b1);
                mma_bf16(acc[0][ng*2+1], ah[0], b2, b3);
                mma_bf16(acc[1][ng*2],   ah[1], b0, b1);
                mma_bf16(acc[1][ng*2+1], ah[1], b2, b3);
            }
        }
        __syncthreads();
    }

    float* cbase = (n0 < 1024) ? g_q : g_k;
    int coloff = n0 & 1023;
#pragma unroll
    for (int mi = 0; mi < 2; mi++) {
        int r0 = m0 + warp_m * 32 + mi * 16 + (lane >> 2);
#pragma unroll
        for (int ni = 0; ni < 8; ni++) {
            int col = coloff + warp_n * 64 + ni * 8 + (lane & 3) * 2;
            *(float2*)&cbase[(size_t)r0 * 1024 + col] =
                make_float2(acc[mi][ni][0], acc[mi][ni][1]);
            *(float2*)&cbase[(size_t)(r0 + 8) * 1024 + col] =
                make_float2(acc[mi][ni][2], acc[mi][ni][3]);
        }
    }
}

// ---------------- Kernel 1b: residual GEMM (3 products, N-tile 64, occ 2) ---
// Stage = {Ahi 16K, Amid 16K, Bhi 8K, Bmid 8K} = 48 KB, 2 stages.
#define RES_STAGE (2 * TILE_B + 2 * 8192)   // 48 KB
#define RES_SMEM  (128 + 2 * RES_STAGE)     // ~96 KB -> 2 CTAs/SM

__global__ void __launch_bounds__(256, 2) res_gemm_kernel()
{
    extern __shared__ char smem[];
    uint32_t sb = smem_u32(smem);
    const int tid = threadIdx.x;
    const int lane = tid & 31;
    const int wid = tid >> 5;
    const int warp_m = wid & 3;
    const int warp_n = wid >> 2;            // 0..1, covers 32 n-cols
    const int m0 = blockIdx.y * 128;
    const int nb = blockIdx.x;              // 0..15, 64 cols each

    const char* ahiSrc  = (const char*)g_Ahi  + (size_t)(m0 >> 7) * 16 * TILE_B;
    const char* amidSrc = (const char*)g_Amid + (size_t)(m0 >> 7) * 16 * TILE_B;
    const int bblock = 16 + (nb >> 1);
    const size_t boff = (size_t)(nb & 1) * 8192;
    const char* bhiSrc  = (const char*)g_Bhi  + (size_t)bblock * 16 * TILE_B + boff;
    const char* bmidSrc = (const char*)g_Bmid + (size_t)bblock * 16 * TILE_B + boff;

    if (tid == 0) {
        mbar_init(sb + 0, 1);
        mbar_init(sb + 8, 1);
    }
    __syncthreads();

    float acc[2][4][4];
#pragma unroll
    for (int i = 0; i < 2; i++)
#pragma unroll
        for (int j = 0; j < 4; j++)
#pragma unroll
            for (int q = 0; q < 4; q++) acc[i][j][q] = 0.f;

    const int aRow  = warp_m * 32 + (lane & 15);
    const int aXor  = (aRow & 7) << 4;
    const int aColB = (lane >> 4) * 16;
    const int bRow  = warp_n * 32 + (lane & 7) + ((lane >> 4) & 1) * 8;
    const int bXor  = (bRow & 7) << 4;
    const int bColB = ((lane >> 3) & 1) * 16;

    if (tid == 0) {
#pragma unroll
        for (int c = 0; c < 2; c++) {
            uint32_t mb = sb + c * 8;
            uint32_t st = sb + 128 + c * RES_STAGE;
            mbar_expect_tx(mb, RES_STAGE);
            bulk_cp(st,                   ahiSrc  + (size_t)c * TILE_B, TILE_B, mb);
            bulk_cp(st + TILE_B,          amidSrc + (size_t)c * TILE_B, TILE_B, mb);
            bulk_cp(st + 2 * TILE_B,        bhiSrc  + (size_t)c * TILE_B, 8192, mb);
            bulk_cp(st + 2 * TILE_B + 8192, bmidSrc + (size_t)c * TILE_B, 8192, mb);
        }
    }

#pragma unroll 1
    for (int c = 0; c < 16; c++) {
        int s = c & 1;
        uint32_t stage = sb + 128 + s * RES_STAGE;
        mbar_wait(sb + s * 8, (c >> 1) & 1);
        __syncthreads();

        uint32_t aHi = stage, aMid = stage + TILE_B;
        uint32_t bHi = stage + 2 * TILE_B, bMid = stage + 2 * TILE_B + 8192;
#pragma unroll 1
        for (int ks = 0; ks < 4; ks++) {
            uint32_t ah[2][4], am[2][4];
#pragma unroll
            for (int mi = 0; mi < 2; mi++) {
                uint32_t roff = (aRow + mi * 16) * 128 + ((ks * 32 + aColB) ^ aXor);
                ldsm_x4(aHi  + roff, ah[mi][0], ah[mi][1], ah[mi][2], ah[mi][3]);
                ldsm_x4(aMid + roff, am[mi][0], am[mi][1], am[mi][2], am[mi][3]);
            }
#pragma unroll
            for (int ng = 0; ng < 2; ng++) {
                uint32_t roff = (bRow + ng * 16) * 128 + ((ks * 32 + bColB) ^ bXor);
                uint32_t b0, b1, b2, b3;
                ldsm_x4(bHi + roff, b0, b1, b2, b3);
                mma_bf16(acc[0][ng*2],   ah[0], b0, b1);
                mma_bf16(acc[0][ng*2+1], ah[0], b2, b3);
                mma_bf16(acc[1][ng*2],   ah[1], b0, b1);
                mma_bf16(acc[1][ng*2+1], ah[1], b2, b3);
                mma_bf16(acc[0][ng*2],   am[0], b0, b1);
                mma_bf16(acc[0][ng*2+1], am[0], b2, b3);
                mma_bf16(acc[1][ng*2],   am[1], b0, b1);
                mma_bf16(acc[1][ng*2+1], am[1], b2, b3);
                ldsm_x4(bMid + roff, b0, b1, b2, b3);
                mma_bf16(acc[0][ng*2],   ah[0], b0, b1);
                mma_bf16(acc[0][ng*2+1], ah[0], b2, b3);
                mma_bf16(acc[1][ng*2],   ah[1], b0, b1);
                mma_bf16(acc[1][ng*2+1], ah[1], b2, b3);
            }
        }
        __syncthreads();
        if (c < 14 && tid == 0) {
            uint32_t mb = sb + s * 8;
            uint32_t st = stage;
            mbar_expect_tx(mb, RES_STAGE);
            bulk_cp(st,                   ahiSrc  + (size_t)(c + 2) * TILE_B, TILE_B, mb);
            bulk_cp(st + TILE_B,          amidSrc + (size_t)(c + 2) * TILE_B, TILE_B, mb);
            bulk_cp(st + 2 * TILE_B,        bhiSrc  + (size_t)(c + 2) * TILE_B, 8192, mb);
            bulk_cp(st + 2 * TILE_B + 8192, bmidSrc + (size_t)(c + 2) * TILE_B, 8192, mb);
        }
    }

    int coloff = nb * 64;
#pragma unroll
    for (int mi = 0; mi < 2; mi++) {
        int r0 = m0 + warp_m * 32 + mi * 16 + (lane >> 2);
#pragma unroll
        for (int ni = 0; ni < 4; ni++) {
            int col = coloff + warp_n * 32 + ni * 8 + (lane & 3) * 2;
            *(float2*)&g_res[(size_t)r0 * 1024 + col] =
                make_float2(acc[mi][ni][0], acc[mi][ni][1]);
            *(float2*)&g_res[(size_t)(r0 + 8) * 1024 + col] =
                make_float2(acc[mi][ni][2], acc[mi][ni][3]);
        }
    }
}

// ---------------- zero fix counter ------------------------------------------
__global__ void zero_nfix_kernel() { g_nfix = 0; }

// ---------------- Kernel 2: cosine -> probs + flag + compact list -----------
__global__ __launch_bounds__(128) void probs_kernel(const float* __restrict__ start_key)
{
    int token = blockIdx.x;
    int l = token & (L - 1);
    const float4* qv = (const float4*)(g_q + (size_t)token * DQK);
    const float4* kv = (l == 0) ? (const float4*)start_key
                                : (const float4*)(g_k + (size_t)(token - 1) * DQK);
    float dot = 0.f, qq = 0.f, kk = 0.f;
    for (int i = threadIdx.x; i < DQK / 4; i += 128) {
        float4 a = qv[i], c = kv[i];
        dot += a.x * c.x + a.y * c.y + a.z * c.z + a.w * c.w;
        qq  += a.x * a.x + a.y * a.y + a.z * a.z + a.w * a.w;
        kk  += c.x * c.x + c.y * c.y + c.z * c.z + c.w * c.w;
    }
#pragma unroll
    for (int o = 16; o; o >>= 1) {
        dot += __shfl_down_sync(0xffffffffu, dot, o);
        qq  += __shfl_down_sync(0xffffffffu, qq,  o);
        kk  += __shfl_down_sync(0xffffffffu, kk,  o);
    }
    __shared__ float sd[4], sq[4], sk[4];
    int w = threadIdx.x >> 5;
    if ((threadIdx.x & 31) == 0) { sd[w] = dot; sq[w] = qq; sk[w] = kk; }
    __syncthreads();
    if (threadIdx.x == 0) {
        dot = sd[0] + sd[1] + sd[2] + sd[3];
        qq  = sq[0] + sq[1] + sq[2] + sq[3];
        kk  = sk[0] + sk[1] + sk[2] + sk[3];
        float denom = fmaxf(sqrtf(qq) * sqrtf(kk), 1e-8f);
        float cosv = dot / denom;
        g_probs[token] = (1.0f - cosv) * 0.5f;
        int fl = (fabsf(cosv) < 2e-3f) ? 1 : 0;
        g_flag[token] = fl;
        if (fl) {
            int slot = atomicAdd(&g_nfix, 1);
            g_fixlist[slot] = token;
        }
    }
}

// ---------------- pad fix list to multiple of 128 ---------------------------
__global__ void pad_fix_kernel()
{
    int nf = g_nfix;
    int np = (nf + 127) & ~127;
    if (nf > 0)
        for (int i = nf; i < np; i++) g_fixlist[i] = g_fixlist[0];
    g_nfixpad = (nf > 0) ? np : 0;
}

// ---------------- Kernel 2b: gathered 3-product GEMM over flagged tokens ----
#define FIX_SMEM (512 + 4 * TILE_B)

__global__ void __launch_bounds__(256, 1) fixup_gemm_kernel()
{
    int mb = blockIdx.y & 255;
    if (mb * 128 >= g_nfixpad) return;
    const int isq = (blockIdx.y < 256);
    const int nblock = (isq ? 0 : 8) + blockIdx.x;     // global n-block 0..15

    extern __shared__ char smem[];
    int* toks = (int*)smem;
    uint32_t sb = smem_u32(smem) + 512;
    const int tid = threadIdx.x;
    const int lane = tid & 31;
    const int wid = tid >> 5;
    const int warp_m = wid & 3;
    const int warp_n = wid >> 2;

    if (tid < 128) {
        int t = g_fixlist[mb * 128 + tid];
        toks[tid] = isq ? t : max(t - 1, 0);
    }
    __syncthreads();

    float acc[2][8][4];
#pragma unroll
    for (int i = 0; i < 2; i++)
#pragma unroll
        for (int j = 0; j < 8; j++)
#pragma unroll
            for (int q = 0; q < 4; q++) acc[i][j][q] = 0.f;

    const int aRow  = warp_m * 32 + (lane & 15);
    const int aXor  = (aRow & 7) << 4;
    const int aColB = (lane >> 4) * 16;
    const int bRow  = warp_n * 64 + (lane & 7) + ((lane >> 4) & 1) * 8;
    const int bXor  = (bRow & 7) << 4;
    const int bColB = ((lane >> 3) & 1) * 16;

    const char* bhiSrc  = (const char*)g_Bhi  + (size_t)nblock * 16 * TILE_B;
    const char* bmidSrc = (const char*)g_Bmid + (size_t)nblock * 16 * TILE_B;

#pragma unroll 1
    for (int c = 0; c < 16; c++) {
#pragma unroll
        for (int it = 0; it < 4; it++) {
            int w = tid + it * 256;
            int r = w >> 3, kg7 = w & 7;
            int tok = toks[r];
            size_t srcOff = ((size_t)(tok >> 7) * 16 + c) * TILE_B
                          + (tok & 127) * 128 + ((kg7 * 16) ^ (((tok & 127) & 7) << 4));
            uint32_t dst = r * 128 + ((kg7 * 16) ^ ((r & 7) << 4));
            *(uint4*)(smem + 512 + dst)              = *(const uint4*)((const char*)g_Ahi  + srcOff);
            *(uint4*)(smem + 512 + TILE_B + dst)     = *(const uint4*)((const char*)g_Amid + srcOff);
            *(uint4*)(smem + 512 + 2 * TILE_B + w * 16) =
                *(const uint4*)(bhiSrc  + (size_t)c * TILE_B + w * 16);
            *(uint4*)(smem + 512 + 3 * TILE_B + w * 16) =
                *(const uint4*)(bmidSrc + (size_t)c * TILE_B + w * 16);
        }
        __syncthreads();

        uint32_t aHi = sb, aMid = sb + TILE_B;
        uint32_t bHi = sb + 2 * TILE_B, bMid = sb + 3 * TILE_B;
#pragma unroll 1
        for (int ks = 0; ks < 4; ks++) {
            uint32_t ah[2][4], am[2][4];
#pragma unroll
            for (int mi = 0; mi < 2; mi++) {
                uint32_t roff = (aRow + mi * 16) * 128 + ((ks * 32 + aColB) ^ aXor);
                ldsm_x4(aHi  + roff, ah[mi][0], ah[mi][1], ah[mi][2], ah[mi][3]);
                ldsm_x4(aMid + roff, am[mi][0], am[mi][1], am[mi][2], am[mi][3]);
            }
#pragma unroll
            for (int ng = 0; ng < 4; ng++) {
                uint32_t roff = (bRow + ng * 16) * 128 + ((ks * 32 + bColB) ^ bXor);
                uint32_t b0, b1, b2, b3;
                ldsm_x4(bHi + roff, b0, b1, b2, b3);
                mma_bf16(acc[0][ng*2],   ah[0], b0, b1);
                mma_bf16(acc[0][ng*2+1], ah[0], b2, b3);
                mma_bf16(acc[1][ng*2],   ah[1], b0, b1);
                mma_bf16(acc[1][ng*2+1], ah[1], b2, b3);
                mma_bf16(acc[0][ng*2],   am[0], b0, b1);
                mma_bf16(acc[0][ng*2+1], am[0], b2, b3);
                mma_bf16(acc[1][ng*2],   am[1], b0, b1);
                mma_bf16(acc[1][ng*2+1], am[1], b2, b3);
                ldsm_x4(bMid + roff, b0, b1, b2, b3);
                mma_bf16(acc[0][ng*2],   ah[0], b0, b1);
                mma_bf16(acc[0][ng*2+1], ah[0], b2, b3);
                mma_bf16(acc[1][ng*2],   ah[1], b0, b1);
                mma_bf16(acc[1][ng*2+1], ah[1], b2, b3);
            }
        }
        __syncthreads();
    }

    float* cbase = isq ? g_q : g_k;
    int coloff = (nblock & 7) * 128;
#pragma unroll
    for (int mi = 0; mi < 2; mi++) {
        int rloc = warp_m * 32 + mi * 16 + (lane >> 2);
        int row0 = toks[rloc];
        int row1 = toks[rloc + 8];
#pragma unroll
        for (int ni = 0; ni < 8; ni++) {
            int col = coloff + warp_n * 64 + ni * 8 + (lane & 3) * 2;
            *(float2*)&cbase[(size_t)row0 * 1024 + col] =
                make_float2(acc[mi][ni][0], acc[mi][ni][1]);
            *(float2*)&cbase[(size_t)row1 * 1024 + col] =
                make_float2(acc[mi][ni][2], acc[mi][ni][3]);
        }
    }
}

// ---------------- Kernel 2c: exact cosine for flagged tokens ----------------
__global__ __launch_bounds__(128) void fixup_cos_kernel(const float* __restrict__ start_key)
{
    int token = blockIdx.x;
    if (!g_flag[token]) return;
    int l = token & (L - 1);
    const float4* qv = (const float4*)(g_q + (size_t)token * DQK);
    const float4* kv = (l == 0) ? (const float4*)start_key
                                : (const float4*)(g_k + (size_t)(token - 1) * DQK);
    float dot = 0.f, qq = 0.f, kk = 0.f;
    for (int i = threadIdx.x; i < DQK / 4; i += 128) {
        float4 a = qv[i], c = kv[i];
        dot += a.x * c.x + a.y * c.y + a.z * c.z + a.w * c.w;
        qq  += a.x * a.x + a.y * a.y + a.z * a.z + a.w * a.w;
        kk  += c.x * c.x + c.y * c.y + c.z * c.z + c.w * c.w;
    }
#pragma unroll
    for (int o = 16; o; o >>= 1) {
        dot += __shfl_down_sync(0xffffffffu, dot, o);
        qq  += __shfl_down_sync(0xffffffffu, qq,  o);
        kk  += __shfl_down_sync(0xffffffffu, kk,  o);
    }
    __shared__ float sd[4], sq[4], sk[4];
    int w = threadIdx.x >> 5;
    if ((threadIdx.x & 31) == 0) { sd[w] = dot; sq[w] = qq; sk[w] = kk; }
    __syncthreads();
    if (threadIdx.x == 0) {
        dot = sd[0] + sd[1] + sd[2] + sd[3];
        qq  = sq[0] + sq[1] + sq[2] + sq[3];
        kk  = sk[0] + sk[1] + sk[2] + sk[3];
        float denom = fmaxf(sqrtf(qq) * sqrtf(kk), 1e-8f);
        g_probs[token] = (1.0f - dot / denom) * 0.5f;
    }
}

// ---------------- Kernel 3: per-batch boundary scan + aux -------------------
__global__ __launch_bounds__(1024) void boundary_kernel()
{
    int b = blockIdx.x;
    int tid = threadIdx.x;
    __shared__ int   s[1024];
    __shared__ float sf[1024];

    int l0 = tid * 4;
    float p[4]; int bd[4]; int cnt = 0; float psum = 0.f;
#pragma unroll
    for (int i = 0; i < 4; i++) {
        int l = l0 + i;
        p[i] = g_probs[b * L + l];
        bd[i] = (l == 0) || (p[i] > 0.5f);
        cnt += bd[i];
        psum += p[i];
    }
    s[tid] = cnt;
    sf[tid] = psum;
    __syncthreads();
    for (int off = 1; off < 1024; off <<= 1) {
        int v = (tid >= off) ? s[tid - off] : 0;
        __syncthreads();
        if (tid >= off) s[tid] += v;
        __syncthreads();
    }
    int incl = s[tid];
    int base = incl - cnt;
    int total = s[1023];
    int run = base;
#pragma unroll
    for (int i = 0; i < 4; i++) {
        int l = l0 + i;
        if (bd[i]) { g_blidx[b * L + run] = l; run++; }
        g_chunkid[b * L + l] = run - 1;
    }
    __syncthreads();
    for (int off = 512; off > 0; off >>= 1) {
        if (tid < off) sf[tid] += sf[tid + off];
        __syncthreads();
    }
    if (tid == 0) {
        float F = (float)total / (float)L;
        float G = sf[0] / (float)L;
        g_auxb[b] = 1.2f * (5.0f * F * G + (1.0f - F) * (1.0f - G));
        g_nch[b] = total;
    }
}

// ---------------- Kernel 4a: zero padded chunk slots of downsampled ---------
__global__ __launch_bounds__(256) void zero_down_kernel(float* __restrict__ out)
{
    int row = blockIdx.x;          // b*L + j
    int b = row >> 12;
    int j = row & (L - 1);
    if (j < g_nch[b]) return;
    float4* o = (float4*)(out + (size_t)row * D);
    o[threadIdx.x] = make_float4(0.f, 0.f, 0.f, 0.f);
}

// ---------------- Kernel 4b: windowed-parallel chunk EMA scan ---------------
__global__ __launch_bounds__(128) void chunk_scan_kernel(
    const float* __restrict__ tokens, float* __restrict__ out)
{
    int b = blockIdx.z;
    int nch = g_nch[b];
    int j0 = blockIdx.y * 128;
    if (j0 >= nch) return;
    int d = blockIdx.x * 128 + threadIdx.x;
    int jstart = (j0 >= 64) ? (j0 - 64) : 0;
    int jend = min(j0 + 128, nch);
    int cnt = jend - jstart;

    __shared__ int   sl[192];
    __shared__ float sp[192];
    for (int i = threadIdx.x; i < cnt; i += 128) {
        int l = g_blidx[b * L + jstart + i];
        sl[i] = l;
        sp[i] = g_probs[b * L + l];
    }
    __syncthreads();

    float h = 0.f;
    int i = 0;
    int warm = j0 - jstart;
    for (; i < warm; i++) {
        float p = sp[i];
        float t = tokens[((size_t)b * L + sl[i]) * D + d];
        h = fmaf(1.f - p, h, p * t);
    }
    for (; i < cnt; i++) {
        int j = jstart + i;
        float p = sp[i];
        float t = tokens[((size_t)b * L + sl[i]) * D + d];
        float x = p * t;
        out[((size_t)b * L + j) * D + d] = x;          // downsampled
        h = fmaf(1.f - p, h, x);
        g_scan[((size_t)b * L + j) * D + d] = h;
    }
}

// ---------------- Kernel 5: ups = gather(scan) + res + b_res ----------------
__global__ __launch_bounds__(256) void ups_kernel(
    float* __restrict__ out, const float* __restrict__ b_res)
{
    int row = blockIdx.x;          // b*L + l
    int b = row >> 12;
    int cid = g_chunkid[row];
    const float4* sc = (const float4*)(g_scan + (size_t)(b * L + cid) * D);
    const float4* rs = (const float4*)(g_res + (size_t)row * D);
    const float4* br = (const float4*)b_res;
    float4* o = (float4*)(out + BLD + (size_t)row * D);
    int t = threadIdx.x;
    float4 a = sc[t], c = rs[t], e = br[t];
    o[t] = make_float4(a.x + c.x + e.x, a.y + c.y + e.y,
                       a.z + c.z + e.z, a.w + c.w + e.w);
}

// ---------------- Kernel 6: finalize aux scalar -----------------------------
__global__ void aux_final_kernel(float* __restrict__ out)
{
    float s = 0.f;
    for (int i = 0; i < B; i++) s += g_auxb[i];
    out[2 * BLD] = (s / (float)B) * 0.03f;
}

// ---------------- launch ----------------------------------------------------
extern "C" void kernel_launch(void* const* d_in, const int* in_sizes, int n_in,
                              void* d_out, int out_size)
{
    const float* tokens = (const float*)d_in[0];
    const float* Wqk    = (const float*)d_in[1];
    const float* skey   = (const float*)d_in[2];
    const float* Wres   = (const float*)d_in[3];
    const float* bres   = (const float*)d_in[4];
    float* out = (float*)d_out;

    cudaFuncSetAttribute(qk_gemm_kernel,
                         cudaFuncAttributeMaxDynamicSharedMemorySize, QK_SMEM);
    cudaFuncSetAttribute(res_gemm_kernel,
                         cudaFuncAttributeMaxDynamicSharedMemorySize, RES_SMEM);
    cudaFuncSetAttribute(fixup_gemm_kernel,
                         cudaFuncAttributeMaxDynamicSharedMemorySize, FIX_SMEM);

    split_a_kernel<<<M * 128 / 256, 256>>>(tokens);
    split_b_kernel<<<NTOT * 128 / 256, 256>>>(Wqk, Wres);
    zero_nfix_kernel<<<1, 1>>>();
    qk_gemm_kernel<<<dim3(16, 256), 256, QK_SMEM>>>();
    res_gemm_kernel<<<dim3(16, 256), 256, RES_SMEM>>>();
    probs_kernel<<<M, 128>>>(skey);
    pad_fix_kernel<<<1, 1>>>();
    fixup_gemm_kernel<<<dim3(8, 512), 256, FIX_SMEM>>>();
    fixup_cos_kernel<<<M, 128>>>(skey);
    boundary_kernel<<<B, 1024>>>();
    zero_down_kernel<<<M, 256>>>(out);
    chunk_scan_kernel<<<dim3(D / 128, L / 128, B), 128>>>(tokens, out);
    ups_kernel<<<M, 256>>>(out, bres);
    aux_final_kernel<<<1, 1>>>(out);
}

// round 14
// speedup vs baseline: 2.2883x; 1.1924x over previous
#include <cuda_runtime.h>
#include <cuda_fp16.h>
#include <cstdint>

#define B   8
#define L   4096
#define D   1024
#define DQK 1024
#define M   (B * L)           // 32768 tokens
#define BLD ((size_t)M * D)   // 33554432
#define NTOT 3072
#define TILE_B 16384          // one 128x64 fp16 tile (128B rows, swizzled)

// ---------------- scratch (device globals; no allocation allowed) ----------
__device__ float g_q[(size_t)M * DQK];     // 128 MiB
__device__ float g_k[(size_t)M * DQK];     // 128 MiB
__device__ float g_res[(size_t)M * D];     // 128 MiB
__device__ float g_scan[(size_t)M * D];    // 128 MiB
__device__ float g_probs[M];
__device__ int   g_flag[M];
__device__ int   g_fixlist[M];
__device__ int   g_nfix;
__device__ int   g_nfixpad;
__device__ int   g_chunkid[M];
__device__ int   g_blidx[M];
__device__ int   g_nch[B];
__device__ float g_auxb[B];

// PRE-SWIZZLED tiled layouts (fp16): [block][chunk 0..15][16KB tile]
__device__ __half g_Ahi [(size_t)M * 1024];
__device__ __half g_Amid[(size_t)M * 1024];
__device__ __half g_Bhi [(size_t)NTOT * 1024];
__device__ __half g_Bmid[(size_t)NTOT * 1024];

// ======================= helpers ===========================================
__device__ __forceinline__ uint32_t smem_u32(const void* p) {
    uint32_t a;
    asm("{ .reg .u64 t; cvta.to.shared.u64 t, %1; cvt.u32.u64 %0, t; }"
        : "=r"(a) : "l"(p));
    return a;
}
__device__ __forceinline__ void mbar_init(uint32_t a, uint32_t cnt) {
    asm volatile("mbarrier.init.shared.b64 [%0], %1;" :: "r"(a), "r"(cnt) : "memory");
}
__device__ __forceinline__ void mbar_expect_tx(uint32_t a, uint32_t bytes) {
    asm volatile("mbarrier.arrive.expect_tx.shared.b64 _, [%0], %1;"
                 :: "r"(a), "r"(bytes) : "memory");
}
__device__ __forceinline__ void mbar_wait(uint32_t a, uint32_t parity) {
    uint32_t done;
    asm volatile(
        "{\n\t.reg .pred p;\n\t"
        "mbarrier.try_wait.parity.acquire.cta.shared::cta.b64 p, [%1], %2;\n\t"
        "selp.b32 %0, 1, 0, p;\n\t}"
        : "=r"(done) : "r"(a), "r"(parity) : "memory");
    if (!done) {
        asm volatile(
            "{\n\t.reg .pred P1;\n\t"
            "WL_%=:\n\t"
            "mbarrier.try_wait.parity.acquire.cta.shared::cta.b64 P1, [%0], %1, 0x989680;\n\t"
            "@P1 bra.uni WD_%=;\n\t"
            "bra.uni WL_%=;\n\t"
            "WD_%=:\n\t}"
            :: "r"(a), "r"(parity) : "memory");
    }
}
__device__ __forceinline__ void bulk_cp(uint32_t dst, const void* src,
                                        uint32_t bytes, uint32_t mbar) {
    asm volatile(
        "cp.async.bulk.shared::cta.global.mbarrier::complete_tx::bytes "
        "[%0], [%1], %2, [%3];"
        :: "r"(dst), "l"(src), "r"(bytes), "r"(mbar) : "memory");
}
__device__ __forceinline__ void ldsm_x4(uint32_t addr, uint32_t& r0, uint32_t& r1,
                                        uint32_t& r2, uint32_t& r3) {
    asm volatile("ldmatrix.sync.aligned.m8n8.x4.shared.b16 {%0,%1,%2,%3}, [%4];"
                 : "=r"(r0), "=r"(r1), "=r"(r2), "=r"(r3) : "r"(addr));
}
__device__ __forceinline__ void mma_f16(float* c,
                                        const uint32_t* a,
                                        uint32_t b0, uint32_t b1) {
    asm volatile(
        "mma.sync.aligned.m16n8k16.row.col.f32.f16.f16.f32 "
        "{%0,%1,%2,%3}, {%4,%5,%6,%7}, {%8,%9}, {%0,%1,%2,%3};"
        : "+f"(c[0]), "+f"(c[1]), "+f"(c[2]), "+f"(c[3])
        : "r"(a[0]), "r"(a[1]), "r"(a[2]), "r"(a[3]), "r"(b0), "r"(b1));
}

__device__ __forceinline__ size_t tile_addr(int block, int row, int kg) {
    int chunk = kg >> 3;
    int colB  = (kg & 7) * 16;
    int sw    = colB ^ ((row & 7) << 4);
    return ((size_t)block * 16 + chunk) * TILE_B + row * 128 + sw;
}

// ---------------- Prep 1: split tokens -> swizzled-tiled fp16 hi/mid --------
__global__ __launch_bounds__(256) void split_a_kernel(const float* __restrict__ A)
{
    int idx = blockIdx.x * 256 + threadIdx.x;      // 0 .. M*128-1
    int m  = idx >> 7;
    int kg = idx & 127;
    const float4* src = (const float4*)(A + (size_t)m * 1024 + kg * 8);
    float4 v0 = src[0], v1 = src[1];
    float x[8] = {v0.x, v0.y, v0.z, v0.w, v1.x, v1.y, v1.z, v1.w};
    unsigned short h[8], mm[8];
#pragma unroll
    for (int j = 0; j < 8; j++) {
        __half bh = __float2half_rn(x[j]);
        float r1 = x[j] - __half2float(bh);
        __half bm = __float2half_rn(r1);
        h[j]  = __half_as_ushort(bh);
        mm[j] = __half_as_ushort(bm);
    }
    size_t a = tile_addr(m >> 7, m & 127, kg);
#define PACK4(arr) make_uint4((unsigned)arr[0] | ((unsigned)arr[1] << 16), \
                              (unsigned)arr[2] | ((unsigned)arr[3] << 16), \
                              (unsigned)arr[4] | ((unsigned)arr[5] << 16), \
                              (unsigned)arr[6] | ((unsigned)arr[7] << 16))
    *(uint4*)((char*)g_Ahi  + a) = PACK4(h);
    *(uint4*)((char*)g_Amid + a) = PACK4(mm);
}

// ---------------- Prep 2: split + transpose weights -> swizzled tiles -------
__global__ __launch_bounds__(256) void split_b_kernel(
    const float* __restrict__ Wqk, const float* __restrict__ Wres)
{
    int id = blockIdx.x * 256 + threadIdx.x;   // 0..393215
    int n  = id % NTOT;
    int kg = id / NTOT;
    unsigned short h[8], mm[8];
#pragma unroll
    for (int j = 0; j < 8; j++) {
        int k = kg * 8 + j;
        float x = (n < 2048) ? Wqk[(size_t)k * 2048 + n]
                             : Wres[(size_t)k * 1024 + (n - 2048)];
        __half bh = __float2half_rn(x);
        float r1 = x - __half2float(bh);
        __half bm = __float2half_rn(r1);
        h[j]  = __half_as_ushort(bh);
        mm[j] = __half_as_ushort(bm);
    }
    size_t a = tile_addr(n >> 7, n & 127, kg);
    *(uint4*)((char*)g_Bhi  + a) = PACK4(h);
    *(uint4*)((char*)g_Bmid + a) = PACK4(mm);
#undef PACK4
}

// ---------------- Kernel 1a: QK GEMM (single product, occ 2) ----------------
#define QK_STAGE (2 * TILE_B)               // 32 KB
#define QK_SMEM  (128 + 3 * QK_STAGE)       // ~96 KB -> 2 CTAs/SM

__global__ void __launch_bounds__(256, 2) qk_gemm_kernel()
{
    extern __shared__ char smem[];
    uint32_t sb = smem_u32(smem);
    const int tid = threadIdx.x;
    const int lane = tid & 31;
    const int wid = tid >> 5;
    const int warp_m = wid & 3;
    const int warp_n = wid >> 2;
    const int m0 = blockIdx.y * 128;
    const int n0 = blockIdx.x * 128;

    const char* asrc = (const char*)g_Ahi + (size_t)(m0 >> 7) * 16 * TILE_B;
    const char* bsrc = (const char*)g_Bhi + (size_t)(n0 >> 7) * 16 * TILE_B;

    if (tid == 0) {
        mbar_init(sb + 0, 1);
        mbar_init(sb + 8, 1);
        mbar_init(sb + 16, 1);
    }
    __syncthreads();

    float acc[2][8][4];
#pragma unroll
    for (int i = 0; i < 2; i++)
#pragma unroll
        for (int j = 0; j < 8; j++)
#pragma unroll
            for (int q = 0; q < 4; q++) acc[i][j][q] = 0.f;

    const int aRow  = warp_m * 32 + (lane & 15);
    const int aXor  = (aRow & 7) << 4;
    const int aColB = (lane >> 4) * 16;
    const int bRow  = warp_n * 64 + (lane & 7) + ((lane >> 4) & 1) * 8;
    const int bXor  = (bRow & 7) << 4;
    const int bColB = ((lane >> 3) & 1) * 16;

    if (tid == 0) {
#pragma unroll
        for (int c = 0; c < 2; c++) {
            uint32_t mb = sb + c * 8;
            uint32_t st = sb + 128 + c * QK_STAGE;
            mbar_expect_tx(mb, QK_STAGE);
            bulk_cp(st,          asrc + (size_t)c * TILE_B, TILE_B, mb);
            bulk_cp(st + TILE_B, bsrc + (size_t)c * TILE_B, TILE_B, mb);
        }
    }

#pragma unroll 1
    for (int c = 0; c < 16; c++) {
        int s = c % 3;
        uint32_t stage = sb + 128 + s * QK_STAGE;
        if (c < 14 && tid == 0) {
            int s2 = (c + 2) % 3;
            uint32_t mb = sb + s2 * 8;
            uint32_t st = sb + 128 + s2 * QK_STAGE;
            mbar_expect_tx(mb, QK_STAGE);
            bulk_cp(st,          asrc + (size_t)(c + 2) * TILE_B, TILE_B, mb);
            bulk_cp(st + TILE_B, bsrc + (size_t)(c + 2) * TILE_B, TILE_B, mb);
        }
        mbar_wait(sb + s * 8, (c / 3) & 1);
        __syncthreads();

        uint32_t aHi = stage, bHi = stage + TILE_B;
#pragma unroll 1
        for (int ks = 0; ks < 4; ks++) {
            uint32_t ah[2][4];
#pragma unroll
            for (int mi = 0; mi < 2; mi++) {
                uint32_t roff = (aRow + mi * 16) * 128 + ((ks * 32 + aColB) ^ aXor);
                ldsm_x4(aHi + roff, ah[mi][0], ah[mi][1], ah[mi][2], ah[mi][3]);
            }
#pragma unroll
            for (int ng = 0; ng < 4; ng++) {
                uint32_t roff = (bRow + ng * 16) * 128 + ((ks * 32 + bColB) ^ bXor);
                uint32_t b0, b1, b2, b3;
                ldsm_x4(bHi + roff, b0, b1, b2, b3);
                mma_f16(acc[0][ng*2],   ah[0], b0, b1);
                mma_f16(acc[0][ng*2+1], ah[0], b2, b3);
                mma_f16(acc[1][ng*2],   ah[1], b0, b1);
                mma_f16(acc[1][ng*2+1], ah[1], b2, b3);
            }
        }
        __syncthreads();
    }

    float* cbase = (n0 < 1024) ? g_q : g_k;
    int coloff = n0 & 1023;
#pragma unroll
    for (int mi = 0; mi < 2; mi++) {
        int r0 = m0 + warp_m * 32 + mi * 16 + (lane >> 2);
#pragma unroll
        for (int ni = 0; ni < 8; ni++) {
            int col = coloff + warp_n * 64 + ni * 8 + (lane & 3) * 2;
            *(float2*)&cbase[(size_t)r0 * 1024 + col] =
                make_float2(acc[mi][ni][0], acc[mi][ni][1]);
            *(float2*)&cbase[(size_t)(r0 + 8) * 1024 + col] =
                make_float2(acc[mi][ni][2], acc[mi][ni][3]);
        }
    }
}

// ---------------- Kernel 1b: residual GEMM (2 fp16 passes, N-tile 64) -------
// res = (Ahi + Amid) @ Bhi — exact-A times hi-B; dropped t@Wm term ~1e-4 rel.
#define RES_STAGE (2 * TILE_B + 8192)       // 40 KB
#define RES_SMEM  (128 + 2 * RES_STAGE)     // ~80 KB -> 2 CTAs/SM

__global__ void __launch_bounds__(256, 2) res_gemm_kernel()
{
    extern __shared__ char smem[];
    uint32_t sb = smem_u32(smem);
    const int tid = threadIdx.x;
    const int lane = tid & 31;
    const int wid = tid >> 5;
    const int warp_m = wid & 3;
    const int warp_n = wid >> 2;            // 0..1, covers 32 n-cols
    const int m0 = blockIdx.y * 128;
    const int nb = blockIdx.x;              // 0..15, 64 cols each

    const char* ahiSrc  = (const char*)g_Ahi  + (size_t)(m0 >> 7) * 16 * TILE_B;
    const char* amidSrc = (const char*)g_Amid + (size_t)(m0 >> 7) * 16 * TILE_B;
    const int bblock = 16 + (nb >> 1);
    const size_t boff = (size_t)(nb & 1) * 8192;
    const char* bhiSrc  = (const char*)g_Bhi  + (size_t)bblock * 16 * TILE_B + boff;

    if (tid == 0) {
        mbar_init(sb + 0, 1);
        mbar_init(sb + 8, 1);
    }
    __syncthreads();

    float acc[2][4][4];
#pragma unroll
    for (int i = 0; i < 2; i++)
#pragma unroll
        for (int j = 0; j < 4; j++)
#pragma unroll
            for (int q = 0; q < 4; q++) acc[i][j][q] = 0.f;

    const int aRow  = warp_m * 32 + (lane & 15);
    const int aXor  = (aRow & 7) << 4;
    const int aColB = (lane >> 4) * 16;
    const int bRow  = warp_n * 32 + (lane & 7) + ((lane >> 4) & 1) * 8;
    const int bXor  = (bRow & 7) << 4;
    const int bColB = ((lane >> 3) & 1) * 16;

    if (tid == 0) {
#pragma unroll
        for (int c = 0; c < 2; c++) {
            uint32_t mb = sb + c * 8;
            uint32_t st = sb + 128 + c * RES_STAGE;
            mbar_expect_tx(mb, RES_STAGE);
            bulk_cp(st,              ahiSrc  + (size_t)c * TILE_B, TILE_B, mb);
            bulk_cp(st + TILE_B,     amidSrc + (size_t)c * TILE_B, TILE_B, mb);
            bulk_cp(st + 2 * TILE_B, bhiSrc  + (size_t)c * TILE_B, 8192, mb);
        }
    }

#pragma unroll 1
    for (int c = 0; c < 16; c++) {
        int s = c & 1;
        uint32_t stage = sb + 128 + s * RES_STAGE;
        mbar_wait(sb + s * 8, (c >> 1) & 1);
        __syncthreads();

        uint32_t aHi = stage, aMid = stage + TILE_B;
        uint32_t bHi = stage + 2 * TILE_B;
#pragma unroll 1
        for (int ks = 0; ks < 4; ks++) {
            uint32_t ah[2][4], am[2][4];
#pragma unroll
            for (int mi = 0; mi < 2; mi++) {
                uint32_t roff = (aRow + mi * 16) * 128 + ((ks * 32 + aColB) ^ aXor);
                ldsm_x4(aHi  + roff, ah[mi][0], ah[mi][1], ah[mi][2], ah[mi][3]);
                ldsm_x4(aMid + roff, am[mi][0], am[mi][1], am[mi][2], am[mi][3]);
            }
#pragma unroll
            for (int ng = 0; ng < 2; ng++) {
                uint32_t roff = (bRow + ng * 16) * 128 + ((ks * 32 + bColB) ^ bXor);
                uint32_t b0, b1, b2, b3;
                ldsm_x4(bHi + roff, b0, b1, b2, b3);
                mma_f16(acc[0][ng*2],   ah[0], b0, b1);
                mma_f16(acc[0][ng*2+1], ah[0], b2, b3);
                mma_f16(acc[1][ng*2],   ah[1], b0, b1);
                mma_f16(acc[1][ng*2+1], ah[1], b2, b3);
                mma_f16(acc[0][ng*2],   am[0], b0, b1);
                mma_f16(acc[0][ng*2+1], am[0], b2, b3);
                mma_f16(acc[1][ng*2],   am[1], b0, b1);
                mma_f16(acc[1][ng*2+1], am[1], b2, b3);
            }
        }
        __syncthreads();
        if (c < 14 && tid == 0) {
            uint32_t mb = sb + s * 8;
            uint32_t st = stage;
            mbar_expect_tx(mb, RES_STAGE);
            bulk_cp(st,              ahiSrc  + (size_t)(c + 2) * TILE_B, TILE_B, mb);
            bulk_cp(st + TILE_B,     amidSrc + (size_t)(c + 2) * TILE_B, TILE_B, mb);
            bulk_cp(st + 2 * TILE_B, bhiSrc  + (size_t)(c + 2) * TILE_B, 8192, mb);
        }
    }

    int coloff = nb * 64;
#pragma unroll
    for (int mi = 0; mi < 2; mi++) {
        int r0 = m0 + warp_m * 32 + mi * 16 + (lane >> 2);
#pragma unroll
        for (int ni = 0; ni < 4; ni++) {
            int col = coloff + warp_n * 32 + ni * 8 + (lane & 3) * 2;
            *(float2*)&g_res[(size_t)r0 * 1024 + col] =
                make_float2(acc[mi][ni][0], acc[mi][ni][1]);
            *(float2*)&g_res[(size_t)(r0 + 8) * 1024 + col] =
                make_float2(acc[mi][ni][2], acc[mi][ni][3]);
        }
    }
}

// ---------------- zero fix counter ------------------------------------------
__global__ void zero_nfix_kernel() { g_nfix = 0; }

// ---------------- Kernel 2: cosine -> probs + flag + compact list -----------
__global__ __launch_bounds__(128) void probs_kernel(const float* __restrict__ start_key)
{
    int token = blockIdx.x;
    int l = token & (L - 1);
    const float4* qv = (const float4*)(g_q + (size_t)token * DQK);
    const float4* kv = (l == 0) ? (const float4*)start_key
                                : (const float4*)(g_k + (size_t)(token - 1) * DQK);
    float dot = 0.f, qq = 0.f, kk = 0.f;
    for (int i = threadIdx.x; i < DQK / 4; i += 128) {
        float4 a = qv[i], c = kv[i];
        dot += a.x * c.x + a.y * c.y + a.z * c.z + a.w * c.w;
        qq  += a.x * a.x + a.y * a.y + a.z * a.z + a.w * a.w;
        kk  += c.x * c.x + c.y * c.y + c.z * c.z + c.w * c.w;
    }
#pragma unroll
    for (int o = 16; o; o >>= 1) {
        dot += __shfl_down_sync(0xffffffffu, dot, o);
        qq  += __shfl_down_sync(0xffffffffu, qq,  o);
        kk  += __shfl_down_sync(0xffffffffu, kk,  o);
    }
    __shared__ float sd[4], sq[4], sk[4];
    int w = threadIdx.x >> 5;
    if ((threadIdx.x & 31) == 0) { sd[w] = dot; sq[w] = qq; sk[w] = kk; }
    __syncthreads();
    if (threadIdx.x == 0) {
        dot = sd[0] + sd[1] + sd[2] + sd[3];
        qq  = sq[0] + sq[1] + sq[2] + sq[3];
        kk  = sk[0] + sk[1] + sk[2] + sk[3];
        float denom = fmaxf(sqrtf(qq) * sqrtf(kk), 1e-8f);
        float cosv = dot / denom;
        g_probs[token] = (1.0f - cosv) * 0.5f;
        int fl = (fabsf(cosv) < 2.5e-4f) ? 1 : 0;
        g_flag[token] = fl;
        if (fl) {
            int slot = atomicAdd(&g_nfix, 1);
            g_fixlist[slot] = token;
        }
    }
}

// ---------------- pad fix list to multiple of 128 ---------------------------
__global__ void pad_fix_kernel()
{
    int nf = g_nfix;
    int np = (nf + 127) & ~127;
    if (nf > 0)
        for (int i = nf; i < np; i++) g_fixlist[i] = g_fixlist[0];
    g_nfixpad = (nf > 0) ? np : 0;
}

// ---------------- Kernel 2b: gathered 3-pass GEMM over flagged tokens -------
#define FIX_SMEM (512 + 4 * TILE_B)

__global__ void __launch_bounds__(256, 1) fixup_gemm_kernel()
{
    int mb = blockIdx.y & 255;
    if (mb * 128 >= g_nfixpad) return;
    const int isq = (blockIdx.y < 256);
    const int nblock = (isq ? 0 : 8) + blockIdx.x;     // global n-block 0..15

    extern __shared__ char smem[];
    int* toks = (int*)smem;
    uint32_t sb = smem_u32(smem) + 512;
    const int tid = threadIdx.x;
    const int lane = tid & 31;
    const int wid = tid >> 5;
    const int warp_m = wid & 3;
    const int warp_n = wid >> 2;

    if (tid < 128) {
        int t = g_fixlist[mb * 128 + tid];
        toks[tid] = isq ? t : max(t - 1, 0);
    }
    __syncthreads();

    float acc[2][8][4];
#pragma unroll
    for (int i = 0; i < 2; i++)
#pragma unroll
        for (int j = 0; j < 8; j++)
#pragma unroll
            for (int q = 0; q < 4; q++) acc[i][j][q] = 0.f;

    const int aRow  = warp_m * 32 + (lane & 15);
    const int aXor  = (aRow & 7) << 4;
    const int aColB = (lane >> 4) * 16;
    const int bRow  = warp_n * 64 + (lane & 7) + ((lane >> 4) & 1) * 8;
    const int bXor  = (bRow & 7) << 4;
    const int bColB = ((lane >> 3) & 1) * 16;

    const char* bhiSrc  = (const char*)g_Bhi  + (size_t)nblock * 16 * TILE_B;
    const char* bmidSrc = (const char*)g_Bmid + (size_t)nblock * 16 * TILE_B;

#pragma unroll 1
    for (int c = 0; c < 16; c++) {
#pragma unroll
        for (int it = 0; it < 4; it++) {
            int w = tid + it * 256;
            int r = w >> 3, kg7 = w & 7;
            int tok = toks[r];
            size_t srcOff = ((size_t)(tok >> 7) * 16 + c) * TILE_B
                          + (tok & 127) * 128 + ((kg7 * 16) ^ (((tok & 127) & 7) << 4));
            uint32_t dst = r * 128 + ((kg7 * 16) ^ ((r & 7) << 4));
            *(uint4*)(smem + 512 + dst)              = *(const uint4*)((const char*)g_Ahi  + srcOff);
            *(uint4*)(smem + 512 + TILE_B + dst)     = *(const uint4*)((const char*)g_Amid + srcOff);
            *(uint4*)(smem + 512 + 2 * TILE_B + w * 16) =
                *(const uint4*)(bhiSrc  + (size_t)c * TILE_B + w * 16);
            *(uint4*)(smem + 512 + 3 * TILE_B + w * 16) =
                *(const uint4*)(bmidSrc + (size_t)c * TILE_B + w * 16);
        }
        __syncthreads();

        uint32_t aHi = sb, aMid = sb + TILE_B;
        uint32_t bHi = sb + 2 * TILE_B, bMid = sb + 3 * TILE_B;
#pragma unroll 1
        for (int ks = 0; ks < 4; ks++) {
            uint32_t ah[2][4], am[2][4];
#pragma unroll
            for (int mi = 0; mi < 2; mi++) {
                uint32_t roff = (aRow + mi * 16) * 128 + ((ks * 32 + aColB) ^ aXor);
                ldsm_x4(aHi  + roff, ah[mi][0], ah[mi][1], ah[mi][2], ah[mi][3]);
                ldsm_x4(aMid + roff, am[mi][0], am[mi][1], am[mi][2], am[mi][3]);
            }
#pragma unroll
            for (int ng = 0; ng < 4; ng++) {
                uint32_t roff = (bRow + ng * 16) * 128 + ((ks * 32 + bColB) ^ bXor);
                uint32_t b0, b1, b2, b3;
                ldsm_x4(bHi + roff, b0, b1, b2, b3);
                mma_f16(acc[0][ng*2],   ah[0], b0, b1);
                mma_f16(acc[0][ng*2+1], ah[0], b2, b3);
                mma_f16(acc[1][ng*2],   ah[1], b0, b1);
                mma_f16(acc[1][ng*2+1], ah[1], b2, b3);
                mma_f16(acc[0][ng*2],   am[0], b0, b1);
                mma_f16(acc[0][ng*2+1], am[0], b2, b3);
                mma_f16(acc[1][ng*2],   am[1], b0, b1);
                mma_f16(acc[1][ng*2+1], am[1], b2, b3);
                ldsm_x4(bMid + roff, b0, b1, b2, b3);
                mma_f16(acc[0][ng*2],   ah[0], b0, b1);
                mma_f16(acc[0][ng*2+1], ah[0], b2, b3);
                mma_f16(acc[1][ng*2],   ah[1], b0, b1);
                mma_f16(acc[1][ng*2+1], ah[1], b2, b3);
            }
        }
        __syncthreads();
    }

    float* cbase = isq ? g_q : g_k;
    int coloff = (nblock & 7) * 128;
#pragma unroll
    for (int mi = 0; mi < 2; mi++) {
        int rloc = warp_m * 32 + mi * 16 + (lane >> 2);
        int row0 = toks[rloc];
        int row1 = toks[rloc + 8];
#pragma unroll
        for (int ni = 0; ni < 8; ni++) {
            int col = coloff + warp_n * 64 + ni * 8 + (lane & 3) * 2;
            *(float2*)&cbase[(size_t)row0 * 1024 + col] =
                make_float2(acc[mi][ni][0], acc[mi][ni][1]);
            *(float2*)&cbase[(size_t)row1 * 1024 + col] =
                make_float2(acc[mi][ni][2], acc[mi][ni][3]);
        }
    }
}

// ---------------- Kernel 2c: exact cosine for flagged tokens ----------------
__global__ __launch_bounds__(128) void fixup_cos_kernel(const float* __restrict__ start_key)
{
    int token = blockIdx.x;
    if (!g_flag[token]) return;
    int l = token & (L - 1);
    const float4* qv = (const float4*)(g_q + (size_t)token * DQK);
    const float4* kv = (l == 0) ? (const float4*)start_key
                                : (const float4*)(g_k + (size_t)(token - 1) * DQK);
    float dot = 0.f, qq = 0.f, kk = 0.f;
    for (int i = threadIdx.x; i < DQK / 4; i += 128) {
        float4 a = qv[i], c = kv[i];
        dot += a.x * c.x + a.y * c.y + a.z * c.z + a.w * c.w;
        qq  += a.x * a.x + a.y * a.y + a.z * a.z + a.w * a.w;
        kk  += c.x * c.x + c.y * c.y + c.z * c.z + c.w * c.w;
    }
#pragma unroll
    for (int o = 16; o; o >>= 1) {
        dot += __shfl_down_sync(0xffffffffu, dot, o);
        qq  += __shfl_down_sync(0xffffffffu, qq,  o);
        kk  += __shfl_down_sync(0xffffffffu, kk,  o);
    }
    __shared__ float sd[4], sq[4], sk[4];
    int w = threadIdx.x >> 5;
    if ((threadIdx.x & 31) == 0) { sd[w] = dot; sq[w] = qq; sk[w] = kk; }
    __syncthreads();
    if (threadIdx.x == 0) {
        dot = sd[0] + sd[1] + sd[2] + sd[3];
        qq  = sq[0] + sq[1] + sq[2] + sq[3];
        kk  = sk[0] + sk[1] + sk[2] + sk[3];
        float denom = fmaxf(sqrtf(qq) * sqrtf(kk), 1e-8f);
        g_probs[token] = (1.0f - dot / denom) * 0.5f;
    }
}

// ---------------- Kernel 3: per-batch boundary scan + aux -------------------
__global__ __launch_bounds__(1024) void boundary_kernel()
{
    int b = blockIdx.x;
    int tid = threadIdx.x;
    __shared__ int   s[1024];
    __shared__ float sf[1024];

    int l0 = tid * 4;
    float p[4]; int bd[4]; int cnt = 0; float psum = 0.f;
#pragma unroll
    for (int i = 0; i < 4; i++) {
        int l = l0 + i;
        p[i] = g_probs[b * L + l];
        bd[i] = (l == 0) || (p[i] > 0.5f);
        cnt += bd[i];
        psum += p[i];
    }
    s[tid] = cnt;
    sf[tid] = psum;
    __syncthreads();
    for (int off = 1; off < 1024; off <<= 1) {
        int v = (tid >= off) ? s[tid - off] : 0;
        __syncthreads();
        if (tid >= off) s[tid] += v;
        __syncthreads();
    }
    int incl = s[tid];
    int base = incl - cnt;
    int total = s[1023];
    int run = base;
#pragma unroll
    for (int i = 0; i < 4; i++) {
        int l = l0 + i;
        if (bd[i]) { g_blidx[b * L + run] = l; run++; }
        g_chunkid[b * L + l] = run - 1;
    }
    __syncthreads();
    for (int off = 512; off > 0; off >>= 1) {
        if (tid < off) sf[tid] += sf[tid + off];
        __syncthreads();
    }
    if (tid == 0) {
        float F = (float)total / (float)L;
        float G = sf[0] / (float)L;
        g_auxb[b] = 1.2f * (5.0f * F * G + (1.0f - F) * (1.0f - G));
        g_nch[b] = total;
    }
}

// ---------------- Kernel 4a: zero padded chunk slots of downsampled ---------
__global__ __launch_bounds__(256) void zero_down_kernel(float* __restrict__ out)
{
    int row = blockIdx.x;          // b*L + j
    int b = row >> 12;
    int j = row & (L - 1);
    if (j < g_nch[b]) return;
    float4* o = (float4*)(out + (size_t)row * D);
    o[threadIdx.x] = make_float4(0.f, 0.f, 0.f, 0.f);
}

// ---------------- Kernel 4b: windowed-parallel chunk EMA scan ---------------
__global__ __launch_bounds__(128) void chunk_scan_kernel(
    const float* __restrict__ tokens, float* __restrict__ out)
{
    int b = blockIdx.z;
    int nch = g_nch[b];
    int j0 = blockIdx.y * 128;
    if (j0 >= nch) return;
    int d = blockIdx.x * 128 + threadIdx.x;
    int jstart = (j0 >= 64) ? (j0 - 64) : 0;
    int jend = min(j0 + 128, nch);
    int cnt = jend - jstart;

    __shared__ int   sl[192];
    __shared__ float sp[192];
    for (int i = threadIdx.x; i < cnt; i += 128) {
        int l = g_blidx[b * L + jstart + i];
        sl[i] = l;
        sp[i] = g_probs[b * L + l];
    }
    __syncthreads();

    float h = 0.f;
    int i = 0;
    int warm = j0 - jstart;
    for (; i < warm; i++) {
        float p = sp[i];
        float t = tokens[((size_t)b * L + sl[i]) * D + d];
        h = fmaf(1.f - p, h, p * t);
    }
    for (; i < cnt; i++) {
        int j = jstart + i;
        float p = sp[i];
        float t = tokens[((size_t)b * L + sl[i]) * D + d];
        float x = p * t;
        out[((size_t)b * L + j) * D + d] = x;          // downsampled
        h = fmaf(1.f - p, h, x);
        g_scan[((size_t)b * L + j) * D + d] = h;
    }
}

// ---------------- Kernel 5: ups = gather(scan) + res + b_res ----------------
__global__ __launch_bounds__(256) void ups_kernel(
    float* __restrict__ out, const float* __restrict__ b_res)
{
    int row = blockIdx.x;          // b*L + l
    int b = row >> 12;
    int cid = g_chunkid[row];
    const float4* sc = (const float4*)(g_scan + (size_t)(b * L + cid) * D);
    const float4* rs = (const float4*)(g_res + (size_t)row * D);
    const float4* br = (const float4*)b_res;
    float4* o = (float4*)(out + BLD + (size_t)row * D);
    int t = threadIdx.x;
    float4 a = sc[t], c = rs[t], e = br[t];
    o[t] = make_float4(a.x + c.x + e.x, a.y + c.y + e.y,
                       a.z + c.z + e.z, a.w + c.w + e.w);
}

// ---------------- Kernel 6: finalize aux scalar -----------------------------
__global__ void aux_final_kernel(float* __restrict__ out)
{
    float s = 0.f;
    for (int i = 0; i < B; i++) s += g_auxb[i];
    out[2 * BLD] = (s / (float)B) * 0.03f;
}

// ---------------- launch ----------------------------------------------------
extern "C" void kernel_launch(void* const* d_in, const int* in_sizes, int n_in,
                              void* d_out, int out_size)
{
    const float* tokens = (const float*)d_in[0];
    const float* Wqk    = (const float*)d_in[1];
    const float* skey   = (const float*)d_in[2];
    const float* Wres   = (const float*)d_in[3];
    const float* bres   = (const float*)d_in[4];
    float* out = (float*)d_out;

    cudaFuncSetAttribute(qk_gemm_kernel,
                         cudaFuncAttributeMaxDynamicSharedMemorySize, QK_SMEM);
    cudaFuncSetAttribute(res_gemm_kernel,
                         cudaFuncAttributeMaxDynamicSharedMemorySize, RES_SMEM);
    cudaFuncSetAttribute(fixup_gemm_kernel,
                         cudaFuncAttributeMaxDynamicSharedMemorySize, FIX_SMEM);

    split_a_kernel<<<M * 128 / 256, 256>>>(tokens);
    split_b_kernel<<<NTOT * 128 / 256, 256>>>(Wqk, Wres);
    zero_nfix_kernel<<<1, 1>>>();
    qk_gemm_kernel<<<dim3(16, 256), 256, QK_SMEM>>>();
    res_gemm_kernel<<<dim3(16, 256), 256, RES_SMEM>>>();
    probs_kernel<<<M, 128>>>(skey);
    pad_fix_kernel<<<1, 1>>>();
    fixup_gemm_kernel<<<dim3(8, 512), 256, FIX_SMEM>>>();
    fixup_cos_kernel<<<M, 128>>>(skey);
    boundary_kernel<<<B, 1024>>>();
    zero_down_kernel<<<M, 256>>>(out);
    chunk_scan_kernel<<<dim3(D / 128, L / 128, B), 128>>>(tokens, out);
    ups_kernel<<<M, 256>>>(out, bres);
    aux_final_kernel<<<1, 1>>>(out);
}

// round 17
// speedup vs baseline: 2.6916x; 1.1762x over previous
#include <cuda_runtime.h>
#include <cuda_fp16.h>
#include <cstdint>

#define B   8
#define L   4096
#define D   1024
#define DQK 1024
#define M   (B * L)           // 32768 tokens
#define BLD ((size_t)M * D)   // 33554432
#define NTOT 3072
#define TILE_B 16384          // one 128x64 fp16 tile (128B rows, swizzled)

// ---------------- scratch (device globals; no allocation allowed) ----------
__device__ float g_q[(size_t)M * DQK];     // 128 MiB
__device__ float g_k[(size_t)M * DQK];     // 128 MiB
__device__ float g_res[(size_t)M * D];     // 128 MiB
__device__ float g_scan[(size_t)M * D];    // 128 MiB
__device__ float g_probs[M];
__device__ int   g_flag[M];
__device__ int   g_fixlist[M];
__device__ int   g_nfix;
__device__ int   g_nfixpad;
__device__ int   g_chunkid[M];
__device__ int   g_blidx[M];
__device__ int   g_nch[B];
__device__ float g_auxb[B];

// PRE-SWIZZLED tiled layouts (fp16): [block][chunk 0..15][16KB tile]
__device__ __half g_Ahi [(size_t)M * 1024];
__device__ __half g_Amid[(size_t)M * 1024];
__device__ __half g_Bhi [(size_t)NTOT * 1024];
__device__ __half g_Bmid[(size_t)NTOT * 1024];

// ======================= helpers ===========================================
__device__ __forceinline__ uint32_t smem_u32(const void* p) {
    uint32_t a;
    asm("{ .reg .u64 t; cvta.to.shared.u64 t, %1; cvt.u32.u64 %0, t; }"
        : "=r"(a) : "l"(p));
    return a;
}
__device__ __forceinline__ void mbar_init(uint32_t a, uint32_t cnt) {
    asm volatile("mbarrier.init.shared.b64 [%0], %1;" :: "r"(a), "r"(cnt) : "memory");
}
__device__ __forceinline__ void mbar_expect_tx(uint32_t a, uint32_t bytes) {
    asm volatile("mbarrier.arrive.expect_tx.shared.b64 _, [%0], %1;"
                 :: "r"(a), "r"(bytes) : "memory");
}
__device__ __forceinline__ void mbar_wait(uint32_t a, uint32_t parity) {
    uint32_t done;
    asm volatile(
        "{\n\t.reg .pred p;\n\t"
        "mbarrier.try_wait.parity.acquire.cta.shared::cta.b64 p, [%1], %2;\n\t"
        "selp.b32 %0, 1, 0, p;\n\t}"
        : "=r"(done) : "r"(a), "r"(parity) : "memory");
    if (!done) {
        asm volatile(
            "{\n\t.reg .pred P1;\n\t"
            "WL_%=:\n\t"
            "mbarrier.try_wait.parity.acquire.cta.shared::cta.b64 P1, [%0], %1, 0x989680;\n\t"
            "@P1 bra.uni WD_%=;\n\t"
            "bra.uni WL_%=;\n\t"
            "WD_%=:\n\t}"
            :: "r"(a), "r"(parity) : "memory");
    }
}
__device__ __forceinline__ void bulk_cp(uint32_t dst, const void* src,
                                        uint32_t bytes, uint32_t mbar) {
    asm volatile(
        "cp.async.bulk.shared::cta.global.mbarrier::complete_tx::bytes "
        "[%0], [%1], %2, [%3];"
        :: "r"(dst), "l"(src), "r"(bytes), "r"(mbar) : "memory");
}
__device__ __forceinline__ void ldsm_x4(uint32_t addr, uint32_t& r0, uint32_t& r1,
                                        uint32_t& r2, uint32_t& r3) {
    asm volatile("ldmatrix.sync.aligned.m8n8.x4.shared.b16 {%0,%1,%2,%3}, [%4];"
                 : "=r"(r0), "=r"(r1), "=r"(r2), "=r"(r3) : "r"(addr));
}
__device__ __forceinline__ void mma_f16(float* c,
                                        const uint32_t* a,
                                        uint32_t b0, uint32_t b1) {
    asm volatile(
        "mma.sync.aligned.m16n8k16.row.col.f32.f16.f16.f32 "
        "{%0,%1,%2,%3}, {%4,%5,%6,%7}, {%8,%9}, {%0,%1,%2,%3};"
        : "+f"(c[0]), "+f"(c[1]), "+f"(c[2]), "+f"(c[3])
        : "r"(a[0]), "r"(a[1]), "r"(a[2]), "r"(a[3]), "r"(b0), "r"(b1));
}

__device__ __forceinline__ size_t tile_addr(int block, int row, int kg) {
    int chunk = kg >> 3;
    int colB  = (kg & 7) * 16;
    int sw    = colB ^ ((row & 7) << 4);
    return ((size_t)block * 16 + chunk) * TILE_B + row * 128 + sw;
}

// ---------------- Prep 1: split tokens -> swizzled-tiled fp16 hi/mid --------
__global__ __launch_bounds__(256) void split_a_kernel(const float* __restrict__ A)
{
    int idx = blockIdx.x * 256 + threadIdx.x;      // 0 .. M*128-1
    int m  = idx >> 7;
    int kg = idx & 127;
    const float4* src = (const float4*)(A + (size_t)m * 1024 + kg * 8);
    float4 v0 = src[0], v1 = src[1];
    float x[8] = {v0.x, v0.y, v0.z, v0.w, v1.x, v1.y, v1.z, v1.w};
    unsigned short h[8], mm[8];
#pragma unroll
    for (int j = 0; j < 8; j++) {
        __half bh = __float2half_rn(x[j]);
        float r1 = x[j] - __half2float(bh);
        __half bm = __float2half_rn(r1);
        h[j]  = __half_as_ushort(bh);
        mm[j] = __half_as_ushort(bm);
    }
    size_t a = tile_addr(m >> 7, m & 127, kg);
#define PACK4(arr) make_uint4((unsigned)arr[0] | ((unsigned)arr[1] << 16), \
                              (unsigned)arr[2] | ((unsigned)arr[3] << 16), \
                              (unsigned)arr[4] | ((unsigned)arr[5] << 16), \
                              (unsigned)arr[6] | ((unsigned)arr[7] << 16))
    *(uint4*)((char*)g_Ahi  + a) = PACK4(h);
    *(uint4*)((char*)g_Amid + a) = PACK4(mm);
}

// ---------------- Prep 2: split + transpose weights -> swizzled tiles -------
__global__ __launch_bounds__(256) void split_b_kernel(
    const float* __restrict__ Wqk, const float* __restrict__ Wres)
{
    int id = blockIdx.x * 256 + threadIdx.x;   // 0..393215
    int n  = id % NTOT;
    int kg = id / NTOT;
    unsigned short h[8], mm[8];
#pragma unroll
    for (int j = 0; j < 8; j++) {
        int k = kg * 8 + j;
        float x = (n < 2048) ? Wqk[(size_t)k * 2048 + n]
                             : Wres[(size_t)k * 1024 + (n - 2048)];
        __half bh = __float2half_rn(x);
        float r1 = x - __half2float(bh);
        __half bm = __float2half_rn(r1);
        h[j]  = __half_as_ushort(bh);
        mm[j] = __half_as_ushort(bm);
    }
    size_t a = tile_addr(n >> 7, n & 127, kg);
    *(uint4*)((char*)g_Bhi  + a) = PACK4(h);
    *(uint4*)((char*)g_Bmid + a) = PACK4(mm);
#undef PACK4
}

// ---------------- Kernel 1: unified single-pass GEMM (occ 2) ----------------
// C[M, 3072] = Ahi @ Bhi for q / k / res. Error corrected where it matters:
// boundary-critical tokens get an exact 3-pass recompute (fixup below); res
// noise (~2e-4 rel) is absorbed by the 1e-3 tolerance.
#define QK_STAGE (2 * TILE_B)               // 32 KB
#define QK_SMEM  (128 + 3 * QK_STAGE)       // ~96 KB -> 2 CTAs/SM

__global__ void __launch_bounds__(256, 2) gemm_kernel()
{
    extern __shared__ char smem[];
    uint32_t sb = smem_u32(smem);
    const int tid = threadIdx.x;
    const int lane = tid & 31;
    const int wid = tid >> 5;
    const int warp_m = wid & 3;
    const int warp_n = wid >> 2;
    const int m0 = blockIdx.y * 128;
    const int n0 = blockIdx.x * 128;

    const char* asrc = (const char*)g_Ahi + (size_t)(m0 >> 7) * 16 * TILE_B;
    const char* bsrc = (const char*)g_Bhi + (size_t)(n0 >> 7) * 16 * TILE_B;

    if (tid == 0) {
        mbar_init(sb + 0, 1);
        mbar_init(sb + 8, 1);
        mbar_init(sb + 16, 1);
    }
    __syncthreads();

    float acc[2][8][4];
#pragma unroll
    for (int i = 0; i < 2; i++)
#pragma unroll
        for (int j = 0; j < 8; j++)
#pragma unroll
            for (int q = 0; q < 4; q++) acc[i][j][q] = 0.f;

    const int aRow  = warp_m * 32 + (lane & 15);
    const int aXor  = (aRow & 7) << 4;
    const int aColB = (lane >> 4) * 16;
    const int bRow  = warp_n * 64 + (lane & 7) + ((lane >> 4) & 1) * 8;
    const int bXor  = (bRow & 7) << 4;
    const int bColB = ((lane >> 3) & 1) * 16;

    if (tid == 0) {
#pragma unroll
        for (int c = 0; c < 2; c++) {
            uint32_t mb = sb + c * 8;
            uint32_t st = sb + 128 + c * QK_STAGE;
            mbar_expect_tx(mb, QK_STAGE);
            bulk_cp(st,          asrc + (size_t)c * TILE_B, TILE_B, mb);
            bulk_cp(st + TILE_B, bsrc + (size_t)c * TILE_B, TILE_B, mb);
        }
    }

#pragma unroll 1
    for (int c = 0; c < 16; c++) {
        int s = c % 3;
        uint32_t stage = sb + 128 + s * QK_STAGE;
        if (c < 14 && tid == 0) {
            int s2 = (c + 2) % 3;
            uint32_t mb = sb + s2 * 8;
            uint32_t st = sb + 128 + s2 * QK_STAGE;
            mbar_expect_tx(mb, QK_STAGE);
            bulk_cp(st,          asrc + (size_t)(c + 2) * TILE_B, TILE_B, mb);
            bulk_cp(st + TILE_B, bsrc + (size_t)(c + 2) * TILE_B, TILE_B, mb);
        }
        mbar_wait(sb + s * 8, (c / 3) & 1);
        __syncthreads();

        uint32_t aHi = stage, bHi = stage + TILE_B;
#pragma unroll 1
        for (int ks = 0; ks < 4; ks++) {
            uint32_t ah[2][4];
#pragma unroll
            for (int mi = 0; mi < 2; mi++) {
                uint32_t roff = (aRow + mi * 16) * 128 + ((ks * 32 + aColB) ^ aXor);
                ldsm_x4(aHi + roff, ah[mi][0], ah[mi][1], ah[mi][2], ah[mi][3]);
            }
#pragma unroll
            for (int ng = 0; ng < 4; ng++) {
                uint32_t roff = (bRow + ng * 16) * 128 + ((ks * 32 + bColB) ^ bXor);
                uint32_t b0, b1, b2, b3;
                ldsm_x4(bHi + roff, b0, b1, b2, b3);
                mma_f16(acc[0][ng*2],   ah[0], b0, b1);
                mma_f16(acc[0][ng*2+1], ah[0], b2, b3);
                mma_f16(acc[1][ng*2],   ah[1], b0, b1);
                mma_f16(acc[1][ng*2+1], ah[1], b2, b3);
            }
        }
        __syncthreads();
    }

    float* cbase; int coloff;
    if (n0 < 1024)      { cbase = g_q;   coloff = n0; }
    else if (n0 < 2048) { cbase = g_k;   coloff = n0 - 1024; }
    else                { cbase = g_res; coloff = n0 - 2048; }
#pragma unroll
    for (int mi = 0; mi < 2; mi++) {
        int r0 = m0 + warp_m * 32 + mi * 16 + (lane >> 2);
#pragma unroll
        for (int ni = 0; ni < 8; ni++) {
            int col = coloff + warp_n * 64 + ni * 8 + (lane & 3) * 2;
            *(float2*)&cbase[(size_t)r0 * 1024 + col] =
                make_float2(acc[mi][ni][0], acc[mi][ni][1]);
            *(float2*)&cbase[(size_t)(r0 + 8) * 1024 + col] =
                make_float2(acc[mi][ni][2], acc[mi][ni][3]);
        }
    }
}

// ---------------- zero fix counter ------------------------------------------
__global__ void zero_nfix_kernel() { g_nfix = 0; }

// ---------------- Kernel 2: cosine -> probs + flag + compact list -----------
__global__ __launch_bounds__(128) void probs_kernel(const float* __restrict__ start_key)
{
    int token = blockIdx.x;
    int l = token & (L - 1);
    const float4* qv = (const float4*)(g_q + (size_t)token * DQK);
    const float4* kv = (l == 0) ? (const float4*)start_key
                                : (const float4*)(g_k + (size_t)(token - 1) * DQK);
    float dot = 0.f, qq = 0.f, kk = 0.f;
    for (int i = threadIdx.x; i < DQK / 4; i += 128) {
        float4 a = qv[i], c = kv[i];
        dot += a.x * c.x + a.y * c.y + a.z * c.z + a.w * c.w;
        qq  += a.x * a.x + a.y * a.y + a.z * a.z + a.w * a.w;
        kk  += c.x * c.x + c.y * c.y + c.z * c.z + c.w * c.w;
    }
#pragma unroll
    for (int o = 16; o; o >>= 1) {
        dot += __shfl_down_sync(0xffffffffu, dot, o);
        qq  += __shfl_down_sync(0xffffffffu, qq,  o);
        kk  += __shfl_down_sync(0xffffffffu, kk,  o);
    }
    __shared__ float sd[4], sq[4], sk[4];
    int w = threadIdx.x >> 5;
    if ((threadIdx.x & 31) == 0) { sd[w] = dot; sq[w] = qq; sk[w] = kk; }
    __syncthreads();
    if (threadIdx.x == 0) {
        dot = sd[0] + sd[1] + sd[2] + sd[3];
        qq  = sq[0] + sq[1] + sq[2] + sq[3];
        kk  = sk[0] + sk[1] + sk[2] + sk[3];
        float denom = fmaxf(sqrtf(qq) * sqrtf(kk), 1e-8f);
        float cosv = dot / denom;
        g_probs[token] = (1.0f - cosv) * 0.5f;
        int fl = (fabsf(cosv) < 2.5e-4f) ? 1 : 0;
        g_flag[token] = fl;
        if (fl) {
            int slot = atomicAdd(&g_nfix, 1);
            g_fixlist[slot] = token;
        }
    }
}

// ---------------- pad fix list to multiple of 128 ---------------------------
__global__ void pad_fix_kernel()
{
    int nf = g_nfix;
    int np = (nf + 127) & ~127;
    if (nf > 0)
        for (int i = nf; i < np; i++) g_fixlist[i] = g_fixlist[0];
    g_nfixpad = (nf > 0) ? np : 0;
}

// ---------------- Kernel 2b: gathered 3-pass GEMM over flagged tokens -------
#define FIX_SMEM (512 + 4 * TILE_B)

__global__ void __launch_bounds__(256, 1) fixup_gemm_kernel()
{
    int mb = blockIdx.y & 255;
    if (mb * 128 >= g_nfixpad) return;
    const int isq = (blockIdx.y < 256);
    const int nblock = (isq ? 0 : 8) + blockIdx.x;     // global n-block 0..15

    extern __shared__ char smem[];
    int* toks = (int*)smem;
    uint32_t sb = smem_u32(smem) + 512;
    const int tid = threadIdx.x;
    const int lane = tid & 31;
    const int wid = tid >> 5;
    const int warp_m = wid & 3;
    const int warp_n = wid >> 2;

    if (tid < 128) {
        int t = g_fixlist[mb * 128 + tid];
        toks[tid] = isq ? t : max(t - 1, 0);
    }
    __syncthreads();

    float acc[2][8][4];
#pragma unroll
    for (int i = 0; i < 2; i++)
#pragma unroll
        for (int j = 0; j < 8; j++)
#pragma unroll
            for (int q = 0; q < 4; q++) acc[i][j][q] = 0.f;

    const int aRow  = warp_m * 32 + (lane & 15);
    const int aXor  = (aRow & 7) << 4;
    const int aColB = (lane >> 4) * 16;
    const int bRow  = warp_n * 64 + (lane & 7) + ((lane >> 4) & 1) * 8;
    const int bXor  = (bRow & 7) << 4;
    const int bColB = ((lane >> 3) & 1) * 16;

    const char* bhiSrc  = (const char*)g_Bhi  + (size_t)nblock * 16 * TILE_B;
    const char* bmidSrc = (const char*)g_Bmid + (size_t)nblock * 16 * TILE_B;

#pragma unroll 1
    for (int c = 0; c < 16; c++) {
#pragma unroll
        for (int it = 0; it < 4; it++) {
            int w = tid + it * 256;
            int r = w >> 3, kg7 = w & 7;
            int tok = toks[r];
            size_t srcOff = ((size_t)(tok >> 7) * 16 + c) * TILE_B
                          + (tok & 127) * 128 + ((kg7 * 16) ^ (((tok & 127) & 7) << 4));
            uint32_t dst = r * 128 + ((kg7 * 16) ^ ((r & 7) << 4));
            *(uint4*)(smem + 512 + dst)              = *(const uint4*)((const char*)g_Ahi  + srcOff);
            *(uint4*)(smem + 512 + TILE_B + dst)     = *(const uint4*)((const char*)g_Amid + srcOff);
            *(uint4*)(smem + 512 + 2 * TILE_B + w * 16) =
                *(const uint4*)(bhiSrc  + (size_t)c * TILE_B + w * 16);
            *(uint4*)(smem + 512 + 3 * TILE_B + w * 16) =
                *(const uint4*)(bmidSrc + (size_t)c * TILE_B + w * 16);
        }
        __syncthreads();

        uint32_t aHi = sb, aMid = sb + TILE_B;
        uint32_t bHi = sb + 2 * TILE_B, bMid = sb + 3 * TILE_B;
#pragma unroll 1
        for (int ks = 0; ks < 4; ks++) {
            uint32_t ah[2][4], am[2][4];
#pragma unroll
            for (int mi = 0; mi < 2; mi++) {
                uint32_t roff = (aRow + mi * 16) * 128 + ((ks * 32 + aColB) ^ aXor);
                ldsm_x4(aHi  + roff, ah[mi][0], ah[mi][1], ah[mi][2], ah[mi][3]);
                ldsm_x4(aMid + roff, am[mi][0], am[mi][1], am[mi][2], am[mi][3]);
            }
#pragma unroll
            for (int ng = 0; ng < 4; ng++) {
                uint32_t roff = (bRow + ng * 16) * 128 + ((ks * 32 + bColB) ^ bXor);
                uint32_t b0, b1, b2, b3;
                ldsm_x4(bHi + roff, b0, b1, b2, b3);
                mma_f16(acc[0][ng*2],   ah[0], b0, b1);
                mma_f16(acc[0][ng*2+1], ah[0], b2, b3);
                mma_f16(acc[1][ng*2],   ah[1], b0, b1);
                mma_f16(acc[1][ng*2+1], ah[1], b2, b3);
                mma_f16(acc[0][ng*2],   am[0], b0, b1);
                mma_f16(acc[0][ng*2+1], am[0], b2, b3);
                mma_f16(acc[1][ng*2],   am[1], b0, b1);
                mma_f16(acc[1][ng*2+1], am[1], b2, b3);
                ldsm_x4(bMid + roff, b0, b1, b2, b3);
                mma_f16(acc[0][ng*2],   ah[0], b0, b1);
                mma_f16(acc[0][ng*2+1], ah[0], b2, b3);
                mma_f16(acc[1][ng*2],   ah[1], b0, b1);
                mma_f16(acc[1][ng*2+1], ah[1], b2, b3);
            }
        }
        __syncthreads();
    }

    float* cbase = isq ? g_q : g_k;
    int coloff = (nblock & 7) * 128;
#pragma unroll
    for (int mi = 0; mi < 2; mi++) {
        int rloc = warp_m * 32 + mi * 16 + (lane >> 2);
        int row0 = toks[rloc];
        int row1 = toks[rloc + 8];
#pragma unroll
        for (int ni = 0; ni < 8; ni++) {
            int col = coloff + warp_n * 64 + ni * 8 + (lane & 3) * 2;
            *(float2*)&cbase[(size_t)row0 * 1024 + col] =
                make_float2(acc[mi][ni][0], acc[mi][ni][1]);
            *(float2*)&cbase[(size_t)row1 * 1024 + col] =
                make_float2(acc[mi][ni][2], acc[mi][ni][3]);
        }
    }
}

// ---------------- Kernel 2c: exact cosine for flagged tokens ----------------
__global__ __launch_bounds__(128) void fixup_cos_kernel(const float* __restrict__ start_key)
{
    int token = blockIdx.x;
    if (!g_flag[token]) return;
    int l = token & (L - 1);
    const float4* qv = (const float4*)(g_q + (size_t)token * DQK);
    const float4* kv = (l == 0) ? (const float4*)start_key
                                : (const float4*)(g_k + (size_t)(token - 1) * DQK);
    float dot = 0.f, qq = 0.f, kk = 0.f;
    for (int i = threadIdx.x; i < DQK / 4; i += 128) {
        float4 a = qv[i], c = kv[i];
        dot += a.x * c.x + a.y * c.y + a.z * c.z + a.w * c.w;
        qq  += a.x * a.x + a.y * a.y + a.z * a.z + a.w * a.w;
        kk  += c.x * c.x + c.y * c.y + c.z * c.z + c.w * c.w;
    }
#pragma unroll
    for (int o = 16; o; o >>= 1) {
        dot += __shfl_down_sync(0xffffffffu, dot, o);
        qq  += __shfl_down_sync(0xffffffffu, qq,  o);
        kk  += __shfl_down_sync(0xffffffffu, kk,  o);
    }
    __shared__ float sd[4], sq[4], sk[4];
    int w = threadIdx.x >> 5;
    if ((threadIdx.x & 31) == 0) { sd[w] = dot; sq[w] = qq; sk[w] = kk; }
    __syncthreads();
    if (threadIdx.x == 0) {
        dot = sd[0] + sd[1] + sd[2] + sd[3];
        qq  = sq[0] + sq[1] + sq[2] + sq[3];
        kk  = sk[0] + sk[1] + sk[2] + sk[3];
        float denom = fmaxf(sqrtf(qq) * sqrtf(kk), 1e-8f);
        g_probs[token] = (1.0f - dot / denom) * 0.5f;
    }
}

// ---------------- Kernel 3: per-batch boundary scan + aux -------------------
__global__ __launch_bounds__(1024) void boundary_kernel()
{
    int b = blockIdx.x;
    int tid = threadIdx.x;
    __shared__ int   s[1024];
    __shared__ float sf[1024];

    int l0 = tid * 4;
    float p[4]; int bd[4]; int cnt = 0; float psum = 0.f;
#pragma unroll
    for (int i = 0; i < 4; i++) {
        int l = l0 + i;
        p[i] = g_probs[b * L + l];
        bd[i] = (l == 0) || (p[i] > 0.5f);
        cnt += bd[i];
        psum += p[i];
    }
    s[tid] = cnt;
    sf[tid] = psum;
    __syncthreads();
    for (int off = 1; off < 1024; off <<= 1) {
        int v = (tid >= off) ? s[tid - off] : 0;
        __syncthreads();
        if (tid >= off) s[tid] += v;
        __syncthreads();
    }
    int incl = s[tid];
    int base = incl - cnt;
    int total = s[1023];
    int run = base;
#pragma unroll
    for (int i = 0; i < 4; i++) {
        int l = l0 + i;
        if (bd[i]) { g_blidx[b * L + run] = l; run++; }
        g_chunkid[b * L + l] = run - 1;
    }
    __syncthreads();
    for (int off = 512; off > 0; off >>= 1) {
        if (tid < off) sf[tid] += sf[tid + off];
        __syncthreads();
    }
    if (tid == 0) {
        float F = (float)total / (float)L;
        float G = sf[0] / (float)L;
        g_auxb[b] = 1.2f * (5.0f * F * G + (1.0f - F) * (1.0f - G));
        g_nch[b] = total;
    }
}

// ---------------- Kernel 4a: zero padded chunk slots of downsampled ---------
__global__ __launch_bounds__(256) void zero_down_kernel(float* __restrict__ out)
{
    int row = blockIdx.x;          // b*L + j
    int b = row >> 12;
    int j = row & (L - 1);
    if (j < g_nch[b]) return;
    float4* o = (float4*)(out + (size_t)row * D);
    o[threadIdx.x] = make_float4(0.f, 0.f, 0.f, 0.f);
}

// ---------------- Kernel 4b: windowed-parallel chunk EMA scan ---------------
__global__ __launch_bounds__(128) void chunk_scan_kernel(
    const float* __restrict__ tokens, float* __restrict__ out)
{
    int b = blockIdx.z;
    int nch = g_nch[b];
    int j0 = blockIdx.y * 128;
    if (j0 >= nch) return;
    int d = blockIdx.x * 128 + threadIdx.x;
    int jstart = (j0 >= 64) ? (j0 - 64) : 0;
    int jend = min(j0 + 128, nch);
    int cnt = jend - jstart;

    __shared__ int   sl[192];
    __shared__ float sp[192];
    for (int i = threadIdx.x; i < cnt; i += 128) {
        int l = g_blidx[b * L + jstart + i];
        sl[i] = l;
        sp[i] = g_probs[b * L + l];
    }
    __syncthreads();

    float h = 0.f;
    int i = 0;
    int warm = j0 - jstart;
    for (; i < warm; i++) {
        float p = sp[i];
        float t = tokens[((size_t)b * L + sl[i]) * D + d];
        h = fmaf(1.f - p, h, p * t);
    }
    for (; i < cnt; i++) {
        int j = jstart + i;
        float p = sp[i];
        float t = tokens[((size_t)b * L + sl[i]) * D + d];
        float x = p * t;
        out[((size_t)b * L + j) * D + d] = x;          // downsampled
        h = fmaf(1.f - p, h, x);
        g_scan[((size_t)b * L + j) * D + d] = h;
    }
}

// ---------------- Kernel 5: ups = gather(scan) + res + b_res ----------------
__global__ __launch_bounds__(256) void ups_kernel(
    float* __restrict__ out, const float* __restrict__ b_res)
{
    int row = blockIdx.x;          // b*L + l
    int b = row >> 12;
    int cid = g_chunkid[row];
    const float4* sc = (const float4*)(g_scan + (size_t)(b * L + cid) * D);
    const float4* rs = (const float4*)(g_res + (size_t)row * D);
    const float4* br = (const float4*)b_res;
    float4* o = (float4*)(out + BLD + (size_t)row * D);
    int t = threadIdx.x;
    float4 a = sc[t], c = rs[t], e = br[t];
    o[t] = make_float4(a.x + c.x + e.x, a.y + c.y + e.y,
                       a.z + c.z + e.z, a.w + c.w + e.w);
}

// ---------------- Kernel 6: finalize aux scalar -----------------------------
__global__ void aux_final_kernel(float* __restrict__ out)
{
    float s = 0.f;
    for (int i = 0; i < B; i++) s += g_auxb[i];
    out[2 * BLD] = (s / (float)B) * 0.03f;
}

// ---------------- launch ----------------------------------------------------
extern "C" void kernel_launch(void* const* d_in, const int* in_sizes, int n_in,
                              void* d_out, int out_size)
{
    const float* tokens = (const float*)d_in[0];
    const float* Wqk    = (const float*)d_in[1];
    const float* skey   = (const float*)d_in[2];
    const float* Wres   = (const float*)d_in[3];
    const float* bres   = (const float*)d_in[4];
    float* out = (float*)d_out;

    cudaFuncSetAttribute(gemm_kernel,
                         cudaFuncAttributeMaxDynamicSharedMemorySize, QK_SMEM);
    cudaFuncSetAttribute(fixup_gemm_kernel,
                         cudaFuncAttributeMaxDynamicSharedMemorySize, FIX_SMEM);

    split_a_kernel<<<M * 128 / 256, 256>>>(tokens);
    split_b_kernel<<<NTOT * 128 / 256, 256>>>(Wqk, Wres);
    zero_nfix_kernel<<<1, 1>>>();
    gemm_kernel<<<dim3(24, 256), 256, QK_SMEM>>>();
    probs_kernel<<<M, 128>>>(skey);
    pad_fix_kernel<<<1, 1>>>();
    fixup_gemm_kernel<<<dim3(8, 512), 256, FIX_SMEM>>>();
    fixup_cos_kernel<<<M, 128>>>(skey);
    boundary_kernel<<<B, 1024>>>();
    zero_down_kernel<<<M, 256>>>(out);
    chunk_scan_kernel<<<dim3(D / 128, L / 128, B), 128>>>(tokens, out);
    ups_kernel<<<M, 256>>>(out, bres);
    aux_final_kernel<<<1, 1>>>(out);
}